// round 9
// baseline (speedup 1.0000x reference)
#include <cuda_runtime.h>
#include <math.h>
#include <stdint.h>

#define ROWS 2048
#define ZLD  1152
#define PSLOT 18432

__device__ float g_xinv[ROWS*384];
__device__ float g_acfA[384*128];
__device__ int   g_periods[256];
__device__ int   g_needed[193];
__device__ float g_P[189*PSLOT];
__device__ float g_Ptr[96*384];
__device__ float g_anchT[4*96*512];
__device__ float g_WkA[8*512*96];
__device__ float g_WvAT[8*96*512];
__device__ float g_cvb[2*512];
__device__ float g_zbuf[(size_t)ROWS*2*ZLD];
__device__ float g_qb[2*ROWS*512];
__device__ float g_Qb[2*ROWS*512];
__device__ float g_ob[2*ROWS*512];
__device__ float g_ab[2*ROWS*512];
__device__ float g_tz[ROWS*96];
__device__ float g_comb[ROWS*1536];
__device__ float g_hb[ROWS*512];

__device__ __host__ __forceinline__ int near_anchor(int L){
  return (L<=18)?12:(L<=36)?24:(L<=72)?48:96;
}
__device__ __forceinline__ int aidx_of(int o){ return (o==12)?0:(o==24)?1:(o==48)?2:3; }

__global__ void k_xinv(const float* __restrict__ x){
  int idx = blockIdx.x*256+threadIdx.x;
  if(idx>=ROWS*384) return;
  int t=idx%384, r=idx/384, b=r>>7, c=r&127;
  g_xinv[idx] = x[((size_t)b*384+t)*128+c];
}

__global__ void k_acf(const float* __restrict__ x){
  __shared__ float xs[16][384];
  __shared__ float bm[16];
  int c=blockIdx.x, tid=threadIdx.x;
  for(int i=tid;i<16*384;i+=blockDim.x){ int b=i/384,t=i-b*384; xs[b][t]=x[((size_t)b*384+t)*128+c]; }
  __syncthreads();
  if(tid<16){ double s=0; for(int t=0;t<384;t++) s+=xs[tid][t]; bm[tid]=(float)(s/384.0); }
  __syncthreads();
  for(int i=tid;i<16*384;i+=blockDim.x){ int b=i/384; xs[b][i-b*384]-=bm[b]; }
  __syncthreads();
  for(int lag=tid;lag<384;lag+=blockDim.x){
    double acc=0; int n=384-lag;
    for(int b=0;b<16;b++){ const float* r=xs[b]; double s=0;
      for(int t=0;t<n;t++) s+=(double)r[t]*(double)r[t+lag]; acc+=s; }
    g_acfA[lag*128+c]=(float)(acc/16.0);
  }
}

__global__ void k_periods(){
  int tid=threadIdx.x;
  for(int i=tid;i<193;i+=blockDim.x) g_needed[i]=0;
  __syncthreads();
  if(tid<128){
    int c=tid; float v1=-INFINITY,v2=-INFINITY; int i1=0,i2=1;
    for(int lag=4;lag<384;lag++){
      float v=g_acfA[lag*128+c];
      float pv=(lag==4)?-INFINITY:g_acfA[(lag-1)*128+c];
      float nv=(lag==383)?-INFINITY:g_acfA[(lag+1)*128+c];
      if(v>pv&&v>nv&&v>0.f){
        if(v>v1){v2=v1;i2=i1;v1=v;i1=lag;}
        else if(v>v2){v2=v;i2=lag;}
      }
    }
    int p1=min(max(i1,4),192), p2=min(max(i2,4),192);
    g_periods[c*2]=p1; g_periods[c*2+1]=p2;
    g_needed[p1]=1; g_needed[p2]=1;
  }
}

__global__ void k_build_P(){
  int bid=blockIdx.x; bool tr=(bid==189);
  int L=tr?384:bid+4;
  if(!tr && !g_needed[L]) return;
  int on=near_anchor(L);
  float* P = tr? g_Ptr : g_P + (size_t)bid*PSLOT;
  int tid=threadIdx.x;
  if(L==on){ for(int x=tid;x<on*L;x+=blockDim.x) P[x]=(x/L==x%L)?1.f:0.f; return; }
  __shared__ int i0s[384]; __shared__ float ws[384];
  __shared__ double dd[96], ll[96];
  for(int j=tid;j<L;j+=blockDim.x){
    double src=((double)j+0.5)*on/L-0.5;
    src=fmin(fmax(src,0.0),(double)(on-1));
    int i0=(int)src; i0s[j]=i0; ws[j]=(float)(src-i0);
  }
  __syncthreads();
  int n=(L>on)?on:L;
  if(tid==0){
    double diag[96], sub[96];
    for(int i=0;i<96;i++){diag[i]=0;sub[i]=0;}
    if(L>on){
      for(int r=0;r<L;r++){ int i0=i0s[r]; double w=ws[r]; int i1=min(i0+1,on-1);
        double a,b; if(i1==i0){a=1;b=0;}else{a=1-w;b=w;}
        diag[i0]+=a*a; if(i1!=i0){diag[i1]+=b*b; sub[i0]+=a*b;} }
    } else {
      for(int r=0;r<L;r++){ int i0=i0s[r]; double w=ws[r]; int i1=min(i0+1,on-1);
        double a,b; if(i1==i0){a=1;b=0;}else{a=1-w;b=w;}
        diag[r]=a*a+b*b;
        if(r+1<L){ int j0=i0s[r+1]; double w2=ws[r+1]; int j1=min(j0+1,on-1);
          double cc,dv; if(j1==j0){cc=1;dv=0;}else{cc=1-w2;dv=w2;}
          double s=0;
          if(i0==j0)s+=a*cc; if(i0==j1&&j1!=j0)s+=a*dv;
          if(i1==j0&&i1!=i0)s+=b*cc; if(i1==j1&&i1!=i0&&j1!=j0)s+=b*dv;
          sub[r]=s; } }
    }
    dd[0]=diag[0];
    for(int i=0;i+1<n;i++){ ll[i]=sub[i]/dd[i]; dd[i+1]=diag[i+1]-ll[i]*sub[i]; }
  }
  __syncthreads();
  double sc=sqrt((double)L/(double)on);
  if(L>on){
    for(int j=tid;j<L;j+=blockDim.x){
      double y[96]; for(int i=0;i<n;i++) y[i]=0;
      int i0=i0s[j]; double w=ws[j]; int i1=min(i0+1,on-1);
      if(i1==i0) y[i0]=1.0; else { y[i0]=1.0-w; y[i1]=w; }
      for(int i=1;i<n;i++) y[i]-=ll[i-1]*y[i-1];
      for(int i=0;i<n;i++) y[i]/=dd[i];
      for(int i=n-2;i>=0;i--) y[i]-=ll[i]*y[i+1];
      for(int i=0;i<n;i++) P[(size_t)i*L+j]=(float)(sc*y[i]);
    }
  } else {
    for(int j=tid;j<n;j+=blockDim.x){
      double y[96], col[96];
      for(int i=0;i<n;i++) y[i]=0;
      for(int i=0;i<96;i++) col[i]=0;
      y[j]=1.0;
      for(int i=1;i<n;i++) y[i]-=ll[i-1]*y[i-1];
      for(int i=0;i<n;i++) y[i]/=dd[i];
      for(int i=n-2;i>=0;i--) y[i]-=ll[i]*y[i+1];
      for(int r=0;r<n;r++){ int i0=i0s[r]; double w=ws[r]; int i1=min(i0+1,on-1);
        if(i1==i0) col[i0]+=y[r]; else { col[i0]+=(1.0-w)*y[r]; col[i1]+=w*y[r]; } }
      for(int i=0;i<on;i++) P[(size_t)i*L+j]=(float)(sc*col[i]);
    }
  }
}

__global__ void k_anchT(const float* a12,const float* a24,const float* a48,const float* a96){
  int a=blockIdx.x;
  const int olds[4]={12,24,48,96};
  const float* A=(a==0)?a12:(a==1)?a24:(a==2)?a48:a96;
  int on=olds[a];
  for(int idx=threadIdx.x;idx<512*on;idx+=blockDim.x){
    int j=idx/on, i=idx-j*on;
    g_anchT[(size_t)a*96*512 + (size_t)i*512 + j]=A[idx];
  }
}

__global__ void k_cv(const float* w1,const float* b1,const float* w2,const float* b2,
                     const float* sb){
  int s=blockIdx.x, j=threadIdx.x;
  const float* W = (s? w2:w1) + (size_t)(1024+j)*512;
  float acc = (s? b2:b1)[1024+j];
  for(int e=0;e<512;e++) acc += W[e]*sb[e];
  g_cvb[s*512+j]=acc;
}

template<int EPI>
__global__ void __launch_bounds__(256) gemm_nt(
    int M,int N,int K,
    const float* __restrict__ A,int lda,
    const float* __restrict__ W,int ldw,
    const float* __restrict__ bias,
    float* __restrict__ C,int ldc)
{
  __shared__ float As[16][65];
  __shared__ float Ws[16][65];
  int bm=blockIdx.y*64, bn=blockIdx.x*64, tid=threadIdx.x;
  int lm=tid>>2, lk=(tid&3)*4, tx=tid&15, ty=tid>>4;
  float acc[4][4]={};
  for(int k0=0;k0<K;k0+=16){
    float4 av=make_float4(0,0,0,0), wv=make_float4(0,0,0,0);
    if(bm+lm<M) av=*(const float4*)(A+(size_t)(bm+lm)*lda+k0+lk);
    if(bn+lm<N) wv=*(const float4*)(W+(size_t)(bn+lm)*ldw+k0+lk);
    As[lk][lm]=av.x; As[lk+1][lm]=av.y; As[lk+2][lm]=av.z; As[lk+3][lm]=av.w;
    Ws[lk][lm]=wv.x; Ws[lk+1][lm]=wv.y; Ws[lk+2][lm]=wv.z; Ws[lk+3][lm]=wv.w;
    __syncthreads();
#pragma unroll
    for(int kk=0;kk<16;kk++){
      float a0=As[kk][ty*4],a1=As[kk][ty*4+1],a2=As[kk][ty*4+2],a3=As[kk][ty*4+3];
      float w0=Ws[kk][tx*4],w1=Ws[kk][tx*4+1],w2=Ws[kk][tx*4+2],w3=Ws[kk][tx*4+3];
      acc[0][0]+=a0*w0;acc[0][1]+=a0*w1;acc[0][2]+=a0*w2;acc[0][3]+=a0*w3;
      acc[1][0]+=a1*w0;acc[1][1]+=a1*w1;acc[1][2]+=a1*w2;acc[1][3]+=a1*w3;
      acc[2][0]+=a2*w0;acc[2][1]+=a2*w1;acc[2][2]+=a2*w2;acc[2][3]+=a2*w3;
      acc[3][0]+=a3*w0;acc[3][1]+=a3*w1;acc[3][2]+=a3*w2;acc[3][3]+=a3*w3;
    }
    __syncthreads();
  }
#pragma unroll
  for(int i=0;i<4;i++)
#pragma unroll
    for(int j=0;j<4;j++){
      int m=bm+ty*4+i, n=bn+tx*4+j;
      if(m<M&&n<N){
        float v=acc[i][j]+(bias?bias[n]:0.f);
        if(EPI==1) v=0.5f*v*(1.f+erff(v*0.70710678118654752f));
        C[(size_t)m*ldc+n]=v;
      }
    }
}

__global__ void k_tokenize(const float* __restrict__ sb){
  int r=blockIdx.x, slot=blockIdx.y, c=r&127, tid=threadIdx.x;
  int p=g_periods[c*2+slot], on=near_anchor(p), np=384/p, a=aidx_of(on);
  __shared__ float xs[384];
  __shared__ float zl[96];
  for(int t=tid;t<384;t+=128) xs[t]=g_xinv[(size_t)r*384+t];
  __syncthreads();
  const float* P=g_P+(size_t)(p-4)*PSLOT;
  float* z=g_zbuf+((size_t)r*2+slot)*ZLD;
  int tot=np*on;
  for(int idx=tid;idx<tot;idx+=128){
    int k=idx/on, i=idx-k*on;
    const float* Pr=P+(size_t)i*p;
    const float* xp=xs+k*p;
    float acc=0;
    for(int u=0;u<p;u++) acc+=Pr[u]*xp[u];
    z[idx]=acc;
    if(k==np-1) zl[i]=acc;
  }
  __syncthreads();
  const float* AT=g_anchT+(size_t)a*96*512;
  float* q=g_qb+((size_t)slot*ROWS+r)*512;
  for(int j=tid;j<512;j+=128){
    float acc=sb[j];
    for(int i=0;i<on;i++) acc+=AT[(size_t)i*512+j]*zl[i];
    q[j]=acc;
  }
}

__global__ void __launch_bounds__(256) k_attn(){
  __shared__ float us[6144];
  __shared__ float sc[6144];
  int c=blockIdx.x, slot=blockIdx.y, tid=threadIdx.x;
  int p=g_periods[c*2+slot], on=near_anchor(p), np=384/p, a=aidx_of(on);
  const float* WkA=g_WkA+(size_t)(slot*4+a)*512*96;
  const float* WvAT=g_WvAT+(size_t)(slot*4+a)*96*512;
  const float* Qb=g_Qb+(size_t)slot*ROWS*512;
  for(int x=tid;x<4*on;x+=256){
    int h=x/on, i=x-h*on;
    float acc[16];
#pragma unroll
    for(int b=0;b<16;b++) acc[b]=0;
    for(int e=0;e<128;e++){
      float wv=WkA[(size_t)(h*128+e)*96+i];
#pragma unroll
      for(int b=0;b<16;b++) acc[b]+=wv*__ldg(&Qb[(size_t)(b*128+c)*512+h*128+e]);
    }
#pragma unroll
    for(int b=0;b<16;b++) us[(b*4+h)*96+i]=acc[b];
  }
  __syncthreads();
  const float isq=0.08838834764831845f;
  for(int x=tid;x<16*np;x+=256){
    int b=x/np, k=x-b*np;
    const float* zr=g_zbuf+((size_t)(b*128+c)*2+slot)*ZLD+(size_t)k*on;
    float a0=0,a1=0,a2=0,a3=0;
    for(int i=0;i<on;i++){ float zv=zr[i];
      a0+=us[(b*4)*96+i]*zv; a1+=us[(b*4+1)*96+i]*zv;
      a2+=us[(b*4+2)*96+i]*zv; a3+=us[(b*4+3)*96+i]*zv; }
    sc[(b*4)*96+k]=a0*isq; sc[(b*4+1)*96+k]=a1*isq;
    sc[(b*4+2)*96+k]=a2*isq; sc[(b*4+3)*96+k]=a3*isq;
  }
  __syncthreads();
  if(tid<64){
    float* row=sc+tid*96; float m=-INFINITY;
    for(int k=0;k<np;k++) m=fmaxf(m,row[k]);
    float s=0;
    for(int k=0;k<np;k++){ float e=expf(row[k]-m); row[k]=e; s+=e; }
    float inv=1.f/s;
    for(int k=0;k<np;k++) row[k]*=inv;
  }
  __syncthreads();
  for(int x=tid;x<4*on;x+=256){
    int h=x/on, i=x-h*on;
    for(int b=0;b<16;b++){
      const float* zr=g_zbuf+((size_t)(b*128+c)*2+slot)*ZLD;
      const float* ar=sc+(b*4+h)*96;
      float acc=0;
      for(int k=0;k<np;k++) acc+=ar[k]*zr[(size_t)k*on+i];
      us[(b*4+h)*96+i]=acc;
    }
  }
  __syncthreads();
  for(int j=tid;j<512;j+=256){
    int h=j>>7;
    float wacc[16];
#pragma unroll
    for(int b=0;b<16;b++) wacc[b]=0;
    for(int i=0;i<on;i++){
      float wv=WvAT[(size_t)i*512+j];
#pragma unroll
      for(int b=0;b<16;b++) wacc[b]+=wv*us[(b*4+h)*96+i];
    }
    float cvv=g_cvb[slot*512+j];
#pragma unroll
    for(int b=0;b<16;b++)
      g_ob[(size_t)slot*ROWS*512+(size_t)(b*128+c)*512+j]=wacc[b]+cvv;
  }
}

__global__ void k_ln(const float* __restrict__ g,const float* __restrict__ bt,int slot){
  __shared__ float red[8];
  int r=blockIdx.x, tid=threadIdx.x;
  const float* q=g_qb+((size_t)slot*ROWS+r)*512;
  const float* a=g_ab+((size_t)slot*ROWS+r)*512;
  float v0=q[tid]+a[tid], v1=q[tid+256]+a[tid+256];
  float s=v0+v1;
  for(int o=16;o;o>>=1) s+=__shfl_xor_sync(~0u,s,o);
  if((tid&31)==0) red[tid>>5]=s;
  __syncthreads();
  if(tid<8){ s=red[tid]; for(int o=4;o;o>>=1) s+=__shfl_xor_sync(0xff,s,o); red[0]=s; }
  __syncthreads();
  float mu=red[0]/512.f;
  __syncthreads();
  float d0=v0-mu, d1=v1-mu;
  s=d0*d0+d1*d1;
  for(int o=16;o;o>>=1) s+=__shfl_xor_sync(~0u,s,o);
  if((tid&31)==0) red[tid>>5]=s;
  __syncthreads();
  if(tid<8){ s=red[tid]; for(int o=4;o;o>>=1) s+=__shfl_xor_sync(0xff,s,o); red[0]=s; }
  __syncthreads();
  float inv=rsqrtf(red[0]/512.f+1e-5f);
  float* out=g_comb+(size_t)r*1536+slot*512;
  out[tid]=d0*inv*g[tid]+bt[tid];
  out[tid+256]=d1*inv*g[tid+256]+bt[tid+256];
}

extern "C" void kernel_launch(void* const* d_in, const int* in_sizes, int n_in,
                              void* d_out, int out_size){
  const float* x   =(const float*)d_in[0];
  const float* a12 =(const float*)d_in[1];
  const float* a24 =(const float*)d_in[2];
  const float* a48 =(const float*)d_in[3];
  const float* a96 =(const float*)d_in[4];
  const float* sb  =(const float*)d_in[5];
  const float* inw[2]={(const float*)d_in[6],(const float*)d_in[12]};
  const float* inb[2]={(const float*)d_in[7],(const float*)d_in[13]};
  const float* ow[2]={(const float*)d_in[8],(const float*)d_in[14]};
  const float* obi[2]={(const float*)d_in[9],(const float*)d_in[15]};
  const float* lng[2]={(const float*)d_in[10],(const float*)d_in[16]};
  const float* lnb[2]={(const float*)d_in[11],(const float*)d_in[17]};
  const float* fw1=(const float*)d_in[18];
  const float* fb1=(const float*)d_in[19];
  const float* fw2=(const float*)d_in[20];
  const float* fb2=(const float*)d_in[21];
  float* out=(float*)d_out;

  float *xinv,*Ptr,*anchT,*WkA,*WvAT,*qb,*Qb,*ob,*ab,*tz,*comb,*hb;
  cudaGetSymbolAddress((void**)&xinv,g_xinv);
  cudaGetSymbolAddress((void**)&Ptr,g_Ptr);
  cudaGetSymbolAddress((void**)&anchT,g_anchT);
  cudaGetSymbolAddress((void**)&WkA,g_WkA);
  cudaGetSymbolAddress((void**)&WvAT,g_WvAT);
  cudaGetSymbolAddress((void**)&qb,g_qb);
  cudaGetSymbolAddress((void**)&Qb,g_Qb);
  cudaGetSymbolAddress((void**)&ob,g_ob);
  cudaGetSymbolAddress((void**)&ab,g_ab);
  cudaGetSymbolAddress((void**)&tz,g_tz);
  cudaGetSymbolAddress((void**)&comb,g_comb);
  cudaGetSymbolAddress((void**)&hb,g_hb);

  k_xinv<<<(ROWS*384+255)/256,256>>>(x);
  k_acf<<<128,384>>>(x);
  k_periods<<<1,192>>>();
  k_build_P<<<190,192>>>();
  k_anchT<<<4,256>>>(a12,a24,a48,a96);
  k_cv<<<2,512>>>(inw[0],inb[0],inw[1],inb[1],sb);

  const int olds[4]={12,24,48,96};
  for(int s=0;s<2;s++)
    for(int a=0;a<4;a++){
      int on=olds[a];
      gemm_nt<0><<<dim3((on+63)/64,8),256>>>(512,on,512,
        inw[s]+512*512,512, anchT+(size_t)a*96*512,512, nullptr,
        WkA+(size_t)(s*4+a)*512*96,96);
      gemm_nt<0><<<dim3(8,(on+63)/64),256>>>(on,512,512,
        anchT+(size_t)a*96*512,512, inw[s]+1024*512,512, nullptr,
        WvAT+(size_t)(s*4+a)*96*512,512);
    }

  k_tokenize<<<dim3(ROWS,2),128>>>(sb);
  for(int s=0;s<2;s++)
    gemm_nt<0><<<dim3(8,32),256>>>(ROWS,512,512,
      qb+(size_t)s*ROWS*512,512, inw[s],512, inb[s],
      Qb+(size_t)s*ROWS*512,512);

  k_attn<<<dim3(128,2),256>>>();

  for(int s=0;s<2;s++)
    gemm_nt<0><<<dim3(8,32),256>>>(ROWS,512,512,
      ob+(size_t)s*ROWS*512,512, ow[s],512, obi[s],
      ab+(size_t)s*ROWS*512,512);

  k_ln<<<ROWS,256>>>(lng[0],lnb[0],0);
  k_ln<<<ROWS,256>>>(lng[1],lnb[1],1);

  gemm_nt<0><<<dim3(2,32),256>>>(ROWS,96,384, xinv,384, Ptr,384, nullptr, tz,96);
  gemm_nt<0><<<dim3(8,32),256>>>(ROWS,512,96, tz,96, a96,96, sb, comb+1024,1536);

  gemm_nt<1><<<dim3(8,32),256>>>(ROWS,512,1536, comb,1536, fw1,1536, fb1, hb,512);
  gemm_nt<0><<<dim3(8,32),256>>>(ROWS,512,512, hb,512, fw2,512, fb2, out,512);
}

// round 10
// speedup vs baseline: 1.4223x; 1.4223x over previous
#include <cuda_runtime.h>
#include <math.h>
#include <stdint.h>

#define ROWS 2048
#define ZLD  1152
#define PSLOT 18432

__device__ float g_xinv[ROWS*384];
__device__ float g_acfA[384*128];
__device__ int   g_periods[256];
__device__ int   g_needed[193];
__device__ float g_P[189*PSLOT];
__device__ float g_Ptr[96*384];
__device__ float g_anchT[4*96*512];
__device__ float g_WkA[8*512*96];
__device__ float g_WvAT[8*96*512];
__device__ float g_cvb[2*512];
__device__ float g_zbuf[(size_t)ROWS*2*ZLD];
__device__ float g_qb[2*ROWS*512];
__device__ float g_Qb[2*ROWS*512];
__device__ float g_ob[2*ROWS*512];
__device__ float g_ab[2*ROWS*512];
__device__ float g_tz[ROWS*96];
__device__ float g_comb[ROWS*1536];
__device__ float g_hb[ROWS*512];

__device__ __host__ __forceinline__ int near_anchor(int L){
  return (L<=18)?12:(L<=36)?24:(L<=72)?48:96;
}
__device__ __forceinline__ int aidx_of(int o){ return (o==12)?0:(o==24)?1:(o==48)?2:3; }

__global__ void k_xinv(const float* __restrict__ x){
  int idx = blockIdx.x*256+threadIdx.x;
  if(idx>=ROWS*384) return;
  int t=idx%384, r=idx/384, b=r>>7, c=r&127;
  g_xinv[idx] = x[((size_t)b*384+t)*128+c];
}

__global__ void k_acf(const float* __restrict__ x){
  __shared__ float xs[16][384];
  __shared__ float bm[16];
  int c=blockIdx.x, tid=threadIdx.x;
  for(int i=tid;i<16*384;i+=blockDim.x){ int b=i/384,t=i-b*384; xs[b][t]=x[((size_t)b*384+t)*128+c]; }
  __syncthreads();
  if(tid<16){ double s=0; for(int t=0;t<384;t++) s+=xs[tid][t]; bm[tid]=(float)(s/384.0); }
  __syncthreads();
  for(int i=tid;i<16*384;i+=blockDim.x){ int b=i/384; xs[b][i-b*384]-=bm[b]; }
  __syncthreads();
  for(int lag=tid;lag<384;lag+=blockDim.x){
    float acc=0.f, comp=0.f;
    int n=384-lag;
    for(int b=0;b<16;b++){
      const float* r=xs[b];
      for(int t=0;t<n;t++){
        float prod=__fmul_rn(r[t],r[t+lag]);
        float yk=__fsub_rn(prod,comp);
        float tt=__fadd_rn(acc,yk);
        comp=__fsub_rn(__fsub_rn(tt,acc),yk);
        acc=tt;
      }
    }
    g_acfA[lag*128+c]=acc/16.f;
  }
}

__global__ void k_periods(){
  int tid=threadIdx.x;
  for(int i=tid;i<193;i+=blockDim.x) g_needed[i]=0;
  __syncthreads();
  if(tid<128){
    int c=tid; float v1=-INFINITY,v2=-INFINITY; int i1=0,i2=1;
    for(int lag=4;lag<384;lag++){
      float v=g_acfA[lag*128+c];
      float pv=(lag==4)?-INFINITY:g_acfA[(lag-1)*128+c];
      float nv=(lag==383)?-INFINITY:g_acfA[(lag+1)*128+c];
      if(v>pv&&v>nv&&v>0.f){
        if(v>v1){v2=v1;i2=i1;v1=v;i1=lag;}
        else if(v>v2){v2=v;i2=lag;}
      }
    }
    int p1=min(max(i1,4),192), p2=min(max(i2,4),192);
    g_periods[c*2]=p1; g_periods[c*2+1]=p2;
    g_needed[p1]=1; g_needed[p2]=1;
  }
}

__global__ void k_build_P(){
  int bid=blockIdx.x; bool tr=(bid==189);
  int L=tr?384:bid+4;
  if(!tr && !g_needed[L]) return;
  int on=near_anchor(L);
  float* P = tr? g_Ptr : g_P + (size_t)bid*PSLOT;
  int tid=threadIdx.x;
  int gtid=blockIdx.y*192+tid;
  if(L==on){ for(int v=gtid;v<on*L;v+=384) P[v]=(v/L==v%L)?1.f:0.f; return; }
  __shared__ int i0s[384]; __shared__ float ws[384];
  __shared__ double dd[96], ll[96];
  __shared__ float ddf[96], llf[96];
  for(int j=tid;j<L;j+=192){
    double src=((double)j+0.5)*on/L-0.5;
    src=fmin(fmax(src,0.0),(double)(on-1));
    int i0=(int)src; i0s[j]=i0; ws[j]=(float)(src-i0);
  }
  __syncthreads();
  int n=(L>on)?on:L;
  if(tid==0){
    double diag[96], sub[96];
    for(int i=0;i<96;i++){diag[i]=0;sub[i]=0;}
    if(L>on){
      for(int r=0;r<L;r++){ int i0=i0s[r]; double w=ws[r]; int i1=min(i0+1,on-1);
        double a,b; if(i1==i0){a=1;b=0;}else{a=1-w;b=w;}
        diag[i0]+=a*a; if(i1!=i0){diag[i1]+=b*b; sub[i0]+=a*b;} }
    } else {
      for(int r=0;r<L;r++){ int i0=i0s[r]; double w=ws[r]; int i1=min(i0+1,on-1);
        double a,b; if(i1==i0){a=1;b=0;}else{a=1-w;b=w;}
        diag[r]=a*a+b*b;
        if(r+1<L){ int j0=i0s[r+1]; double w2=ws[r+1]; int j1=min(j0+1,on-1);
          double cc,dv; if(j1==j0){cc=1;dv=0;}else{cc=1-w2;dv=w2;}
          double s=0;
          if(i0==j0)s+=a*cc; if(i0==j1&&j1!=j0)s+=a*dv;
          if(i1==j0&&i1!=i0)s+=b*cc; if(i1==j1&&i1!=i0&&j1!=j0)s+=b*dv;
          sub[r]=s; } }
    }
    dd[0]=diag[0];
    for(int i=0;i+1<n;i++){ ll[i]=sub[i]/dd[i]; dd[i+1]=diag[i+1]-ll[i]*sub[i]; }
  }
  __syncthreads();
  for(int i=tid;i<n;i+=192){ ddf[i]=(float)dd[i]; if(i+1<n) llf[i]=(float)ll[i]; }
  __syncthreads();
  float sc=sqrtf((float)L/(float)on);
  if(L>on){
    int j=gtid;
    if(j<L){
      float y[96];
      for(int i=0;i<n;i++) y[i]=0.f;
      int i0=i0s[j]; float w=ws[j]; int i1=min(i0+1,on-1);
      if(i1==i0) y[i0]=1.f; else { y[i0]=1.f-w; y[i1]=w; }
      for(int i=1;i<n;i++) y[i]-=llf[i-1]*y[i-1];
      for(int i=0;i<n;i++) y[i]/=ddf[i];
      for(int i=n-2;i>=0;i--) y[i]-=llf[i]*y[i+1];
      for(int i=0;i<n;i++) P[(size_t)i*L+j]=sc*y[i];
    }
  } else {
    int j=gtid;
    if(j<n){
      float y[96], col[96];
      for(int i=0;i<n;i++) y[i]=0.f;
      for(int i=0;i<96;i++) col[i]=0.f;
      y[j]=1.f;
      for(int i=1;i<n;i++) y[i]-=llf[i-1]*y[i-1];
      for(int i=0;i<n;i++) y[i]/=ddf[i];
      for(int i=n-2;i>=0;i--) y[i]-=llf[i]*y[i+1];
      for(int r=0;r<n;r++){ int i0=i0s[r]; float w=ws[r]; int i1=min(i0+1,on-1);
        if(i1==i0) col[i0]+=y[r]; else { col[i0]+=(1.f-w)*y[r]; col[i1]+=w*y[r]; } }
      for(int i=0;i<on;i++) P[(size_t)i*L+j]=sc*col[i];
    }
  }
}

__global__ void k_anchT(const float* a12,const float* a24,const float* a48,const float* a96){
  int a=blockIdx.x;
  const int olds[4]={12,24,48,96};
  const float* A=(a==0)?a12:(a==1)?a24:(a==2)?a48:a96;
  int on=olds[a];
  for(int idx=threadIdx.x;idx<512*on;idx+=blockDim.x){
    int j=idx/on, i=idx-j*on;
    g_anchT[(size_t)a*96*512 + (size_t)i*512 + j]=A[idx];
  }
}

__global__ void k_cv(const float* w1,const float* b1,const float* w2,const float* b2,
                     const float* sb){
  int s=blockIdx.x, j=threadIdx.x;
  const float* W = (s? w2:w1) + (size_t)(1024+j)*512;
  float acc = (s? b2:b1)[1024+j];
  for(int e=0;e<512;e++) acc += W[e]*sb[e];
  g_cvb[s*512+j]=acc;
}

// C = A(MxK) @ W(NxK)^T + bias  [EPI==1: exact-erf GELU]
// BM=128 BN=64 BK=16, 256 threads, 8x4 microtile. K must be %16.
template<int EPI>
__global__ void __launch_bounds__(256) gemm_nt(
    int M,int N,int K,
    const float* __restrict__ A,int lda,
    const float* __restrict__ W,int ldw,
    const float* __restrict__ bias,
    float* __restrict__ C,int ldc)
{
  __shared__ __align__(16) float As[16][132];
  __shared__ __align__(16) float Ws[16][68];
  int bm=blockIdx.y*128, bn=blockIdx.x*64, tid=threadIdx.x;
  int tx=tid&15, ty=tid>>4;
  int lm=tid>>2, lk=(tid&3)*4;
  float acc[8][4]={};
  for(int k0=0;k0<K;k0+=16){
#pragma unroll
    for(int h=0;h<2;h++){
      int m=bm+lm+h*64;
      float4 v=make_float4(0,0,0,0);
      if(m<M) v=*(const float4*)(A+(size_t)m*lda+k0+lk);
      As[lk][lm+h*64]=v.x; As[lk+1][lm+h*64]=v.y; As[lk+2][lm+h*64]=v.z; As[lk+3][lm+h*64]=v.w;
    }
    {
      int nn=bn+lm;
      float4 v=make_float4(0,0,0,0);
      if(nn<N) v=*(const float4*)(W+(size_t)nn*ldw+k0+lk);
      Ws[lk][lm]=v.x; Ws[lk+1][lm]=v.y; Ws[lk+2][lm]=v.z; Ws[lk+3][lm]=v.w;
    }
    __syncthreads();
#pragma unroll
    for(int kk=0;kk<16;kk++){
      float4 a0=*(float4*)&As[kk][ty*8];
      float4 a1=*(float4*)&As[kk][ty*8+4];
      float4 wv=*(float4*)&Ws[kk][tx*4];
      float am[8]={a0.x,a0.y,a0.z,a0.w,a1.x,a1.y,a1.z,a1.w};
      float wm4[4]={wv.x,wv.y,wv.z,wv.w};
#pragma unroll
      for(int i=0;i<8;i++)
#pragma unroll
        for(int j=0;j<4;j++) acc[i][j]+=am[i]*wm4[j];
    }
    __syncthreads();
  }
#pragma unroll
  for(int i=0;i<8;i++){
    int m=bm+ty*8+i;
    if(m>=M) continue;
#pragma unroll
    for(int j=0;j<4;j++){
      int nn=bn+tx*4+j;
      if(nn<N){
        float v=acc[i][j]+(bias?bias[nn]:0.f);
        if(EPI==1) v=0.5f*v*(1.f+erff(v*0.70710678118654752f));
        C[(size_t)m*ldc+nn]=v;
      }
    }
  }
}

__global__ void k_tokenize(const float* __restrict__ sb){
  int r=blockIdx.x, slot=blockIdx.y, c=r&127, tid=threadIdx.x;
  int p=g_periods[c*2+slot], on=near_anchor(p), np=384/p, a=aidx_of(on);
  __shared__ float xs[384];
  __shared__ float zl[96];
  for(int t=tid;t<384;t+=128) xs[t]=g_xinv[(size_t)r*384+t];
  __syncthreads();
  const float* P=g_P+(size_t)(p-4)*PSLOT;
  float* z=g_zbuf+((size_t)r*2+slot)*ZLD;
  int tot=np*on;
  for(int idx=tid;idx<tot;idx+=128){
    int k=idx/on, i=idx-k*on;
    const float* Pr=P+(size_t)i*p;
    const float* xp=xs+k*p;
    float acc=0;
    for(int u=0;u<p;u++) acc+=Pr[u]*xp[u];
    z[idx]=acc;
    if(k==np-1) zl[i]=acc;
  }
  __syncthreads();
  const float* AT=g_anchT+(size_t)a*96*512;
  float* q=g_qb+((size_t)slot*ROWS+r)*512;
  for(int j=tid;j<512;j+=128){
    float acc=sb[j];
    for(int i=0;i<on;i++) acc+=AT[(size_t)i*512+j]*zl[i];
    q[j]=acc;
  }
}

__global__ void __launch_bounds__(256) k_attn(){
  __shared__ float us[6144];   // [(b*4+h)*96+i]
  __shared__ float sc[6144];   // phase1: Q staging; later: scores
  int c=blockIdx.x, slot=blockIdx.y, tid=threadIdx.x;
  int p=g_periods[c*2+slot], on=near_anchor(p), np=384/p, a=aidx_of(on);
  const float* WkA=g_WkA+(size_t)(slot*4+a)*512*96;
  const float* WvAT=g_WvAT+(size_t)(slot*4+a)*96*512;
  const float* Qb=g_Qb+(size_t)slot*ROWS*512;
  // phase 1: u[b][h][i] = sum_e WkA[h*128+e,i] * Q[b, h*128+e]; two h-pairs
  for(int hp=0;hp<2;hp++){
    for(int x=tid;x<4096;x+=256){
      int b=x>>8, rme=x&255;
      sc[x]=Qb[(size_t)(b*128+c)*512 + hp*256 + rme];
    }
    __syncthreads();
    for(int x=tid;x<2*on;x+=256){
      int hh=x/on, i=x-hh*on;
      int h=hp*2+hh;
      float acc[16];
#pragma unroll
      for(int b=0;b<16;b++) acc[b]=0;
      for(int e=0;e<128;e++){
        float wv=WkA[(size_t)(h*128+e)*96+i];
#pragma unroll
        for(int b=0;b<16;b++) acc[b]+=wv*sc[b*256+hh*128+e];
      }
#pragma unroll
      for(int b=0;b<16;b++) us[(b*4+h)*96+i]=acc[b];
    }
    __syncthreads();
  }
  const float isq=0.08838834764831845f;
  for(int x=tid;x<16*np;x+=256){
    int b=x/np, k=x-b*np;
    const float* zr=g_zbuf+((size_t)(b*128+c)*2+slot)*ZLD+(size_t)k*on;
    float a0=0,a1=0,a2=0,a3=0;
    for(int i=0;i<on;i++){ float zv=zr[i];
      a0+=us[(b*4)*96+i]*zv; a1+=us[(b*4+1)*96+i]*zv;
      a2+=us[(b*4+2)*96+i]*zv; a3+=us[(b*4+3)*96+i]*zv; }
    sc[(b*4)*96+k]=a0*isq; sc[(b*4+1)*96+k]=a1*isq;
    sc[(b*4+2)*96+k]=a2*isq; sc[(b*4+3)*96+k]=a3*isq;
  }
  __syncthreads();
  if(tid<64){
    float* row=sc+tid*96; float m=-INFINITY;
    for(int k=0;k<np;k++) m=fmaxf(m,row[k]);
    float s=0;
    for(int k=0;k<np;k++){ float e=expf(row[k]-m); row[k]=e; s+=e; }
    float inv=1.f/s;
    for(int k=0;k<np;k++) row[k]*=inv;
  }
  __syncthreads();
  for(int x=tid;x<4*on;x+=256){
    int h=x/on, i=x-h*on;
    for(int b=0;b<16;b++){
      const float* zr=g_zbuf+((size_t)(b*128+c)*2+slot)*ZLD;
      const float* ar=sc+(b*4+h)*96;
      float acc=0;
      for(int k=0;k<np;k++) acc+=ar[k]*zr[(size_t)k*on+i];
      us[(b*4+h)*96+i]=acc;
    }
  }
  __syncthreads();
  for(int j=tid;j<512;j+=256){
    int h=j>>7;
    float wacc[16];
#pragma unroll
    for(int b=0;b<16;b++) wacc[b]=0;
    for(int i=0;i<on;i++){
      float wv=WvAT[(size_t)i*512+j];
#pragma unroll
      for(int b=0;b<16;b++) wacc[b]+=wv*us[(b*4+h)*96+i];
    }
    float cvv=g_cvb[slot*512+j];
#pragma unroll
    for(int b=0;b<16;b++)
      g_ob[(size_t)slot*ROWS*512+(size_t)(b*128+c)*512+j]=wacc[b]+cvv;
  }
}

__global__ void k_ln(const float* __restrict__ g,const float* __restrict__ bt,int slot){
  __shared__ float red[8];
  int r=blockIdx.x, tid=threadIdx.x;
  const float* q=g_qb+((size_t)slot*ROWS+r)*512;
  const float* a=g_ab+((size_t)slot*ROWS+r)*512;
  float v0=q[tid]+a[tid], v1=q[tid+256]+a[tid+256];
  float s=v0+v1;
  for(int o=16;o;o>>=1) s+=__shfl_xor_sync(~0u,s,o);
  if((tid&31)==0) red[tid>>5]=s;
  __syncthreads();
  if(tid<8){ s=red[tid]; for(int o=4;o;o>>=1) s+=__shfl_xor_sync(0xff,s,o); red[0]=s; }
  __syncthreads();
  float mu=red[0]/512.f;
  __syncthreads();
  float d0=v0-mu, d1=v1-mu;
  s=d0*d0+d1*d1;
  for(int o=16;o;o>>=1) s+=__shfl_xor_sync(~0u,s,o);
  if((tid&31)==0) red[tid>>5]=s;
  __syncthreads();
  if(tid<8){ s=red[tid]; for(int o=4;o;o>>=1) s+=__shfl_xor_sync(0xff,s,o); red[0]=s; }
  __syncthreads();
  float inv=rsqrtf(red[0]/512.f+1e-5f);
  float* out=g_comb+(size_t)r*1536+slot*512;
  out[tid]=d0*inv*g[tid]+bt[tid];
  out[tid+256]=d1*inv*g[tid+256]+bt[tid+256];
}

extern "C" void kernel_launch(void* const* d_in, const int* in_sizes, int n_in,
                              void* d_out, int out_size){
  const float* x   =(const float*)d_in[0];
  const float* a12 =(const float*)d_in[1];
  const float* a24 =(const float*)d_in[2];
  const float* a48 =(const float*)d_in[3];
  const float* a96 =(const float*)d_in[4];
  const float* sb  =(const float*)d_in[5];
  const float* inw[2]={(const float*)d_in[6],(const float*)d_in[12]};
  const float* inb[2]={(const float*)d_in[7],(const float*)d_in[13]};
  const float* ow[2]={(const float*)d_in[8],(const float*)d_in[14]};
  const float* obi[2]={(const float*)d_in[9],(const float*)d_in[15]};
  const float* lng[2]={(const float*)d_in[10],(const float*)d_in[16]};
  const float* lnb[2]={(const float*)d_in[11],(const float*)d_in[17]};
  const float* fw1=(const float*)d_in[18];
  const float* fb1=(const float*)d_in[19];
  const float* fw2=(const float*)d_in[20];
  const float* fb2=(const float*)d_in[21];
  float* out=(float*)d_out;

  float *xinv,*Ptr,*anchT,*WkA,*WvAT,*qb,*Qb,*ob,*ab,*tz,*comb,*hb;
  cudaGetSymbolAddress((void**)&xinv,g_xinv);
  cudaGetSymbolAddress((void**)&Ptr,g_Ptr);
  cudaGetSymbolAddress((void**)&anchT,g_anchT);
  cudaGetSymbolAddress((void**)&WkA,g_WkA);
  cudaGetSymbolAddress((void**)&WvAT,g_WvAT);
  cudaGetSymbolAddress((void**)&qb,g_qb);
  cudaGetSymbolAddress((void**)&Qb,g_Qb);
  cudaGetSymbolAddress((void**)&ob,g_ob);
  cudaGetSymbolAddress((void**)&ab,g_ab);
  cudaGetSymbolAddress((void**)&tz,g_tz);
  cudaGetSymbolAddress((void**)&comb,g_comb);
  cudaGetSymbolAddress((void**)&hb,g_hb);

  k_xinv<<<(ROWS*384+255)/256,256>>>(x);
  k_acf<<<128,384>>>(x);
  k_periods<<<1,192>>>();
  k_build_P<<<dim3(190,2),192>>>();
  k_anchT<<<4,256>>>(a12,a24,a48,a96);
  k_cv<<<2,512>>>(inw[0],inb[0],inw[1],inb[1],sb);

  const int olds[4]={12,24,48,96};
  for(int s=0;s<2;s++)
    for(int a=0;a<4;a++){
      int on=olds[a];
      gemm_nt<0><<<dim3((on+63)/64,4),256>>>(512,on,512,
        inw[s]+512*512,512, anchT+(size_t)a*96*512,512, nullptr,
        WkA+(size_t)(s*4+a)*512*96,96);
      gemm_nt<0><<<dim3(8,(on+127)/128),256>>>(on,512,512,
        anchT+(size_t)a*96*512,512, inw[s]+1024*512,512, nullptr,
        WvAT+(size_t)(s*4+a)*96*512,512);
    }

  k_tokenize<<<dim3(ROWS,2),128>>>(sb);
  for(int s=0;s<2;s++)
    gemm_nt<0><<<dim3(8,16),256>>>(ROWS,512,512,
      qb+(size_t)s*ROWS*512,512, inw[s],512, inb[s],
      Qb+(size_t)s*ROWS*512,512);

  k_attn<<<dim3(128,2),256>>>();

  for(int s=0;s<2;s++)
    gemm_nt<0><<<dim3(8,16),256>>>(ROWS,512,512,
      ob+(size_t)s*ROWS*512,512, ow[s],512, obi[s],
      ab+(size_t)s*ROWS*512,512);

  k_ln<<<ROWS,256>>>(lng[0],lnb[0],0);
  k_ln<<<ROWS,256>>>(lng[1],lnb[1],1);

  gemm_nt<0><<<dim3(2,16),256>>>(ROWS,96,384, xinv,384, Ptr,384, nullptr, tz,96);
  gemm_nt<0><<<dim3(8,16),256>>>(ROWS,512,96, tz,96, a96,96, sb, comb+1024,1536);

  gemm_nt<1><<<dim3(8,16),256>>>(ROWS,512,1536, comb,1536, fw1,1536, fb1, hb,512);
  gemm_nt<0><<<dim3(8,16),256>>>(ROWS,512,512, hb,512, fw2,512, fb2, out,512);
}

// round 11
// speedup vs baseline: 1.8188x; 1.2788x over previous
#include <cuda_runtime.h>
#include <math.h>
#include <stdint.h>

#define ROWS 2048
#define ZLD  1152
#define PSLOT 18432

__device__ float g_xinv[ROWS*384];
__device__ float g_acfA[384*128];
__device__ int   g_periods[256];
__device__ int   g_needed[193];
__device__ float g_P[189*PSLOT];
__device__ float g_Ptr[96*384];
__device__ float g_anchT[4*96*512];
__device__ float g_WkA[8*512*96];
__device__ float g_WvAT[8*96*512];
__device__ float g_cvb[2*512];
__device__ float g_zbuf[(size_t)ROWS*2*ZLD];
__device__ float g_qb[2*ROWS*512];
__device__ float g_Qb[2*ROWS*512];
__device__ float g_ob[2*ROWS*512];
__device__ float g_ab[2*ROWS*512];
__device__ float g_tz[ROWS*96];
__device__ float g_comb[ROWS*1536];
__device__ float g_hb[ROWS*512];

__device__ __host__ __forceinline__ int near_anchor(int L){
  return (L<=18)?12:(L<=36)?24:(L<=72)?48:96;
}
__device__ __forceinline__ int aidx_of(int o){ return (o==12)?0:(o==24)?1:(o==48)?2:3; }

__global__ void k_xinv(const float* __restrict__ x){
  int idx = blockIdx.x*256+threadIdx.x;
  if(idx>=ROWS*384) return;
  int t=idx%384, r=idx/384, b=r>>7, c=r&127;
  g_xinv[idx] = x[((size_t)b*384+t)*128+c];
}

__global__ void k_acf(){
  __shared__ float xs[16][384];
  __shared__ float bm[16];
  int c=blockIdx.x, tid=threadIdx.x;
  for(int i=tid;i<16*384;i+=blockDim.x){
    int b=i/384,t=i-b*384;
    xs[b][t]=g_xinv[((size_t)(b*128+c))*384+t];
  }
  __syncthreads();
  if(tid<16){ float s0=0,s1=0;
    for(int t=0;t<384;t+=2){ s0+=xs[tid][t]; s1+=xs[tid][t+1]; }
    bm[tid]=(s0+s1)/384.f; }
  __syncthreads();
  for(int i=tid;i<16*384;i+=blockDim.x){ int b=i/384; xs[b][i-b*384]-=bm[b]; }
  __syncthreads();
  for(int lag=tid;lag<384;lag+=blockDim.x){
    float acc=0.f;
    int n=384-lag;
    for(int b=0;b<16;b++){
      const float* r=xs[b];
      float s0=0.f,s1=0.f;
      int t=0;
      for(;t+1<n;t+=2){ s0=fmaf(r[t],r[t+lag],s0); s1=fmaf(r[t+1],r[t+1+lag],s1); }
      if(t<n) s0=fmaf(r[t],r[t+lag],s0);
      acc+=s0+s1;
    }
    g_acfA[lag*128+c]=acc/16.f;
  }
}

__global__ void k_periods(){
  int tid=threadIdx.x;
  for(int i=tid;i<193;i+=blockDim.x) g_needed[i]=0;
  __syncthreads();
  if(tid<128){
    int c=tid; float v1=-INFINITY,v2=-INFINITY; int i1=0,i2=1;
    for(int lag=4;lag<384;lag++){
      float v=g_acfA[lag*128+c];
      float pv=(lag==4)?-INFINITY:g_acfA[(lag-1)*128+c];
      float nv=(lag==383)?-INFINITY:g_acfA[(lag+1)*128+c];
      if(v>pv&&v>nv&&v>0.f){
        if(v>v1){v2=v1;i2=i1;v1=v;i1=lag;}
        else if(v>v2){v2=v;i2=lag;}
      }
    }
    int p1=min(max(i1,4),192), p2=min(max(i2,4),192);
    g_periods[c*2]=p1; g_periods[c*2+1]=p2;
    g_needed[p1]=1; g_needed[p2]=1;
  }
}

__global__ void k_build_P(){
  int bid=blockIdx.x; bool tr=(bid==189);
  int L=tr?384:bid+4;
  if(!tr && !g_needed[L]) return;
  int on=near_anchor(L);
  float* P = tr? g_Ptr : g_P + (size_t)bid*PSLOT;
  int tid=threadIdx.x;
  int gtid=blockIdx.y*192+tid;
  if(L==on){ for(int v=gtid;v<on*L;v+=384) P[v]=(v/L==v%L)?1.f:0.f; return; }
  __shared__ int i0s[384]; __shared__ float ws[384];
  __shared__ float ddf[96], llf[96];
  for(int j=tid;j<L;j+=192){
    float src=((float)j+0.5f)*(float)on/(float)L-0.5f;
    src=fminf(fmaxf(src,0.f),(float)(on-1));
    int i0=(int)src; i0s[j]=i0; ws[j]=src-(float)i0;
  }
  __syncthreads();
  int n=(L>on)?on:L;
  if(tid==0){
    float diag[96], sub[96];
    for(int i=0;i<96;i++){diag[i]=0;sub[i]=0;}
    if(L>on){
      for(int r=0;r<L;r++){ int i0=i0s[r]; float w=ws[r]; int i1=min(i0+1,on-1);
        float a,b; if(i1==i0){a=1;b=0;}else{a=1-w;b=w;}
        diag[i0]+=a*a; if(i1!=i0){diag[i1]+=b*b; sub[i0]+=a*b;} }
    } else {
      for(int r=0;r<L;r++){ int i0=i0s[r]; float w=ws[r]; int i1=min(i0+1,on-1);
        float a,b; if(i1==i0){a=1;b=0;}else{a=1-w;b=w;}
        diag[r]=a*a+b*b;
        if(r+1<L){ int j0=i0s[r+1]; float w2=ws[r+1]; int j1=min(j0+1,on-1);
          float cc,dv; if(j1==j0){cc=1;dv=0;}else{cc=1-w2;dv=w2;}
          float s=0;
          if(i0==j0)s+=a*cc; if(i0==j1&&j1!=j0)s+=a*dv;
          if(i1==j0&&i1!=i0)s+=b*cc; if(i1==j1&&i1!=i0&&j1!=j0)s+=b*dv;
          sub[r]=s; } }
    }
    ddf[0]=diag[0];
    for(int i=0;i+1<n;i++){ llf[i]=sub[i]/ddf[i]; ddf[i+1]=diag[i+1]-llf[i]*sub[i]; }
  }
  __syncthreads();
  float sc=sqrtf((float)L/(float)on);
  if(L>on){
    int j=gtid;
    if(j<L){
      float y[96];
      for(int i=0;i<n;i++) y[i]=0.f;
      int i0=i0s[j]; float w=ws[j]; int i1=min(i0+1,on-1);
      if(i1==i0) y[i0]=1.f; else { y[i0]=1.f-w; y[i1]=w; }
      for(int i=1;i<n;i++) y[i]-=llf[i-1]*y[i-1];
      for(int i=0;i<n;i++) y[i]/=ddf[i];
      for(int i=n-2;i>=0;i--) y[i]-=llf[i]*y[i+1];
      for(int i=0;i<n;i++) P[(size_t)i*L+j]=sc*y[i];
    }
  } else {
    int j=gtid;
    if(j<n){
      float y[96], col[96];
      for(int i=0;i<n;i++) y[i]=0.f;
      for(int i=0;i<96;i++) col[i]=0.f;
      y[j]=1.f;
      for(int i=1;i<n;i++) y[i]-=llf[i-1]*y[i-1];
      for(int i=0;i<n;i++) y[i]/=ddf[i];
      for(int i=n-2;i>=0;i--) y[i]-=llf[i]*y[i+1];
      for(int r=0;r<n;r++){ int i0=i0s[r]; float w=ws[r]; int i1=min(i0+1,on-1);
        if(i1==i0) col[i0]+=y[r]; else { col[i0]+=(1.f-w)*y[r]; col[i1]+=w*y[r]; } }
      for(int i=0;i<on;i++) P[(size_t)i*L+j]=sc*col[i];
    }
  }
}

__global__ void k_anchT(const float* a12,const float* a24,const float* a48,const float* a96){
  int a=blockIdx.x;
  const int olds[4]={12,24,48,96};
  const float* A=(a==0)?a12:(a==1)?a24:(a==2)?a48:a96;
  int on=olds[a];
  for(int idx=threadIdx.x;idx<512*on;idx+=blockDim.x){
    int j=idx/on, i=idx-j*on;
    g_anchT[(size_t)a*96*512 + (size_t)i*512 + j]=A[idx];
  }
}

__global__ void k_cv(const float* w1,const float* b1,const float* w2,const float* b2,
                     const float* sb){
  int s=blockIdx.x, j=threadIdx.x;
  const float* W = (s? w2:w1) + (size_t)(1024+j)*512;
  float acc = (s? b2:b1)[1024+j];
  for(int e=0;e<512;e++) acc += W[e]*sb[e];
  g_cvb[s*512+j]=acc;
}

// C = A(MxK) @ W(NxK)^T + bias  [EPI==1: exact-erf GELU]
// BM=128 BN=64 BK=16, 256 threads, 8x4 microtile, double-buffered. K%16==0.
template<int EPI>
__global__ void __launch_bounds__(256) gemm_nt(
    int M,int N,int K,
    const float* __restrict__ A,int lda,
    const float* __restrict__ W,int ldw,
    const float* __restrict__ bias,
    float* __restrict__ C,int ldc)
{
  __shared__ __align__(16) float As[2][16][132];
  __shared__ __align__(16) float Ws[2][16][68];
  int bm=blockIdx.y*128, bn=blockIdx.x*64, tid=threadIdx.x;
  int tx=tid&15, ty=tid>>4;
  int lm=tid>>2, lk=(tid&3)*4;
  int m0=bm+lm, m1=bm+lm+64, nn=bn+lm;
  float acc[8][4]={};
  float4 pa0,pa1,pw;
  const float4 z4=make_float4(0,0,0,0);
  pa0=(m0<M)?*(const float4*)(A+(size_t)m0*lda+lk):z4;
  pa1=(m1<M)?*(const float4*)(A+(size_t)m1*lda+lk):z4;
  pw =(nn<N)?*(const float4*)(W+(size_t)nn*ldw+lk):z4;
  As[0][lk][lm]=pa0.x; As[0][lk+1][lm]=pa0.y; As[0][lk+2][lm]=pa0.z; As[0][lk+3][lm]=pa0.w;
  As[0][lk][lm+64]=pa1.x; As[0][lk+1][lm+64]=pa1.y; As[0][lk+2][lm+64]=pa1.z; As[0][lk+3][lm+64]=pa1.w;
  Ws[0][lk][lm]=pw.x; Ws[0][lk+1][lm]=pw.y; Ws[0][lk+2][lm]=pw.z; Ws[0][lk+3][lm]=pw.w;
  __syncthreads();
  for(int k0=0;k0<K;k0+=16){
    int buf=(k0>>4)&1;
    bool more=(k0+16<K);
    if(more){
      pa0=(m0<M)?*(const float4*)(A+(size_t)m0*lda+k0+16+lk):z4;
      pa1=(m1<M)?*(const float4*)(A+(size_t)m1*lda+k0+16+lk):z4;
      pw =(nn<N)?*(const float4*)(W+(size_t)nn*ldw+k0+16+lk):z4;
    }
#pragma unroll
    for(int kk=0;kk<16;kk++){
      float4 a0=*(float4*)&As[buf][kk][ty*8];
      float4 a1=*(float4*)&As[buf][kk][ty*8+4];
      float4 wv=*(float4*)&Ws[buf][kk][tx*4];
      float am[8]={a0.x,a0.y,a0.z,a0.w,a1.x,a1.y,a1.z,a1.w};
      float wm4[4]={wv.x,wv.y,wv.z,wv.w};
#pragma unroll
      for(int i=0;i<8;i++)
#pragma unroll
        for(int j=0;j<4;j++) acc[i][j]+=am[i]*wm4[j];
    }
    if(more){
      int nb=buf^1;
      As[nb][lk][lm]=pa0.x; As[nb][lk+1][lm]=pa0.y; As[nb][lk+2][lm]=pa0.z; As[nb][lk+3][lm]=pa0.w;
      As[nb][lk][lm+64]=pa1.x; As[nb][lk+1][lm+64]=pa1.y; As[nb][lk+2][lm+64]=pa1.z; As[nb][lk+3][lm+64]=pa1.w;
      Ws[nb][lk][lm]=pw.x; Ws[nb][lk+1][lm]=pw.y; Ws[nb][lk+2][lm]=pw.z; Ws[nb][lk+3][lm]=pw.w;
      __syncthreads();
    }
  }
#pragma unroll
  for(int i=0;i<8;i++){
    int m=bm+ty*8+i;
    if(m>=M) continue;
#pragma unroll
    for(int j=0;j<4;j++){
      int n2=bn+tx*4+j;
      if(n2<N){
        float v=acc[i][j]+(bias?bias[n2]:0.f);
        if(EPI==1) v=0.5f*v*(1.f+erff(v*0.70710678118654752f));
        C[(size_t)m*ldc+n2]=v;
      }
    }
  }
}

__global__ void k_tokenize(const float* __restrict__ sb){
  int r=blockIdx.x, slot=blockIdx.y, c=r&127, tid=threadIdx.x;
  int p=g_periods[c*2+slot], on=near_anchor(p), np=384/p, a=aidx_of(on);
  __shared__ float xs[384];
  __shared__ float zl[96];
  for(int t=tid;t<384;t+=128) xs[t]=g_xinv[(size_t)r*384+t];
  __syncthreads();
  const float* P=g_P+(size_t)(p-4)*PSLOT;
  float* z=g_zbuf+((size_t)r*2+slot)*ZLD;
  int tot=np*on;
  for(int idx=tid;idx<tot;idx+=128){
    int k=idx/on, i=idx-k*on;
    const float* Pr=P+(size_t)i*p;
    const float* xp=xs+k*p;
    float acc=0;
    for(int u=0;u<p;u++) acc+=Pr[u]*xp[u];
    z[idx]=acc;
    if(k==np-1) zl[i]=acc;
  }
  __syncthreads();
  const float* AT=g_anchT+(size_t)a*96*512;
  float* q=g_qb+((size_t)slot*ROWS+r)*512;
  for(int j=tid;j<512;j+=128){
    float acc=sb[j];
    for(int i=0;i<on;i++) acc+=AT[(size_t)i*512+j]*zl[i];
    q[j]=acc;
  }
}

__global__ void __launch_bounds__(256) k_attn(){
  __shared__ float us[6144];
  __shared__ float sc[6144];
  int c=blockIdx.x, slot=blockIdx.y, tid=threadIdx.x;
  int p=g_periods[c*2+slot], on=near_anchor(p), np=384/p, a=aidx_of(on);
  const float* WkA=g_WkA+(size_t)(slot*4+a)*512*96;
  const float* WvAT=g_WvAT+(size_t)(slot*4+a)*96*512;
  const float* Qb=g_Qb+(size_t)slot*ROWS*512;
  for(int hp=0;hp<2;hp++){
    for(int x=tid;x<4096;x+=256){
      int b=x>>8, rme=x&255;
      sc[x]=Qb[(size_t)(b*128+c)*512 + hp*256 + rme];
    }
    __syncthreads();
    for(int x=tid;x<2*on;x+=256){
      int hh=x/on, i=x-hh*on;
      int h=hp*2+hh;
      float acc[16];
#pragma unroll
      for(int b=0;b<16;b++) acc[b]=0;
      for(int e=0;e<128;e++){
        float wv=WkA[(size_t)(h*128+e)*96+i];
#pragma unroll
        for(int b=0;b<16;b++) acc[b]+=wv*sc[b*256+hh*128+e];
      }
#pragma unroll
      for(int b=0;b<16;b++) us[(b*4+h)*96+i]=acc[b];
    }
    __syncthreads();
  }
  const float isq=0.08838834764831845f;
  for(int x=tid;x<16*np;x+=256){
    int b=x/np, k=x-b*np;
    const float* zr=g_zbuf+((size_t)(b*128+c)*2+slot)*ZLD+(size_t)k*on;
    float a0=0,a1=0,a2=0,a3=0;
    for(int i=0;i<on;i++){ float zv=zr[i];
      a0+=us[(b*4)*96+i]*zv; a1+=us[(b*4+1)*96+i]*zv;
      a2+=us[(b*4+2)*96+i]*zv; a3+=us[(b*4+3)*96+i]*zv; }
    sc[(b*4)*96+k]=a0*isq; sc[(b*4+1)*96+k]=a1*isq;
    sc[(b*4+2)*96+k]=a2*isq; sc[(b*4+3)*96+k]=a3*isq;
  }
  __syncthreads();
  if(tid<64){
    float* row=sc+tid*96; float m=-INFINITY;
    for(int k=0;k<np;k++) m=fmaxf(m,row[k]);
    float s=0;
    for(int k=0;k<np;k++){ float e=expf(row[k]-m); row[k]=e; s+=e; }
    float inv=1.f/s;
    for(int k=0;k<np;k++) row[k]*=inv;
  }
  __syncthreads();
  for(int x=tid;x<4*on;x+=256){
    int h=x/on, i=x-h*on;
    for(int b=0;b<16;b++){
      const float* zr=g_zbuf+((size_t)(b*128+c)*2+slot)*ZLD;
      const float* ar=sc+(b*4+h)*96;
      float acc=0;
      for(int k=0;k<np;k++) acc+=ar[k]*zr[(size_t)k*on+i];
      us[(b*4+h)*96+i]=acc;
    }
  }
  __syncthreads();
  for(int j=tid;j<512;j+=256){
    int h=j>>7;
    float wacc[16];
#pragma unroll
    for(int b=0;b<16;b++) wacc[b]=0;
    for(int i=0;i<on;i++){
      float wv=WvAT[(size_t)i*512+j];
#pragma unroll
      for(int b=0;b<16;b++) wacc[b]+=wv*us[(b*4+h)*96+i];
    }
    float cvv=g_cvb[slot*512+j];
#pragma unroll
    for(int b=0;b<16;b++)
      g_ob[(size_t)slot*ROWS*512+(size_t)(b*128+c)*512+j]=wacc[b]+cvv;
  }
}

__global__ void k_ln(const float* __restrict__ g0,const float* __restrict__ b0,
                     const float* __restrict__ g1,const float* __restrict__ b1){
  __shared__ float red[8];
  int r=blockIdx.x, slot=blockIdx.y, tid=threadIdx.x;
  const float* g=slot?g1:g0;
  const float* bt=slot?b1:b0;
  const float* q=g_qb+((size_t)slot*ROWS+r)*512;
  const float* a=g_ab+((size_t)slot*ROWS+r)*512;
  float v0=q[tid]+a[tid], v1=q[tid+256]+a[tid+256];
  float s=v0+v1;
  for(int o=16;o;o>>=1) s+=__shfl_xor_sync(~0u,s,o);
  if((tid&31)==0) red[tid>>5]=s;
  __syncthreads();
  if(tid<8){ s=red[tid]; for(int o=4;o;o>>=1) s+=__shfl_xor_sync(0xff,s,o); red[0]=s; }
  __syncthreads();
  float mu=red[0]/512.f;
  __syncthreads();
  float d0=v0-mu, d1=v1-mu;
  s=d0*d0+d1*d1;
  for(int o=16;o;o>>=1) s+=__shfl_xor_sync(~0u,s,o);
  if((tid&31)==0) red[tid>>5]=s;
  __syncthreads();
  if(tid<8){ s=red[tid]; for(int o=4;o;o>>=1) s+=__shfl_xor_sync(0xff,s,o); red[0]=s; }
  __syncthreads();
  float inv=rsqrtf(red[0]/512.f+1e-5f);
  float* out=g_comb+(size_t)r*1536+slot*512;
  out[tid]=d0*inv*g[tid]+bt[tid];
  out[tid+256]=d1*inv*g[tid+256]+bt[tid+256];
}

extern "C" void kernel_launch(void* const* d_in, const int* in_sizes, int n_in,
                              void* d_out, int out_size){
  const float* x   =(const float*)d_in[0];
  const float* a12 =(const float*)d_in[1];
  const float* a24 =(const float*)d_in[2];
  const float* a48 =(const float*)d_in[3];
  const float* a96 =(const float*)d_in[4];
  const float* sb  =(const float*)d_in[5];
  const float* inw[2]={(const float*)d_in[6],(const float*)d_in[12]};
  const float* inb[2]={(const float*)d_in[7],(const float*)d_in[13]};
  const float* ow[2]={(const float*)d_in[8],(const float*)d_in[14]};
  const float* obi[2]={(const float*)d_in[9],(const float*)d_in[15]};
  const float* lng[2]={(const float*)d_in[10],(const float*)d_in[16]};
  const float* lnb[2]={(const float*)d_in[11],(const float*)d_in[17]};
  const float* fw1=(const float*)d_in[18];
  const float* fb1=(const float*)d_in[19];
  const float* fw2=(const float*)d_in[20];
  const float* fb2=(const float*)d_in[21];
  float* out=(float*)d_out;

  float *xinv,*Ptr,*anchT,*WkA,*WvAT,*qb,*Qb,*ob,*ab,*tz,*comb,*hb;
  cudaGetSymbolAddress((void**)&xinv,g_xinv);
  cudaGetSymbolAddress((void**)&Ptr,g_Ptr);
  cudaGetSymbolAddress((void**)&anchT,g_anchT);
  cudaGetSymbolAddress((void**)&WkA,g_WkA);
  cudaGetSymbolAddress((void**)&WvAT,g_WvAT);
  cudaGetSymbolAddress((void**)&qb,g_qb);
  cudaGetSymbolAddress((void**)&Qb,g_Qb);
  cudaGetSymbolAddress((void**)&ob,g_ob);
  cudaGetSymbolAddress((void**)&ab,g_ab);
  cudaGetSymbolAddress((void**)&tz,g_tz);
  cudaGetSymbolAddress((void**)&comb,g_comb);
  cudaGetSymbolAddress((void**)&hb,g_hb);

  k_xinv<<<(ROWS*384+255)/256,256>>>(x);
  k_acf<<<128,384>>>();
  k_periods<<<1,192>>>();
  k_build_P<<<dim3(190,2),192>>>();
  k_anchT<<<4,256>>>(a12,a24,a48,a96);
  k_cv<<<2,512>>>(inw[0],inb[0],inw[1],inb[1],sb);

  for(int s=0;s<2;s++)
    for(int a=0;a<4;a++){
      int on=(a==0)?12:(a==1)?24:(a==2)?48:96;
      gemm_nt<0><<<dim3((on+63)/64,4),256>>>(512,on,512,
        inw[s]+512*512,512, anchT+(size_t)a*96*512,512, nullptr,
        WkA+(size_t)(s*4+a)*512*96,96);
      gemm_nt<0><<<dim3(8,(on+127)/128),256>>>(on,512,512,
        anchT+(size_t)a*96*512,512, inw[s]+1024*512,512, nullptr,
        WvAT+(size_t)(s*4+a)*96*512,512);
    }

  k_tokenize<<<dim3(ROWS,2),128>>>(sb);
  for(int s=0;s<2;s++)
    gemm_nt<0><<<dim3(8,16),256>>>(ROWS,512,512,
      qb+(size_t)s*ROWS*512,512, inw[s],512, inb[s],
      Qb+(size_t)s*ROWS*512,512);

  k_attn<<<dim3(128,2),256>>>();

  for(int s=0;s<2;s++)
    gemm_nt<0><<<dim3(8,16),256>>>(ROWS,512,512,
      ob+(size_t)s*ROWS*512,512, ow[s],512, obi[s],
      ab+(size_t)s*ROWS*512,512);

  k_ln<<<dim3(ROWS,2),256>>>(lng[0],lnb[0],lng[1],lnb[1]);

  gemm_nt<0><<<dim3(2,16),256>>>(ROWS,96,384, xinv,384, Ptr,384, nullptr, tz,96);
  gemm_nt<0><<<dim3(8,16),256>>>(ROWS,512,96, tz,96, a96,96, sb, comb+1024,1536);

  gemm_nt<1><<<dim3(8,16),256>>>(ROWS,512,1536, comb,1536, fw1,1536, fb1, hb,512);
  gemm_nt<0><<<dim3(8,16),256>>>(ROWS,512,512, hb,512, fw2,512, fb2, out,512);
}

// round 12
// speedup vs baseline: 1.8853x; 1.0365x over previous
#include <cuda_runtime.h>
#include <math.h>
#include <stdint.h>

#define ROWS 2048
#define ZLD  1152
#define PSLOT 18432

__device__ float g_xinv[ROWS*384];
__device__ float g_acfA[384*128];
__device__ int   g_periods[256];
__device__ int   g_needed[193];
__device__ float g_P[189*PSLOT];
__device__ float g_Ptr[96*384];
__device__ float g_anchT[4*96*512];
__device__ float g_WkA[8*512*96];
__device__ float g_WvAT[8*96*512];
__device__ float g_cvb[2*512];
__device__ float g_zbuf[(size_t)ROWS*2*ZLD];
__device__ float g_qb[2*ROWS*512];
__device__ float g_Qb[2*ROWS*512];
__device__ float g_ob[2*ROWS*512];
__device__ float g_ab[2*ROWS*512];
__device__ float g_tz[ROWS*96];
__device__ float g_comb[ROWS*1536];
__device__ float g_hb[ROWS*512];

__device__ __host__ __forceinline__ int near_anchor(int L){
  return (L<=18)?12:(L<=36)?24:(L<=72)?48:96;
}
__device__ __forceinline__ int aidx_of(int o){ return (o==12)?0:(o==24)?1:(o==48)?2:3; }

__global__ void k_xinv(const float* __restrict__ x){
  int idx = blockIdx.x*256+threadIdx.x;
  if(idx>=ROWS*384) return;
  int t=idx%384, r=idx/384, b=r>>7, c=r&127;
  g_xinv[idx] = x[((size_t)b*384+t)*128+c];
}

__global__ void k_acf(){
  __shared__ float xs[16][384];
  __shared__ float bm[16];
  int c=blockIdx.x, tid=threadIdx.x;
  for(int i=tid;i<16*384;i+=blockDim.x){
    int b=i/384,t=i-b*384;
    xs[b][t]=g_xinv[((size_t)(b*128+c))*384+t];
  }
  __syncthreads();
  if(tid<16){ float s0=0,s1=0;
    for(int t=0;t<384;t+=2){ s0+=xs[tid][t]; s1+=xs[tid][t+1]; }
    bm[tid]=(s0+s1)/384.f; }
  __syncthreads();
  for(int i=tid;i<16*384;i+=blockDim.x){ int b=i/384; xs[b][i-b*384]-=bm[b]; }
  __syncthreads();
  for(int lag=tid;lag<384;lag+=blockDim.x){
    float acc=0.f;
    int n=384-lag;
    for(int b=0;b<16;b++){
      const float* r=xs[b];
      float s0=0.f,s1=0.f;
      int t=0;
      for(;t+1<n;t+=2){ s0=fmaf(r[t],r[t+lag],s0); s1=fmaf(r[t+1],r[t+1+lag],s1); }
      if(t<n) s0=fmaf(r[t],r[t+lag],s0);
      acc+=s0+s1;
    }
    g_acfA[lag*128+c]=acc/16.f;
  }
}

__global__ void k_periods(){
  int tid=threadIdx.x;
  for(int i=tid;i<193;i+=blockDim.x) g_needed[i]=0;
  __syncthreads();
  if(tid<128){
    int c=tid; float v1=-INFINITY,v2=-INFINITY; int i1=0,i2=1;
    for(int lag=4;lag<384;lag++){
      float v=g_acfA[lag*128+c];
      float pv=(lag==4)?-INFINITY:g_acfA[(lag-1)*128+c];
      float nv=(lag==383)?-INFINITY:g_acfA[(lag+1)*128+c];
      if(v>pv&&v>nv&&v>0.f){
        if(v>v1){v2=v1;i2=i1;v1=v;i1=lag;}
        else if(v>v2){v2=v;i2=lag;}
      }
    }
    int p1=min(max(i1,4),192), p2=min(max(i2,4),192);
    g_periods[c*2]=p1; g_periods[c*2+1]=p2;
    g_needed[p1]=1; g_needed[p2]=1;
  }
}

__global__ void k_build_P(){
  int bid=blockIdx.x; bool tr=(bid==189);
  int L=tr?384:bid+4;
  if(!tr && !g_needed[L]) return;
  int on=near_anchor(L);
  float* P = tr? g_Ptr : g_P + (size_t)bid*PSLOT;
  int tid=threadIdx.x;
  int gtid=blockIdx.y*192+tid;
  if(L==on){ for(int v=gtid;v<on*L;v+=384) P[v]=(v/L==v%L)?1.f:0.f; return; }
  __shared__ int i0s[384]; __shared__ float ws[384];
  __shared__ float ddf[96], llf[96];
  for(int j=tid;j<L;j+=192){
    float src=((float)j+0.5f)*(float)on/(float)L-0.5f;
    src=fminf(fmaxf(src,0.f),(float)(on-1));
    int i0=(int)src; i0s[j]=i0; ws[j]=src-(float)i0;
  }
  __syncthreads();
  int n=(L>on)?on:L;
  if(tid==0){
    float diag[96], sub[96];
    for(int i=0;i<96;i++){diag[i]=0;sub[i]=0;}
    if(L>on){
      for(int r=0;r<L;r++){ int i0=i0s[r]; float w=ws[r]; int i1=min(i0+1,on-1);
        float a,b; if(i1==i0){a=1;b=0;}else{a=1-w;b=w;}
        diag[i0]+=a*a; if(i1!=i0){diag[i1]+=b*b; sub[i0]+=a*b;} }
    } else {
      for(int r=0;r<L;r++){ int i0=i0s[r]; float w=ws[r]; int i1=min(i0+1,on-1);
        float a,b; if(i1==i0){a=1;b=0;}else{a=1-w;b=w;}
        diag[r]=a*a+b*b;
        if(r+1<L){ int j0=i0s[r+1]; float w2=ws[r+1]; int j1=min(j0+1,on-1);
          float cc,dv; if(j1==j0){cc=1;dv=0;}else{cc=1-w2;dv=w2;}
          float s=0;
          if(i0==j0)s+=a*cc; if(i0==j1&&j1!=j0)s+=a*dv;
          if(i1==j0&&i1!=i0)s+=b*cc; if(i1==j1&&i1!=i0&&j1!=j0)s+=b*dv;
          sub[r]=s; } }
    }
    ddf[0]=diag[0];
    for(int i=0;i+1<n;i++){ llf[i]=sub[i]/ddf[i]; ddf[i+1]=diag[i+1]-llf[i]*sub[i]; }
  }
  __syncthreads();
  float sc=sqrtf((float)L/(float)on);
  if(L>on){
    int j=gtid;
    if(j<L){
      float y[96];
      for(int i=0;i<n;i++) y[i]=0.f;
      int i0=i0s[j]; float w=ws[j]; int i1=min(i0+1,on-1);
      if(i1==i0) y[i0]=1.f; else { y[i0]=1.f-w; y[i1]=w; }
      for(int i=1;i<n;i++) y[i]-=llf[i-1]*y[i-1];
      for(int i=0;i<n;i++) y[i]/=ddf[i];
      for(int i=n-2;i>=0;i--) y[i]-=llf[i]*y[i+1];
      for(int i=0;i<n;i++) P[(size_t)i*L+j]=sc*y[i];
    }
  } else {
    int j=gtid;
    if(j<n){
      float y[96], col[96];
      for(int i=0;i<n;i++) y[i]=0.f;
      for(int i=0;i<96;i++) col[i]=0.f;
      y[j]=1.f;
      for(int i=1;i<n;i++) y[i]-=llf[i-1]*y[i-1];
      for(int i=0;i<n;i++) y[i]/=ddf[i];
      for(int i=n-2;i>=0;i--) y[i]-=llf[i]*y[i+1];
      for(int r=0;r<n;r++){ int i0=i0s[r]; float w=ws[r]; int i1=min(i0+1,on-1);
        if(i1==i0) col[i0]+=y[r]; else { col[i0]+=(1.f-w)*y[r]; col[i1]+=w*y[r]; } }
      for(int i=0;i<on;i++) P[(size_t)i*L+j]=sc*col[i];
    }
  }
}

__global__ void k_anchT(const float* a12,const float* a24,const float* a48,const float* a96){
  int a=blockIdx.x;
  const int olds[4]={12,24,48,96};
  const float* A=(a==0)?a12:(a==1)?a24:(a==2)?a48:a96;
  int on=olds[a];
  for(int idx=threadIdx.x;idx<512*on;idx+=blockDim.x){
    int j=idx/on, i=idx-j*on;
    g_anchT[(size_t)a*96*512 + (size_t)i*512 + j]=A[idx];
  }
}

__global__ void k_cv(const float* w1,const float* b1,const float* w2,const float* b2,
                     const float* sb){
  int s=blockIdx.x, j=threadIdx.x;
  const float* W = (s? w2:w1) + (size_t)(1024+j)*512;
  float acc = (s? b2:b1)[1024+j];
  for(int e=0;e<512;e++) acc += W[e]*sb[e];
  g_cvb[s*512+j]=acc;
}

// fp32 SIMT GEMM (small/odd shapes): C = A(MxK)@W(NxK)^T + bias
template<int EPI>
__global__ void __launch_bounds__(256) gemm_nt(
    int M,int N,int K,
    const float* __restrict__ A,int lda,
    const float* __restrict__ W,int ldw,
    const float* __restrict__ bias,
    float* __restrict__ C,int ldc)
{
  __shared__ __align__(16) float As[2][16][132];
  __shared__ __align__(16) float Ws[2][16][68];
  int bm=blockIdx.y*128, bn=blockIdx.x*64, tid=threadIdx.x;
  int tx=tid&15, ty=tid>>4;
  int lm=tid>>2, lk=(tid&3)*4;
  int m0=bm+lm, m1=bm+lm+64, nn=bn+lm;
  float acc[8][4]={};
  float4 pa0,pa1,pw;
  const float4 z4=make_float4(0,0,0,0);
  pa0=(m0<M)?*(const float4*)(A+(size_t)m0*lda+lk):z4;
  pa1=(m1<M)?*(const float4*)(A+(size_t)m1*lda+lk):z4;
  pw =(nn<N)?*(const float4*)(W+(size_t)nn*ldw+lk):z4;
  As[0][lk][lm]=pa0.x; As[0][lk+1][lm]=pa0.y; As[0][lk+2][lm]=pa0.z; As[0][lk+3][lm]=pa0.w;
  As[0][lk][lm+64]=pa1.x; As[0][lk+1][lm+64]=pa1.y; As[0][lk+2][lm+64]=pa1.z; As[0][lk+3][lm+64]=pa1.w;
  Ws[0][lk][lm]=pw.x; Ws[0][lk+1][lm]=pw.y; Ws[0][lk+2][lm]=pw.z; Ws[0][lk+3][lm]=pw.w;
  __syncthreads();
  for(int k0=0;k0<K;k0+=16){
    int buf=(k0>>4)&1;
    bool more=(k0+16<K);
    if(more){
      pa0=(m0<M)?*(const float4*)(A+(size_t)m0*lda+k0+16+lk):z4;
      pa1=(m1<M)?*(const float4*)(A+(size_t)m1*lda+k0+16+lk):z4;
      pw =(nn<N)?*(const float4*)(W+(size_t)nn*ldw+k0+16+lk):z4;
    }
#pragma unroll
    for(int kk=0;kk<16;kk++){
      float4 a0=*(float4*)&As[buf][kk][ty*8];
      float4 a1=*(float4*)&As[buf][kk][ty*8+4];
      float4 wv=*(float4*)&Ws[buf][kk][tx*4];
      float am[8]={a0.x,a0.y,a0.z,a0.w,a1.x,a1.y,a1.z,a1.w};
      float wm4[4]={wv.x,wv.y,wv.z,wv.w};
#pragma unroll
      for(int i=0;i<8;i++)
#pragma unroll
        for(int j=0;j<4;j++) acc[i][j]+=am[i]*wm4[j];
    }
    if(more){
      int nb=buf^1;
      As[nb][lk][lm]=pa0.x; As[nb][lk+1][lm]=pa0.y; As[nb][lk+2][lm]=pa0.z; As[nb][lk+3][lm]=pa0.w;
      As[nb][lk][lm+64]=pa1.x; As[nb][lk+1][lm+64]=pa1.y; As[nb][lk+2][lm+64]=pa1.z; As[nb][lk+3][lm+64]=pa1.w;
      Ws[nb][lk][lm]=pw.x; Ws[nb][lk+1][lm]=pw.y; Ws[nb][lk+2][lm]=pw.z; Ws[nb][lk+3][lm]=pw.w;
      __syncthreads();
    }
  }
#pragma unroll
  for(int i=0;i<8;i++){
    int m=bm+ty*8+i;
    if(m>=M) continue;
#pragma unroll
    for(int j=0;j<4;j++){
      int n2=bn+tx*4+j;
      if(n2<N){
        float v=acc[i][j]+(bias?bias[n2]:0.f);
        if(EPI==1) v=0.5f*v*(1.f+erff(v*0.70710678118654752f));
        C[(size_t)m*ldc+n2]=v;
      }
    }
  }
}

// TF32 tensor-core GEMM: C = A(MxK)@W(NxK)^T + bias. M%128==0, N%128==0, K%16==0.
// BM=128 BN=128 BK=16, 8 warps (4x2), warp tile 32x64 via m16n8k8.
__device__ __forceinline__ float4 cvt_tf32_4(const float* p){
  float4 v=*(const float4*)p;
  uint32_t o0,o1,o2,o3;
  asm("cvt.rna.tf32.f32 %0, %1;":"=r"(o0):"f"(v.x));
  asm("cvt.rna.tf32.f32 %0, %1;":"=r"(o1):"f"(v.y));
  asm("cvt.rna.tf32.f32 %0, %1;":"=r"(o2):"f"(v.z));
  asm("cvt.rna.tf32.f32 %0, %1;":"=r"(o3):"f"(v.w));
  float4 r;
  r.x=__uint_as_float(o0); r.y=__uint_as_float(o1);
  r.z=__uint_as_float(o2); r.w=__uint_as_float(o3);
  return r;
}
template<int EPI>
__global__ void __launch_bounds__(256) gemm_tf32(
    int M,int N,int K,
    const float* __restrict__ A,int lda,
    const float* __restrict__ W,int ldw,
    const float* __restrict__ bias,
    float* __restrict__ C,int ldc)
{
  __shared__ __align__(16) float As[2][128*20];
  __shared__ __align__(16) float Ws[2][128*20];
  int bm=blockIdx.y*128, bn=blockIdx.x*128;
  int tid=threadIdx.x;
  int warp=tid>>5, lane=tid&31;
  int wm=warp>>1, wn=warp&1;
  int g=lane>>2, t4=lane&3;
  int lr=tid>>1, lq=(tid&1)*8;
  float acc[2][8][4];
#pragma unroll
  for(int a=0;a<2;a++)
#pragma unroll
    for(int b=0;b<8;b++)
#pragma unroll
      for(int d=0;d<4;d++) acc[a][b][d]=0.f;

  const float* Arow=A+(size_t)(bm+lr)*lda;
  const float* Wrow=W+(size_t)(bn+lr)*ldw;
  {
    float4 a0=cvt_tf32_4(Arow+lq), a1=cvt_tf32_4(Arow+lq+4);
    float4 w0=cvt_tf32_4(Wrow+lq), w1=cvt_tf32_4(Wrow+lq+4);
    *(float4*)&As[0][lr*20+lq]=a0; *(float4*)&As[0][lr*20+lq+4]=a1;
    *(float4*)&Ws[0][lr*20+lq]=w0; *(float4*)&Ws[0][lr*20+lq+4]=w1;
  }
  __syncthreads();
  for(int k0=0;k0<K;k0+=16){
    int buf=(k0>>4)&1;
    bool more=(k0+16<K);
    float4 pa0,pa1,pw0,pw1;
    if(more){
      pa0=cvt_tf32_4(Arow+k0+16+lq); pa1=cvt_tf32_4(Arow+k0+16+lq+4);
      pw0=cvt_tf32_4(Wrow+k0+16+lq); pw1=cvt_tf32_4(Wrow+k0+16+lq+4);
    }
    const float* as=As[buf];
    const float* ws=Ws[buf];
#pragma unroll
    for(int kk=0;kk<2;kk++){
      int kof=kk*8+t4;
      uint32_t afr[2][4];
#pragma unroll
      for(int mt=0;mt<2;mt++){
        int mb=(wm*32+mt*16+g)*20+kof;
        afr[mt][0]=__float_as_uint(as[mb]);
        afr[mt][1]=__float_as_uint(as[mb+8*20]);
        afr[mt][2]=__float_as_uint(as[mb+4]);
        afr[mt][3]=__float_as_uint(as[mb+8*20+4]);
      }
#pragma unroll
      for(int nt=0;nt<8;nt++){
        int nb=(wn*64+nt*8+g)*20+kof;
        uint32_t b0=__float_as_uint(ws[nb]);
        uint32_t b1=__float_as_uint(ws[nb+4]);
#pragma unroll
        for(int mt=0;mt<2;mt++){
          asm("mma.sync.aligned.m16n8k8.row.col.f32.tf32.tf32.f32 "
              "{%0,%1,%2,%3}, {%4,%5,%6,%7}, {%8,%9}, {%0,%1,%2,%3};"
              : "+f"(acc[mt][nt][0]),"+f"(acc[mt][nt][1]),
                "+f"(acc[mt][nt][2]),"+f"(acc[mt][nt][3])
              : "r"(afr[mt][0]),"r"(afr[mt][1]),"r"(afr[mt][2]),"r"(afr[mt][3]),
                "r"(b0),"r"(b1));
        }
      }
    }
    if(more){
      int nb2=buf^1;
      *(float4*)&As[nb2][lr*20+lq]=pa0; *(float4*)&As[nb2][lr*20+lq+4]=pa1;
      *(float4*)&Ws[nb2][lr*20+lq]=pw0; *(float4*)&Ws[nb2][lr*20+lq+4]=pw1;
      __syncthreads();
    }
  }
#pragma unroll
  for(int mt=0;mt<2;mt++){
    int mrow=bm+wm*32+mt*16+g;
#pragma unroll
    for(int nt=0;nt<8;nt++){
      int ncol=bn+wn*64+nt*8+t4*2;
      float b0v=bias?bias[ncol]:0.f, b1v=bias?bias[ncol+1]:0.f;
      float v0=acc[mt][nt][0]+b0v, v1=acc[mt][nt][1]+b1v;
      float v2=acc[mt][nt][2]+b0v, v3=acc[mt][nt][3]+b1v;
      if(EPI==1){
        v0=0.5f*v0*(1.f+erff(v0*0.70710678118654752f));
        v1=0.5f*v1*(1.f+erff(v1*0.70710678118654752f));
        v2=0.5f*v2*(1.f+erff(v2*0.70710678118654752f));
        v3=0.5f*v3*(1.f+erff(v3*0.70710678118654752f));
      }
      *(float2*)(C+(size_t)mrow*ldc+ncol)=make_float2(v0,v1);
      *(float2*)(C+(size_t)(mrow+8)*ldc+ncol)=make_float2(v2,v3);
    }
  }
}

__global__ void k_tokenize(const float* __restrict__ sb){
  int r=blockIdx.x, slot=blockIdx.y, c=r&127, tid=threadIdx.x;
  int p=g_periods[c*2+slot], on=near_anchor(p), np=384/p, a=aidx_of(on);
  __shared__ float xs[384];
  __shared__ float zl[96];
  for(int t=tid;t<384;t+=128) xs[t]=g_xinv[(size_t)r*384+t];
  __syncthreads();
  const float* P=g_P+(size_t)(p-4)*PSLOT;
  float* z=g_zbuf+((size_t)r*2+slot)*ZLD;
  int tot=np*on;
  for(int idx=tid;idx<tot;idx+=128){
    int k=idx/on, i=idx-k*on;
    const float* Pr=P+(size_t)i*p;
    const float* xp=xs+k*p;
    float acc=0;
    for(int u=0;u<p;u++) acc+=Pr[u]*xp[u];
    z[idx]=acc;
    if(k==np-1) zl[i]=acc;
  }
  __syncthreads();
  const float* AT=g_anchT+(size_t)a*96*512;
  float* q=g_qb+((size_t)slot*ROWS+r)*512;
  for(int j=tid;j<512;j+=128){
    float acc=sb[j];
    for(int i=0;i<on;i++) acc+=AT[(size_t)i*512+j]*zl[i];
    q[j]=acc;
  }
}

__global__ void __launch_bounds__(256) k_attn(){
  __shared__ float us[6144];
  __shared__ float sc[6144];
  int c=blockIdx.x, slot=blockIdx.y, tid=threadIdx.x;
  int p=g_periods[c*2+slot], on=near_anchor(p), np=384/p, a=aidx_of(on);
  const float* WkA=g_WkA+(size_t)(slot*4+a)*512*96;
  const float* WvAT=g_WvAT+(size_t)(slot*4+a)*96*512;
  const float* Qb=g_Qb+(size_t)slot*ROWS*512;
  for(int hp=0;hp<2;hp++){
    for(int x=tid;x<4096;x+=256){
      int b=x>>8, rme=x&255;
      sc[x]=Qb[(size_t)(b*128+c)*512 + hp*256 + rme];
    }
    __syncthreads();
    for(int x=tid;x<2*on;x+=256){
      int hh=x/on, i=x-hh*on;
      int h=hp*2+hh;
      float acc[16];
#pragma unroll
      for(int b=0;b<16;b++) acc[b]=0;
      for(int e=0;e<128;e++){
        float wv=WkA[(size_t)(h*128+e)*96+i];
#pragma unroll
        for(int b=0;b<16;b++) acc[b]+=wv*sc[b*256+hh*128+e];
      }
#pragma unroll
      for(int b=0;b<16;b++) us[(b*4+h)*96+i]=acc[b];
    }
    __syncthreads();
  }
  const float isq=0.08838834764831845f;
  for(int x=tid;x<16*np;x+=256){
    int b=x/np, k=x-b*np;
    const float* zr=g_zbuf+((size_t)(b*128+c)*2+slot)*ZLD+(size_t)k*on;
    float a0=0,a1=0,a2=0,a3=0;
    for(int i=0;i<on;i++){ float zv=zr[i];
      a0+=us[(b*4)*96+i]*zv; a1+=us[(b*4+1)*96+i]*zv;
      a2+=us[(b*4+2)*96+i]*zv; a3+=us[(b*4+3)*96+i]*zv; }
    sc[(b*4)*96+k]=a0*isq; sc[(b*4+1)*96+k]=a1*isq;
    sc[(b*4+2)*96+k]=a2*isq; sc[(b*4+3)*96+k]=a3*isq;
  }
  __syncthreads();
  if(tid<64){
    float* row=sc+tid*96; float m=-INFINITY;
    for(int k=0;k<np;k++) m=fmaxf(m,row[k]);
    float s=0;
    for(int k=0;k<np;k++){ float e=expf(row[k]-m); row[k]=e; s+=e; }
    float inv=1.f/s;
    for(int k=0;k<np;k++) row[k]*=inv;
  }
  __syncthreads();
  for(int x=tid;x<4*on;x+=256){
    int h=x/on, i=x-h*on;
    for(int b=0;b<16;b++){
      const float* zr=g_zbuf+((size_t)(b*128+c)*2+slot)*ZLD;
      const float* ar=sc+(b*4+h)*96;
      float acc=0;
      for(int k=0;k<np;k++) acc+=ar[k]*zr[(size_t)k*on+i];
      us[(b*4+h)*96+i]=acc;
    }
  }
  __syncthreads();
  for(int j=tid;j<512;j+=256){
    int h=j>>7;
    float wacc[16];
#pragma unroll
    for(int b=0;b<16;b++) wacc[b]=0;
    for(int i=0;i<on;i++){
      float wv=WvAT[(size_t)i*512+j];
#pragma unroll
      for(int b=0;b<16;b++) wacc[b]+=wv*us[(b*4+h)*96+i];
    }
    float cvv=g_cvb[slot*512+j];
#pragma unroll
    for(int b=0;b<16;b++)
      g_ob[(size_t)slot*ROWS*512+(size_t)(b*128+c)*512+j]=wacc[b]+cvv;
  }
}

__global__ void k_ln(const float* __restrict__ g0,const float* __restrict__ b0,
                     const float* __restrict__ g1,const float* __restrict__ b1){
  __shared__ float red[8];
  int r=blockIdx.x, slot=blockIdx.y, tid=threadIdx.x;
  const float* g=slot?g1:g0;
  const float* bt=slot?b1:b0;
  const float* q=g_qb+((size_t)slot*ROWS+r)*512;
  const float* a=g_ab+((size_t)slot*ROWS+r)*512;
  float v0=q[tid]+a[tid], v1=q[tid+256]+a[tid+256];
  float s=v0+v1;
  for(int o=16;o;o>>=1) s+=__shfl_xor_sync(~0u,s,o);
  if((tid&31)==0) red[tid>>5]=s;
  __syncthreads();
  if(tid<8){ s=red[tid]; for(int o=4;o;o>>=1) s+=__shfl_xor_sync(0xff,s,o); red[0]=s; }
  __syncthreads();
  float mu=red[0]/512.f;
  __syncthreads();
  float d0=v0-mu, d1=v1-mu;
  s=d0*d0+d1*d1;
  for(int o=16;o;o>>=1) s+=__shfl_xor_sync(~0u,s,o);
  if((tid&31)==0) red[tid>>5]=s;
  __syncthreads();
  if(tid<8){ s=red[tid]; for(int o=4;o;o>>=1) s+=__shfl_xor_sync(0xff,s,o); red[0]=s; }
  __syncthreads();
  float inv=rsqrtf(red[0]/512.f+1e-5f);
  float* out=g_comb+(size_t)r*1536+slot*512;
  out[tid]=d0*inv*g[tid]+bt[tid];
  out[tid+256]=d1*inv*g[tid+256]+bt[tid+256];
}

extern "C" void kernel_launch(void* const* d_in, const int* in_sizes, int n_in,
                              void* d_out, int out_size){
  const float* x   =(const float*)d_in[0];
  const float* a12 =(const float*)d_in[1];
  const float* a24 =(const float*)d_in[2];
  const float* a48 =(const float*)d_in[3];
  const float* a96 =(const float*)d_in[4];
  const float* sb  =(const float*)d_in[5];
  const float* inw[2]={(const float*)d_in[6],(const float*)d_in[12]};
  const float* inb[2]={(const float*)d_in[7],(const float*)d_in[13]};
  const float* ow[2]={(const float*)d_in[8],(const float*)d_in[14]};
  const float* obi[2]={(const float*)d_in[9],(const float*)d_in[15]};
  const float* lng[2]={(const float*)d_in[10],(const float*)d_in[16]};
  const float* lnb[2]={(const float*)d_in[11],(const float*)d_in[17]};
  const float* fw1=(const float*)d_in[18];
  const float* fb1=(const float*)d_in[19];
  const float* fw2=(const float*)d_in[20];
  const float* fb2=(const float*)d_in[21];
  float* out=(float*)d_out;

  float *xinv,*Ptr,*anchT,*WkA,*WvAT,*qb,*Qb,*ob,*ab,*tz,*comb,*hb;
  cudaGetSymbolAddress((void**)&xinv,g_xinv);
  cudaGetSymbolAddress((void**)&Ptr,g_Ptr);
  cudaGetSymbolAddress((void**)&anchT,g_anchT);
  cudaGetSymbolAddress((void**)&WkA,g_WkA);
  cudaGetSymbolAddress((void**)&WvAT,g_WvAT);
  cudaGetSymbolAddress((void**)&qb,g_qb);
  cudaGetSymbolAddress((void**)&Qb,g_Qb);
  cudaGetSymbolAddress((void**)&ob,g_ob);
  cudaGetSymbolAddress((void**)&ab,g_ab);
  cudaGetSymbolAddress((void**)&tz,g_tz);
  cudaGetSymbolAddress((void**)&comb,g_comb);
  cudaGetSymbolAddress((void**)&hb,g_hb);

  k_xinv<<<(ROWS*384+255)/256,256>>>(x);
  k_acf<<<128,384>>>();
  k_periods<<<1,192>>>();
  k_build_P<<<dim3(190,2),192>>>();
  k_anchT<<<4,256>>>(a12,a24,a48,a96);
  k_cv<<<2,512>>>(inw[0],inb[0],inw[1],inb[1],sb);

  for(int s=0;s<2;s++)
    for(int a=0;a<4;a++){
      int on=(a==0)?12:(a==1)?24:(a==2)?48:96;
      gemm_nt<0><<<dim3((on+63)/64,4),256>>>(512,on,512,
        inw[s]+512*512,512, anchT+(size_t)a*96*512,512, nullptr,
        WkA+(size_t)(s*4+a)*512*96,96);
      gemm_nt<0><<<dim3(8,(on+127)/128),256>>>(on,512,512,
        anchT+(size_t)a*96*512,512, inw[s]+1024*512,512, nullptr,
        WvAT+(size_t)(s*4+a)*96*512,512);
    }

  k_tokenize<<<dim3(ROWS,2),128>>>(sb);
  for(int s=0;s<2;s++)
    gemm_tf32<0><<<dim3(4,16),256>>>(ROWS,512,512,
      qb+(size_t)s*ROWS*512,512, inw[s],512, inb[s],
      Qb+(size_t)s*ROWS*512,512);

  k_attn<<<dim3(128,2),256>>>();

  for(int s=0;s<2;s++)
    gemm_tf32<0><<<dim3(4,16),256>>>(ROWS,512,512,
      ob+(size_t)s*ROWS*512,512, ow[s],512, obi[s],
      ab+(size_t)s*ROWS*512,512);

  k_ln<<<dim3(ROWS,2),256>>>(lng[0],lnb[0],lng[1],lnb[1]);

  gemm_nt<0><<<dim3(2,16),256>>>(ROWS,96,384, xinv,384, Ptr,384, nullptr, tz,96);
  gemm_tf32<0><<<dim3(4,16),256>>>(ROWS,512,96, tz,96, a96,96, sb, comb+1024,1536);

  gemm_tf32<1><<<dim3(4,16),256>>>(ROWS,512,1536, comb,1536, fw1,1536, fb1, hb,512);
  gemm_tf32<0><<<dim3(4,16),256>>>(ROWS,512,512, hb,512, fw2,512, fb2, out,512);
}

// round 13
// speedup vs baseline: 2.7049x; 1.4347x over previous
#include <cuda_runtime.h>
#include <math.h>
#include <stdint.h>

#define ROWS 2048
#define ZLD  1152
#define PSLOT 18432

__device__ float g_xinv[ROWS*384];
__device__ float g_acfA[384*128];
__device__ int   g_periods[256];
__device__ int   g_needed[193];
__device__ float g_P[189*PSLOT];
__device__ float g_Ptr[96*384];
__device__ float g_anchT[4*96*512];
__device__ float g_WkA[8*512*96];
__device__ float g_WvAT[8*96*512];
__device__ float g_cvb[2*512];
__device__ float g_zbuf[(size_t)ROWS*2*ZLD];
__device__ float g_qb[2*ROWS*512];
__device__ float g_Qb[2*ROWS*512];
__device__ float g_ob[2*ROWS*512];
__device__ float g_ab[2*ROWS*512];
__device__ float g_tz[ROWS*96];
__device__ float g_comb[ROWS*1536];
__device__ float g_hb[ROWS*512];

__device__ __host__ __forceinline__ int near_anchor(int L){
  return (L<=18)?12:(L<=36)?24:(L<=72)?48:96;
}
__device__ __forceinline__ int aidx_of(int o){ return (o==12)?0:(o==24)?1:(o==48)?2:3; }

__global__ void k_xinv(const float* __restrict__ x){
  int idx = blockIdx.x*256+threadIdx.x;
  if(idx>=ROWS*384) return;
  int t=idx%384, r=idx/384, b=r>>7, c=r&127;
  g_xinv[idx] = x[((size_t)b*384+t)*128+c];
}

__global__ void k_acf(){
  __shared__ float xs[16][384];
  __shared__ float bm[16];
  int c=blockIdx.x, tid=threadIdx.x;
  for(int i=tid;i<16*384;i+=blockDim.x){
    int b=i/384,t=i-b*384;
    xs[b][t]=g_xinv[((size_t)(b*128+c))*384+t];
  }
  __syncthreads();
  if(tid<16){ float s0=0,s1=0;
    for(int t=0;t<384;t+=2){ s0+=xs[tid][t]; s1+=xs[tid][t+1]; }
    bm[tid]=(s0+s1)/384.f; }
  __syncthreads();
  for(int i=tid;i<16*384;i+=blockDim.x){ int b=i/384; xs[b][i-b*384]-=bm[b]; }
  __syncthreads();
  for(int lag=tid;lag<384;lag+=blockDim.x){
    float acc=0.f;
    int n=384-lag;
    for(int b=0;b<16;b++){
      const float* r=xs[b];
      float s0=0.f,s1=0.f;
      int t=0;
      for(;t+1<n;t+=2){ s0=fmaf(r[t],r[t+lag],s0); s1=fmaf(r[t+1],r[t+1+lag],s1); }
      if(t<n) s0=fmaf(r[t],r[t+lag],s0);
      acc+=s0+s1;
    }
    g_acfA[lag*128+c]=acc/16.f;
  }
}

__global__ void k_periods(){
  int tid=threadIdx.x;
  for(int i=tid;i<193;i+=blockDim.x) g_needed[i]=0;
  __syncthreads();
  if(tid<128){
    int c=tid; float v1=-INFINITY,v2=-INFINITY; int i1=0,i2=1;
    for(int lag=4;lag<384;lag++){
      float v=g_acfA[lag*128+c];
      float pv=(lag==4)?-INFINITY:g_acfA[(lag-1)*128+c];
      float nv=(lag==383)?-INFINITY:g_acfA[(lag+1)*128+c];
      if(v>pv&&v>nv&&v>0.f){
        if(v>v1){v2=v1;i2=i1;v1=v;i1=lag;}
        else if(v>v2){v2=v;i2=lag;}
      }
    }
    int p1=min(max(i1,4),192), p2=min(max(i2,4),192);
    g_periods[c*2]=p1; g_periods[c*2+1]=p2;
    g_needed[p1]=1; g_needed[p2]=1;
  }
}

// 96 threads/block, grid (190,4). Column solves live in shared (ys[i][tid]).
__global__ void __launch_bounds__(96) k_build_P(){
  int bid=blockIdx.x; bool tr=(bid==189);
  int L=tr?384:bid+4;
  if(!tr && !g_needed[L]) return;
  int on=near_anchor(L);
  float* P = tr? g_Ptr : g_P + (size_t)bid*PSLOT;
  int tid=threadIdx.x;
  int gtid=blockIdx.y*96+tid;
  if(L==on){ for(int v=gtid;v<on*L;v+=384) P[v]=(v/L==v%L)?1.f:0.f; return; }
  __shared__ int i0s[384]; __shared__ float ws[384];
  __shared__ float ddf[96], llf[96];
  __shared__ float ys[96][96];
  for(int j=tid;j<L;j+=96){
    float src=((float)j+0.5f)*(float)on/(float)L-0.5f;
    src=fminf(fmaxf(src,0.f),(float)(on-1));
    int i0=(int)src; i0s[j]=i0; ws[j]=src-(float)i0;
  }
  __syncthreads();
  int n=(L>on)?on:L;
  if(tid==0){
    float diag[96], sub[96];
    for(int i=0;i<96;i++){diag[i]=0;sub[i]=0;}
    if(L>on){
      for(int r=0;r<L;r++){ int i0=i0s[r]; float w=ws[r]; int i1=min(i0+1,on-1);
        float a,b; if(i1==i0){a=1;b=0;}else{a=1-w;b=w;}
        diag[i0]+=a*a; if(i1!=i0){diag[i1]+=b*b; sub[i0]+=a*b;} }
    } else {
      for(int r=0;r<L;r++){ int i0=i0s[r]; float w=ws[r]; int i1=min(i0+1,on-1);
        float a,b; if(i1==i0){a=1;b=0;}else{a=1-w;b=w;}
        diag[r]=a*a+b*b;
        if(r+1<L){ int j0=i0s[r+1]; float w2=ws[r+1]; int j1=min(j0+1,on-1);
          float cc,dv; if(j1==j0){cc=1;dv=0;}else{cc=1-w2;dv=w2;}
          float s=0;
          if(i0==j0)s+=a*cc; if(i0==j1&&j1!=j0)s+=a*dv;
          if(i1==j0&&i1!=i0)s+=b*cc; if(i1==j1&&i1!=i0&&j1!=j0)s+=b*dv;
          sub[r]=s; } }
    }
    ddf[0]=diag[0];
    for(int i=0;i+1<n;i++){ llf[i]=sub[i]/ddf[i]; ddf[i+1]=diag[i+1]-llf[i]*sub[i]; }
  }
  __syncthreads();
  float sc=sqrtf((float)L/(float)on);
  int j=gtid;
  if(L>on){
    if(j<L){
      for(int i=0;i<n;i++) ys[i][tid]=0.f;
      int i0=i0s[j]; float w=ws[j]; int i1=min(i0+1,on-1);
      if(i1==i0) ys[i0][tid]=1.f; else { ys[i0][tid]=1.f-w; ys[i1][tid]=w; }
      for(int i=1;i<n;i++) ys[i][tid]-=llf[i-1]*ys[i-1][tid];
      ys[n-1][tid]/=ddf[n-1];
      for(int i=n-2;i>=0;i--) ys[i][tid]=ys[i][tid]/ddf[i]-llf[i]*ys[i+1][tid];
      for(int i=0;i<n;i++) P[(size_t)i*L+j]=sc*ys[i][tid];
    }
  } else {
    if(j<n){
      float col[96];
      for(int i=0;i<n;i++) ys[i][tid]=0.f;
      for(int i=0;i<96;i++) col[i]=0.f;
      ys[j][tid]=1.f;
      for(int i=1;i<n;i++) ys[i][tid]-=llf[i-1]*ys[i-1][tid];
      ys[n-1][tid]/=ddf[n-1];
      for(int i=n-2;i>=0;i--) ys[i][tid]=ys[i][tid]/ddf[i]-llf[i]*ys[i+1][tid];
      for(int r=0;r<n;r++){ int i0=i0s[r]; float w=ws[r]; int i1=min(i0+1,on-1);
        float yv=ys[r][tid];
        if(i1==i0) col[i0]+=yv; else { col[i0]+=(1.f-w)*yv; col[i1]+=w*yv; } }
      for(int i=0;i<on;i++) P[(size_t)i*L+j]=sc*col[i];
    }
  }
}

__global__ void k_anchT(const float* a12,const float* a24,const float* a48,const float* a96){
  int a=blockIdx.x;
  const int olds[4]={12,24,48,96};
  const float* A=(a==0)?a12:(a==1)?a24:(a==2)?a48:a96;
  int on=olds[a];
  for(int idx=threadIdx.x;idx<512*on;idx+=blockDim.x){
    int j=idx/on, i=idx-j*on;
    g_anchT[(size_t)a*96*512 + (size_t)i*512 + j]=A[idx];
  }
}

__global__ void k_cv(const float* w1,const float* b1,const float* w2,const float* b2,
                     const float* sb){
  int s=blockIdx.x, j=threadIdx.x;
  const float* W = (s? w2:w1) + (size_t)(1024+j)*512;
  float acc = (s? b2:b1)[1024+j];
  for(int e=0;e<512;e++) acc += W[e]*sb[e];
  g_cvb[s*512+j]=acc;
}

// shared SIMT GEMM body: C=A(MxK)@W(NxK)^T+bias, BM=128 BN=64 BK=16, 256 thr
template<int EPI>
__device__ __forceinline__ void gemm_body(
    int M,int N,int K,
    const float* __restrict__ A,int lda,
    const float* __restrict__ W,int ldw,
    const float* __restrict__ bias,
    float* __restrict__ C,int ldc,
    int bm,int bn,
    float (*As)[16][132], float (*Ws)[16][68])
{
  int tid=threadIdx.x;
  int tx=tid&15, ty=tid>>4;
  int lm=tid>>2, lk=(tid&3)*4;
  int m0=bm+lm, m1=bm+lm+64, nn=bn+lm;
  float acc[8][4]={};
  float4 pa0,pa1,pw;
  const float4 z4=make_float4(0,0,0,0);
  pa0=(m0<M)?*(const float4*)(A+(size_t)m0*lda+lk):z4;
  pa1=(m1<M)?*(const float4*)(A+(size_t)m1*lda+lk):z4;
  pw =(nn<N)?*(const float4*)(W+(size_t)nn*ldw+lk):z4;
  As[0][lk][lm]=pa0.x; As[0][lk+1][lm]=pa0.y; As[0][lk+2][lm]=pa0.z; As[0][lk+3][lm]=pa0.w;
  As[0][lk][lm+64]=pa1.x; As[0][lk+1][lm+64]=pa1.y; As[0][lk+2][lm+64]=pa1.z; As[0][lk+3][lm+64]=pa1.w;
  Ws[0][lk][lm]=pw.x; Ws[0][lk+1][lm]=pw.y; Ws[0][lk+2][lm]=pw.z; Ws[0][lk+3][lm]=pw.w;
  __syncthreads();
  for(int k0=0;k0<K;k0+=16){
    int buf=(k0>>4)&1;
    bool more=(k0+16<K);
    if(more){
      pa0=(m0<M)?*(const float4*)(A+(size_t)m0*lda+k0+16+lk):z4;
      pa1=(m1<M)?*(const float4*)(A+(size_t)m1*lda+k0+16+lk):z4;
      pw =(nn<N)?*(const float4*)(W+(size_t)nn*ldw+k0+16+lk):z4;
    }
#pragma unroll
    for(int kk=0;kk<16;kk++){
      float4 a0=*(float4*)&As[buf][kk][ty*8];
      float4 a1=*(float4*)&As[buf][kk][ty*8+4];
      float4 wv=*(float4*)&Ws[buf][kk][tx*4];
      float am[8]={a0.x,a0.y,a0.z,a0.w,a1.x,a1.y,a1.z,a1.w};
      float wm4[4]={wv.x,wv.y,wv.z,wv.w};
#pragma unroll
      for(int i=0;i<8;i++)
#pragma unroll
        for(int j=0;j<4;j++) acc[i][j]+=am[i]*wm4[j];
    }
    if(more){
      int nb=buf^1;
      As[nb][lk][lm]=pa0.x; As[nb][lk+1][lm]=pa0.y; As[nb][lk+2][lm]=pa0.z; As[nb][lk+3][lm]=pa0.w;
      As[nb][lk][lm+64]=pa1.x; As[nb][lk+1][lm+64]=pa1.y; As[nb][lk+2][lm+64]=pa1.z; As[nb][lk+3][lm+64]=pa1.w;
      Ws[nb][lk][lm]=pw.x; Ws[nb][lk+1][lm]=pw.y; Ws[nb][lk+2][lm]=pw.z; Ws[nb][lk+3][lm]=pw.w;
      __syncthreads();
    }
  }
#pragma unroll
  for(int i=0;i<8;i++){
    int m=bm+ty*8+i;
    if(m>=M) continue;
#pragma unroll
    for(int j=0;j<4;j++){
      int n2=bn+tx*4+j;
      if(n2<N){
        float v=acc[i][j]+(bias?bias[n2]:0.f);
        if(EPI==1) v=0.5f*v*(1.f+erff(v*0.70710678118654752f));
        C[(size_t)m*ldc+n2]=v;
      }
    }
  }
}

template<int EPI>
__global__ void __launch_bounds__(256) gemm_nt(
    int M,int N,int K,
    const float* __restrict__ A,int lda,
    const float* __restrict__ W,int ldw,
    const float* __restrict__ bias,
    float* __restrict__ C,int ldc)
{
  __shared__ __align__(16) float As[2][16][132];
  __shared__ __align__(16) float Ws[2][16][68];
  gemm_body<EPI>(M,N,K,A,lda,W,ldw,bias,C,ldc,blockIdx.y*128,blockIdx.x*64,As,Ws);
}

// all 16 WkA/WvAT GEMMs in one launch. z: kv=z&1, a=(z>>1)&3, s=z>>3
__global__ void __launch_bounds__(256) k_smallgemm(
    const float* __restrict__ inw0, const float* __restrict__ inw1)
{
  __shared__ __align__(16) float As[2][16][132];
  __shared__ __align__(16) float Ws[2][16][68];
  int z=blockIdx.z;
  int kv=z&1, a=(z>>1)&3, s=z>>3;
  int on=12<<a;
  const float* inw = s? inw1 : inw0;
  const float* anch = g_anchT + (size_t)a*96*512;
  int M,N; const float *A,*W; float* C; int ldc;
  if(kv==0){
    M=512; N=on; A=inw+512*512; W=anch; C=g_WkA+(size_t)(s*4+a)*512*96; ldc=96;
  } else {
    M=on; N=512; A=anch; W=inw+1024*512; C=g_WvAT+(size_t)(s*4+a)*96*512; ldc=512;
  }
  int bm=blockIdx.y*128, bn=blockIdx.x*64;
  if(bm>=M||bn>=N) return;
  gemm_body<0>(M,N,512,A,512,W,512,nullptr,C,ldc,bm,bn,As,Ws);
}

// TF32 tensor-core GEMM, z-batched (2 weight sets / strided A,C).
__device__ __forceinline__ float4 cvt_tf32_4(const float* p){
  float4 v=*(const float4*)p;
  uint32_t o0,o1,o2,o3;
  asm("cvt.rna.tf32.f32 %0, %1;":"=r"(o0):"f"(v.x));
  asm("cvt.rna.tf32.f32 %0, %1;":"=r"(o1):"f"(v.y));
  asm("cvt.rna.tf32.f32 %0, %1;":"=r"(o2):"f"(v.z));
  asm("cvt.rna.tf32.f32 %0, %1;":"=r"(o3):"f"(v.w));
  float4 r;
  r.x=__uint_as_float(o0); r.y=__uint_as_float(o1);
  r.z=__uint_as_float(o2); r.w=__uint_as_float(o3);
  return r;
}
template<int EPI>
__global__ void __launch_bounds__(256) gemm_tf32_b(
    int M,int N,int K,
    const float* __restrict__ A0,int lda,size_t sA,
    const float* __restrict__ W0,const float* __restrict__ W1,int ldw,
    const float* __restrict__ b0,const float* __restrict__ b1,
    float* __restrict__ C0,int ldc,size_t sC)
{
  __shared__ __align__(16) float As[2][128*20];
  __shared__ __align__(16) float Ws[2][128*20];
  int z=blockIdx.z;
  const float* A=A0+(size_t)z*sA;
  const float* W=z?W1:W0;
  const float* bias=z?b1:b0;
  float* C=C0+(size_t)z*sC;
  int bm=blockIdx.y*128, bn=blockIdx.x*128;
  int tid=threadIdx.x;
  int warp=tid>>5, lane=tid&31;
  int wm=warp>>1, wn=warp&1;
  int g=lane>>2, t4=lane&3;
  int lr=tid>>1, lq=(tid&1)*8;
  float acc[2][8][4];
#pragma unroll
  for(int a=0;a<2;a++)
#pragma unroll
    for(int b=0;b<8;b++)
#pragma unroll
      for(int d=0;d<4;d++) acc[a][b][d]=0.f;
  const float* Arow=A+(size_t)(bm+lr)*lda;
  const float* Wrow=W+(size_t)(bn+lr)*ldw;
  {
    float4 a0=cvt_tf32_4(Arow+lq), a1=cvt_tf32_4(Arow+lq+4);
    float4 w0=cvt_tf32_4(Wrow+lq), w1=cvt_tf32_4(Wrow+lq+4);
    *(float4*)&As[0][lr*20+lq]=a0; *(float4*)&As[0][lr*20+lq+4]=a1;
    *(float4*)&Ws[0][lr*20+lq]=w0; *(float4*)&Ws[0][lr*20+lq+4]=w1;
  }
  __syncthreads();
  for(int k0=0;k0<K;k0+=16){
    int buf=(k0>>4)&1;
    bool more=(k0+16<K);
    float4 pa0,pa1,pw0,pw1;
    if(more){
      pa0=cvt_tf32_4(Arow+k0+16+lq); pa1=cvt_tf32_4(Arow+k0+16+lq+4);
      pw0=cvt_tf32_4(Wrow+k0+16+lq); pw1=cvt_tf32_4(Wrow+k0+16+lq+4);
    }
    const float* as=As[buf];
    const float* ws=Ws[buf];
#pragma unroll
    for(int kk=0;kk<2;kk++){
      int kof=kk*8+t4;
      uint32_t afr[2][4];
#pragma unroll
      for(int mt=0;mt<2;mt++){
        int mb=(wm*32+mt*16+g)*20+kof;
        afr[mt][0]=__float_as_uint(as[mb]);
        afr[mt][1]=__float_as_uint(as[mb+8*20]);
        afr[mt][2]=__float_as_uint(as[mb+4]);
        afr[mt][3]=__float_as_uint(as[mb+8*20+4]);
      }
#pragma unroll
      for(int nt=0;nt<8;nt++){
        int nb=(wn*64+nt*8+g)*20+kof;
        uint32_t bb0=__float_as_uint(ws[nb]);
        uint32_t bb1=__float_as_uint(ws[nb+4]);
#pragma unroll
        for(int mt=0;mt<2;mt++){
          asm("mma.sync.aligned.m16n8k8.row.col.f32.tf32.tf32.f32 "
              "{%0,%1,%2,%3}, {%4,%5,%6,%7}, {%8,%9}, {%0,%1,%2,%3};"
              : "+f"(acc[mt][nt][0]),"+f"(acc[mt][nt][1]),
                "+f"(acc[mt][nt][2]),"+f"(acc[mt][nt][3])
              : "r"(afr[mt][0]),"r"(afr[mt][1]),"r"(afr[mt][2]),"r"(afr[mt][3]),
                "r"(bb0),"r"(bb1));
        }
      }
    }
    if(more){
      int nb2=buf^1;
      *(float4*)&As[nb2][lr*20+lq]=pa0; *(float4*)&As[nb2][lr*20+lq+4]=pa1;
      *(float4*)&Ws[nb2][lr*20+lq]=pw0; *(float4*)&Ws[nb2][lr*20+lq+4]=pw1;
      __syncthreads();
    }
  }
#pragma unroll
  for(int mt=0;mt<2;mt++){
    int mrow=bm+wm*32+mt*16+g;
#pragma unroll
    for(int nt=0;nt<8;nt++){
      int ncol=bn+wn*64+nt*8+t4*2;
      float b0v=bias?bias[ncol]:0.f, b1v=bias?bias[ncol+1]:0.f;
      float v0=acc[mt][nt][0]+b0v, v1=acc[mt][nt][1]+b1v;
      float v2=acc[mt][nt][2]+b0v, v3=acc[mt][nt][3]+b1v;
      if(EPI==1){
        v0=0.5f*v0*(1.f+erff(v0*0.70710678118654752f));
        v1=0.5f*v1*(1.f+erff(v1*0.70710678118654752f));
        v2=0.5f*v2*(1.f+erff(v2*0.70710678118654752f));
        v3=0.5f*v3*(1.f+erff(v3*0.70710678118654752f));
      }
      *(float2*)(C+(size_t)mrow*ldc+ncol)=make_float2(v0,v1);
      *(float2*)(C+(size_t)(mrow+8)*ldc+ncol)=make_float2(v2,v3);
    }
  }
}

__global__ void k_tokenize(const float* __restrict__ sb){
  int r=blockIdx.x, slot=blockIdx.y, c=r&127, tid=threadIdx.x;
  int p=g_periods[c*2+slot], on=near_anchor(p), np=384/p, a=aidx_of(on);
  __shared__ float xs[384];
  __shared__ float zl[96];
  for(int t=tid;t<384;t+=128) xs[t]=g_xinv[(size_t)r*384+t];
  __syncthreads();
  const float* P=g_P+(size_t)(p-4)*PSLOT;
  float* z=g_zbuf+((size_t)r*2+slot)*ZLD;
  int tot=np*on;
  for(int idx=tid;idx<tot;idx+=128){
    int k=idx/on, i=idx-k*on;
    const float* Pr=P+(size_t)i*p;
    const float* xp=xs+k*p;
    float acc=0;
    for(int u=0;u<p;u++) acc+=Pr[u]*xp[u];
    z[idx]=acc;
    if(k==np-1) zl[i]=acc;
  }
  __syncthreads();
  const float* AT=g_anchT+(size_t)a*96*512;
  float* q=g_qb+((size_t)slot*ROWS+r)*512;
  for(int j=tid;j<512;j+=128){
    float acc=sb[j];
    for(int i=0;i<on;i++) acc+=AT[(size_t)i*512+j]*zl[i];
    q[j]=acc;
  }
}

__global__ void __launch_bounds__(256) k_attn(){
  __shared__ float us[6144];
  __shared__ float sc[6144];
  int c=blockIdx.x, slot=blockIdx.y, tid=threadIdx.x;
  int p=g_periods[c*2+slot], on=near_anchor(p), np=384/p, a=aidx_of(on);
  const float* WkA=g_WkA+(size_t)(slot*4+a)*512*96;
  const float* WvAT=g_WvAT+(size_t)(slot*4+a)*96*512;
  const float* Qb=g_Qb+(size_t)slot*ROWS*512;
  for(int hp=0;hp<2;hp++){
    for(int x=tid;x<4096;x+=256){
      int b=x>>8, rme=x&255;
      sc[x]=Qb[(size_t)(b*128+c)*512 + hp*256 + rme];
    }
    __syncthreads();
    for(int x=tid;x<2*on;x+=256){
      int hh=x/on, i=x-hh*on;
      int h=hp*2+hh;
      float acc[16];
#pragma unroll
      for(int b=0;b<16;b++) acc[b]=0;
      for(int e=0;e<128;e++){
        float wv=WkA[(size_t)(h*128+e)*96+i];
#pragma unroll
        for(int b=0;b<16;b++) acc[b]+=wv*sc[b*256+hh*128+e];
      }
#pragma unroll
      for(int b=0;b<16;b++) us[(b*4+h)*96+i]=acc[b];
    }
    __syncthreads();
  }
  const float isq=0.08838834764831845f;
  for(int x=tid;x<16*np;x+=256){
    int b=x/np, k=x-b*np;
    const float* zr=g_zbuf+((size_t)(b*128+c)*2+slot)*ZLD+(size_t)k*on;
    float a0=0,a1=0,a2=0,a3=0;
    for(int i=0;i<on;i++){ float zv=zr[i];
      a0+=us[(b*4)*96+i]*zv; a1+=us[(b*4+1)*96+i]*zv;
      a2+=us[(b*4+2)*96+i]*zv; a3+=us[(b*4+3)*96+i]*zv; }
    sc[(b*4)*96+k]=a0*isq; sc[(b*4+1)*96+k]=a1*isq;
    sc[(b*4+2)*96+k]=a2*isq; sc[(b*4+3)*96+k]=a3*isq;
  }
  __syncthreads();
  if(tid<64){
    float* row=sc+tid*96; float m=-INFINITY;
    for(int k=0;k<np;k++) m=fmaxf(m,row[k]);
    float s=0;
    for(int k=0;k<np;k++){ float e=expf(row[k]-m); row[k]=e; s+=e; }
    float inv=1.f/s;
    for(int k=0;k<np;k++) row[k]*=inv;
  }
  __syncthreads();
  for(int x=tid;x<4*on;x+=256){
    int h=x/on, i=x-h*on;
    for(int b=0;b<16;b++){
      const float* zr=g_zbuf+((size_t)(b*128+c)*2+slot)*ZLD;
      const float* ar=sc+(b*4+h)*96;
      float acc=0;
      for(int k=0;k<np;k++) acc+=ar[k]*zr[(size_t)k*on+i];
      us[(b*4+h)*96+i]=acc;
    }
  }
  __syncthreads();
  for(int j=tid;j<512;j+=256){
    int h=j>>7;
    float wacc[16];
#pragma unroll
    for(int b=0;b<16;b++) wacc[b]=0;
    for(int i=0;i<on;i++){
      float wv=WvAT[(size_t)i*512+j];
#pragma unroll
      for(int b=0;b<16;b++) wacc[b]+=wv*us[(b*4+h)*96+i];
    }
    float cvv=g_cvb[slot*512+j];
#pragma unroll
    for(int b=0;b<16;b++)
      g_ob[(size_t)slot*ROWS*512+(size_t)(b*128+c)*512+j]=wacc[b]+cvv;
  }
}

__global__ void k_ln(const float* __restrict__ g0,const float* __restrict__ b0,
                     const float* __restrict__ g1,const float* __restrict__ b1){
  __shared__ float red[8];
  int r=blockIdx.x, slot=blockIdx.y, tid=threadIdx.x;
  const float* g=slot?g1:g0;
  const float* bt=slot?b1:b0;
  const float* q=g_qb+((size_t)slot*ROWS+r)*512;
  const float* a=g_ab+((size_t)slot*ROWS+r)*512;
  float v0=q[tid]+a[tid], v1=q[tid+256]+a[tid+256];
  float s=v0+v1;
  for(int o=16;o;o>>=1) s+=__shfl_xor_sync(~0u,s,o);
  if((tid&31)==0) red[tid>>5]=s;
  __syncthreads();
  if(tid<8){ s=red[tid]; for(int o=4;o;o>>=1) s+=__shfl_xor_sync(0xff,s,o); red[0]=s; }
  __syncthreads();
  float mu=red[0]/512.f;
  __syncthreads();
  float d0=v0-mu, d1=v1-mu;
  s=d0*d0+d1*d1;
  for(int o=16;o;o>>=1) s+=__shfl_xor_sync(~0u,s,o);
  if((tid&31)==0) red[tid>>5]=s;
  __syncthreads();
  if(tid<8){ s=red[tid]; for(int o=4;o;o>>=1) s+=__shfl_xor_sync(0xff,s,o); red[0]=s; }
  __syncthreads();
  float inv=rsqrtf(red[0]/512.f+1e-5f);
  float* out=g_comb+(size_t)r*1536+slot*512;
  out[tid]=d0*inv*g[tid]+bt[tid];
  out[tid+256]=d1*inv*g[tid+256]+bt[tid+256];
}

extern "C" void kernel_launch(void* const* d_in, const int* in_sizes, int n_in,
                              void* d_out, int out_size){
  const float* x   =(const float*)d_in[0];
  const float* a12 =(const float*)d_in[1];
  const float* a24 =(const float*)d_in[2];
  const float* a48 =(const float*)d_in[3];
  const float* a96 =(const float*)d_in[4];
  const float* sb  =(const float*)d_in[5];
  const float* inw[2]={(const float*)d_in[6],(const float*)d_in[12]};
  const float* inb[2]={(const float*)d_in[7],(const float*)d_in[13]};
  const float* ow[2]={(const float*)d_in[8],(const float*)d_in[14]};
  const float* obi[2]={(const float*)d_in[9],(const float*)d_in[15]};
  const float* lng[2]={(const float*)d_in[10],(const float*)d_in[16]};
  const float* lnb[2]={(const float*)d_in[11],(const float*)d_in[17]};
  const float* fw1=(const float*)d_in[18];
  const float* fb1=(const float*)d_in[19];
  const float* fw2=(const float*)d_in[20];
  const float* fb2=(const float*)d_in[21];
  float* out=(float*)d_out;

  float *xinv,*Ptr,*qb,*Qb,*ob,*ab,*tz,*comb,*hb;
  cudaGetSymbolAddress((void**)&xinv,g_xinv);
  cudaGetSymbolAddress((void**)&Ptr,g_Ptr);
  cudaGetSymbolAddress((void**)&qb,g_qb);
  cudaGetSymbolAddress((void**)&Qb,g_Qb);
  cudaGetSymbolAddress((void**)&ob,g_ob);
  cudaGetSymbolAddress((void**)&ab,g_ab);
  cudaGetSymbolAddress((void**)&tz,g_tz);
  cudaGetSymbolAddress((void**)&comb,g_comb);
  cudaGetSymbolAddress((void**)&hb,g_hb);

  const size_t SL=(size_t)ROWS*512;

  k_xinv<<<(ROWS*384+255)/256,256>>>(x);
  k_acf<<<128,384>>>();
  k_periods<<<1,192>>>();
  k_build_P<<<dim3(190,4),96>>>();
  k_anchT<<<4,256>>>(a12,a24,a48,a96);
  k_cv<<<2,512>>>(inw[0],inb[0],inw[1],inb[1],sb);

  k_smallgemm<<<dim3(8,4,16),256>>>(inw[0],inw[1]);

  k_tokenize<<<dim3(ROWS,2),128>>>(sb);

  gemm_tf32_b<0><<<dim3(4,16,2),256>>>(ROWS,512,512,
    qb,512,SL, inw[0],inw[1],512, inb[0],inb[1], Qb,512,SL);

  k_attn<<<dim3(128,2),256>>>();

  gemm_tf32_b<0><<<dim3(4,16,2),256>>>(ROWS,512,512,
    ob,512,SL, ow[0],ow[1],512, obi[0],obi[1], ab,512,SL);

  k_ln<<<dim3(ROWS,2),256>>>(lng[0],lnb[0],lng[1],lnb[1]);

  gemm_nt<0><<<dim3(2,16),256>>>(ROWS,96,384, xinv,384, Ptr,384, nullptr, tz,96);
  gemm_tf32_b<0><<<dim3(4,16,1),256>>>(ROWS,512,96,
    tz,96,0, a96,a96,96, sb,sb, comb+1024,1536,0);

  gemm_tf32_b<1><<<dim3(4,16,1),256>>>(ROWS,512,1536,
    comb,1536,0, fw1,fw1,1536, fb1,fb1, hb,512,0);
  gemm_tf32_b<0><<<dim3(4,16,1),256>>>(ROWS,512,512,
    hb,512,0, fw2,fw2,512, fb2,fb2, out,512,0);
}

// round 14
// speedup vs baseline: 2.9429x; 1.0880x over previous
#include <cuda_runtime.h>
#include <math.h>
#include <stdint.h>

#define ROWS 2048
#define ZLD  1152
#define PSLOT 18432
#define CLD  1136

__device__ float g_xinv[ROWS*384];
__device__ float g_acfA[384*128];
__device__ int   g_periods[256];
__device__ int   g_needed[193];
__device__ float g_P[189*PSLOT];
__device__ float g_Ptr[96*384];
__device__ float g_anchT[4*96*512];
__device__ float g_WkA[8*512*96];
__device__ float g_WvAT[8*96*512];
__device__ float g_cvb[2*512];
__device__ float g_cc[512];
__device__ float g_fw1m[512*CLD];
__device__ float g_zbuf[(size_t)ROWS*2*ZLD];
__device__ float g_qb[2*ROWS*512];
__device__ float g_Qb[2*ROWS*512];
__device__ float g_ob[2*ROWS*512];
__device__ float g_ab[2*ROWS*512];
__device__ float g_comb2[(size_t)ROWS*CLD];
__device__ float g_hb[ROWS*512];

__device__ __host__ __forceinline__ int near_anchor(int L){
  return (L<=18)?12:(L<=36)?24:(L<=72)?48:96;
}
__device__ __forceinline__ int aidx_of(int o){ return (o==12)?0:(o==24)?1:(o==48)?2:3; }

__global__ void k_xinv(const float* __restrict__ x){
  int idx = blockIdx.x*256+threadIdx.x;
  if(idx>=ROWS*384) return;
  int t=idx%384, r=idx/384, b=r>>7, c=r&127;
  g_xinv[idx] = x[((size_t)b*384+t)*128+c];
}

// 96 threads: each owns 4 consecutive lags, register sliding window.
__global__ void __launch_bounds__(96) k_acf(const float* __restrict__ x){
  __shared__ float xs[16][388];
  __shared__ float bm[16];
  int c=blockIdx.x, tid=threadIdx.x;
  for(int i=tid;i<16*384;i+=96){
    int b=i/384,t=i-b*384;
    xs[b][t]=x[((size_t)b*384+t)*128+c];
  }
  if(tid<64) xs[tid>>2][384+(tid&3)]=0.f;
  __syncthreads();
  if(tid<16){ float s0=0,s1=0;
    for(int t=0;t<384;t+=2){ s0+=xs[tid][t]; s1+=xs[tid][t+1]; }
    bm[tid]=(s0+s1)/384.f; }
  __syncthreads();
  for(int i=tid;i<16*384;i+=96){ int b=i/384; xs[b][i-b*384]-=bm[b]; }
  __syncthreads();
  int l=tid*4;
  float a0=0,a1=0,a2=0,a3=0;
  int n=384-l;
  for(int b=0;b<16;b++){
    const float* r=xs[b];
    float w0=r[l],w1=r[l+1],w2=r[l+2],w3=r[l+3];
    for(int t=0;t<n;t++){
      float rv=r[t];
      a0=fmaf(rv,w0,a0); a1=fmaf(rv,w1,a1);
      a2=fmaf(rv,w2,a2); a3=fmaf(rv,w3,a3);
      w0=w1; w1=w2; w2=w3; w3=r[t+l+4];
    }
  }
  g_acfA[l*128+c]=a0*0.0625f;
  g_acfA[(l+1)*128+c]=a1*0.0625f;
  g_acfA[(l+2)*128+c]=a2*0.0625f;
  g_acfA[(l+3)*128+c]=a3*0.0625f;
}

__global__ void k_periods(){
  int tid=threadIdx.x;
  for(int i=tid;i<193;i+=blockDim.x) g_needed[i]=0;
  __syncthreads();
  if(tid<128){
    int c=tid; float v1=-INFINITY,v2=-INFINITY; int i1=0,i2=1;
    float pv=-INFINITY;
    float v=g_acfA[4*128+c];
    for(int lag=4;lag<384;lag++){
      float nv=(lag==383)?-INFINITY:g_acfA[(lag+1)*128+c];
      if(v>pv&&v>nv&&v>0.f){
        if(v>v1){v2=v1;i2=i1;v1=v;i1=lag;}
        else if(v>v2){v2=v;i2=lag;}
      }
      pv=v; v=nv;
    }
    int p1=min(max(i1,4),192), p2=min(max(i2,4),192);
    g_periods[c*2]=p1; g_periods[c*2+1]=p2;
    g_needed[p1]=1; g_needed[p2]=1;
  }
}

__global__ void __launch_bounds__(192) k_build_P(){
  int bid=blockIdx.x; bool tr=(bid==189);
  int L=tr?384:bid+4;
  if(!tr && !g_needed[L]) return;
  int on=near_anchor(L);
  float* P = tr? g_Ptr : g_P + (size_t)bid*PSLOT;
  int tid=threadIdx.x;
  int gtid=blockIdx.y*192+tid;
  if(L==on){ for(int v=gtid;v<on*L;v+=384) P[v]=(v/L==v%L)?1.f:0.f; return; }
  __shared__ int i0s[384]; __shared__ float ws[384];
  __shared__ float ddf[96], llf[96];
  for(int j=tid;j<L;j+=192){
    float src=((float)j+0.5f)*(float)on/(float)L-0.5f;
    src=fminf(fmaxf(src,0.f),(float)(on-1));
    int i0=(int)src; i0s[j]=i0; ws[j]=src-(float)i0;
  }
  __syncthreads();
  int n=(L>on)?on:L;
  if(tid==0){
    float diag[96], sub[96];
    for(int i=0;i<96;i++){diag[i]=0;sub[i]=0;}
    if(L>on){
      for(int r=0;r<L;r++){ int i0=i0s[r]; float w=ws[r]; int i1=min(i0+1,on-1);
        float a,b; if(i1==i0){a=1;b=0;}else{a=1-w;b=w;}
        diag[i0]+=a*a; if(i1!=i0){diag[i1]+=b*b; sub[i0]+=a*b;} }
    } else {
      for(int r=0;r<L;r++){ int i0=i0s[r]; float w=ws[r]; int i1=min(i0+1,on-1);
        float a,b; if(i1==i0){a=1;b=0;}else{a=1-w;b=w;}
        diag[r]=a*a+b*b;
        if(r+1<L){ int j0=i0s[r+1]; float w2=ws[r+1]; int j1=min(j0+1,on-1);
          float cc,dv; if(j1==j0){cc=1;dv=0;}else{cc=1-w2;dv=w2;}
          float s=0;
          if(i0==j0)s+=a*cc; if(i0==j1&&j1!=j0)s+=a*dv;
          if(i1==j0&&i1!=i0)s+=b*cc; if(i1==j1&&i1!=i0&&j1!=j0)s+=b*dv;
          sub[r]=s; } }
    }
    ddf[0]=diag[0];
    for(int i=0;i+1<n;i++){ llf[i]=sub[i]/ddf[i]; ddf[i+1]=diag[i+1]-llf[i]*sub[i]; }
  }
  __syncthreads();
  float sc=sqrtf((float)L/(float)on);
  if(L>on){
    int j=gtid;
    if(j<L){
      float y[96];
      for(int i=0;i<n;i++) y[i]=0.f;
      int i0=i0s[j]; float w=ws[j]; int i1=min(i0+1,on-1);
      if(i1==i0) y[i0]=1.f; else { y[i0]=1.f-w; y[i1]=w; }
      for(int i=1;i<n;i++) y[i]-=llf[i-1]*y[i-1];
      for(int i=0;i<n;i++) y[i]/=ddf[i];
      for(int i=n-2;i>=0;i--) y[i]-=llf[i]*y[i+1];
      for(int i=0;i<n;i++) P[(size_t)i*L+j]=sc*y[i];
    }
  } else {
    int j=gtid;
    if(j<n){
      float y[96], col[96];
      for(int i=0;i<n;i++) y[i]=0.f;
      for(int i=0;i<96;i++) col[i]=0.f;
      y[j]=1.f;
      for(int i=1;i<n;i++) y[i]-=llf[i-1]*y[i-1];
      for(int i=0;i<n;i++) y[i]/=ddf[i];
      for(int i=n-2;i>=0;i--) y[i]-=llf[i]*y[i+1];
      for(int r=0;r<n;r++){ int i0=i0s[r]; float w=ws[r]; int i1=min(i0+1,on-1);
        if(i1==i0) col[i0]+=y[r]; else { col[i0]+=(1.f-w)*y[r]; col[i1]+=w*y[r]; } }
      for(int i=0;i<on;i++) P[(size_t)i*L+j]=sc*col[i];
    }
  }
}

__global__ void k_anchT(const float* a12,const float* a24,const float* a48,const float* a96){
  int a=blockIdx.x;
  const int olds[4]={12,24,48,96};
  const float* A=(a==0)?a12:(a==1)?a24:(a==2)?a48:a96;
  int on=olds[a];
  for(int idx=threadIdx.x;idx<512*on;idx+=blockDim.x){
    int j=idx/on, i=idx-j*on;
    g_anchT[(size_t)a*96*512 + (size_t)i*512 + j]=A[idx];
  }
}

// s=0,1: cv per slot; s=2: cc = fb1 + fw1[:,1024:1536]@sb
__global__ void k_cv(const float* w1,const float* b1,const float* w2,const float* b2,
                     const float* sb,const float* fw1,const float* fb1){
  int s=blockIdx.x, j=threadIdx.x;
  if(s<2){
    const float* W = (s? w2:w1) + (size_t)(1024+j)*512;
    float acc = (s? b2:b1)[1024+j];
    for(int e=0;e<512;e++) acc += W[e]*sb[e];
    g_cvb[s*512+j]=acc;
  } else {
    const float* W = fw1 + (size_t)j*1536 + 1024;
    float acc = fb1[j];
    for(int e=0;e<512;e++) acc += W[e]*sb[e];
    g_cc[j]=acc;
  }
}

// copy fw1[:, :1024] into g_fw1m (ld 1136) and zero pad cols [1120,1136)
__global__ void k_fw1copy(const float* __restrict__ fw1){
  int idx=blockIdx.x*256+threadIdx.x;
  if(idx>=512*1040) return;
  int j=idx/1040, t=idx-j*1040;
  if(t<1024) g_fw1m[(size_t)j*CLD+t]=fw1[(size_t)j*1536+t];
  else g_fw1m[(size_t)j*CLD+1120+(t-1024)]=0.f;
}

template<int EPI>
__device__ __forceinline__ void gemm_body(
    int M,int N,int K,
    const float* __restrict__ A,int lda,
    const float* __restrict__ W,int ldw,
    const float* __restrict__ bias,
    float* __restrict__ C,int ldc,
    int bm,int bn,
    float (*As)[16][132], float (*Ws)[16][68])
{
  int tid=threadIdx.x;
  int tx=tid&15, ty=tid>>4;
  int lm=tid>>2, lk=(tid&3)*4;
  int m0=bm+lm, m1=bm+lm+64, nn=bn+lm;
  float acc[8][4]={};
  float4 pa0,pa1,pw;
  const float4 z4=make_float4(0,0,0,0);
  pa0=(m0<M)?*(const float4*)(A+(size_t)m0*lda+lk):z4;
  pa1=(m1<M)?*(const float4*)(A+(size_t)m1*lda+lk):z4;
  pw =(nn<N)?*(const float4*)(W+(size_t)nn*ldw+lk):z4;
  As[0][lk][lm]=pa0.x; As[0][lk+1][lm]=pa0.y; As[0][lk+2][lm]=pa0.z; As[0][lk+3][lm]=pa0.w;
  As[0][lk][lm+64]=pa1.x; As[0][lk+1][lm+64]=pa1.y; As[0][lk+2][lm+64]=pa1.z; As[0][lk+3][lm+64]=pa1.w;
  Ws[0][lk][lm]=pw.x; Ws[0][lk+1][lm]=pw.y; Ws[0][lk+2][lm]=pw.z; Ws[0][lk+3][lm]=pw.w;
  __syncthreads();
  for(int k0=0;k0<K;k0+=16){
    int buf=(k0>>4)&1;
    bool more=(k0+16<K);
    if(more){
      pa0=(m0<M)?*(const float4*)(A+(size_t)m0*lda+k0+16+lk):z4;
      pa1=(m1<M)?*(const float4*)(A+(size_t)m1*lda+k0+16+lk):z4;
      pw =(nn<N)?*(const float4*)(W+(size_t)nn*ldw+k0+16+lk):z4;
    }
#pragma unroll
    for(int kk=0;kk<16;kk++){
      float4 a0=*(float4*)&As[buf][kk][ty*8];
      float4 a1=*(float4*)&As[buf][kk][ty*8+4];
      float4 wv=*(float4*)&Ws[buf][kk][tx*4];
      float am[8]={a0.x,a0.y,a0.z,a0.w,a1.x,a1.y,a1.z,a1.w};
      float wm4[4]={wv.x,wv.y,wv.z,wv.w};
#pragma unroll
      for(int i=0;i<8;i++)
#pragma unroll
        for(int j=0;j<4;j++) acc[i][j]+=am[i]*wm4[j];
    }
    if(more){
      int nb=buf^1;
      As[nb][lk][lm]=pa0.x; As[nb][lk+1][lm]=pa0.y; As[nb][lk+2][lm]=pa0.z; As[nb][lk+3][lm]=pa0.w;
      As[nb][lk][lm+64]=pa1.x; As[nb][lk+1][lm+64]=pa1.y; As[nb][lk+2][lm+64]=pa1.z; As[nb][lk+3][lm+64]=pa1.w;
      Ws[nb][lk][lm]=pw.x; Ws[nb][lk+1][lm]=pw.y; Ws[nb][lk+2][lm]=pw.z; Ws[nb][lk+3][lm]=pw.w;
      __syncthreads();
    }
  }
#pragma unroll
  for(int i=0;i<8;i++){
    int m=bm+ty*8+i;
    if(m>=M) continue;
#pragma unroll
    for(int j=0;j<4;j++){
      int n2=bn+tx*4+j;
      if(n2<N){
        float v=acc[i][j]+(bias?bias[n2]:0.f);
        if(EPI==1) v=0.5f*v*(1.f+erff(v*0.70710678118654752f));
        C[(size_t)m*ldc+n2]=v;
      }
    }
  }
}

template<int EPI>
__global__ void __launch_bounds__(256) gemm_nt(
    int M,int N,int K,
    const float* __restrict__ A,int lda,
    const float* __restrict__ W,int ldw,
    const float* __restrict__ bias,
    float* __restrict__ C,int ldc)
{
  __shared__ __align__(16) float As[2][16][132];
  __shared__ __align__(16) float Ws[2][16][68];
  gemm_body<EPI>(M,N,K,A,lda,W,ldw,bias,C,ldc,blockIdx.y*128,blockIdx.x*64,As,Ws);
}

// z<16: WkA/WvAT (kv=z&1, a=(z>>1)&3, s=z>>3); z==16: Wc = fw1c@a96 -> g_fw1m[:,1024:1120]
__global__ void __launch_bounds__(256) k_smallgemm(
    const float* __restrict__ inw0, const float* __restrict__ inw1,
    const float* __restrict__ fw1)
{
  __shared__ __align__(16) float As[2][16][132];
  __shared__ __align__(16) float Ws[2][16][68];
  int z=blockIdx.z;
  int M,N,lda; const float *A,*W; float* C; int ldc;
  if(z<16){
    int kv=z&1, a=(z>>1)&3, s=z>>3;
    int on=12<<a;
    const float* inw = s? inw1 : inw0;
    const float* anch = g_anchT + (size_t)a*96*512;
    if(kv==0){
      M=512; N=on; A=inw+512*512; W=anch; C=g_WkA+(size_t)(s*4+a)*512*96; ldc=96;
    } else {
      M=on; N=512; A=anch; W=inw+1024*512; C=g_WvAT+(size_t)(s*4+a)*96*512; ldc=512;
    }
    lda=512;
  } else {
    M=512; N=96; A=fw1+1024; lda=1536; W=g_anchT+(size_t)3*96*512;
    C=g_fw1m+1024; ldc=CLD;
  }
  int bm=blockIdx.y*128, bn=blockIdx.x*64;
  if(bm>=M||bn>=N) return;
  gemm_body<0>(M,N,512,A,lda,W,512,nullptr,C,ldc,bm,bn,As,Ws);
}

__device__ __forceinline__ float4 cvt_tf32_4(const float* p){
  float4 v=*(const float4*)p;
  uint32_t o0,o1,o2,o3;
  asm("cvt.rna.tf32.f32 %0, %1;":"=r"(o0):"f"(v.x));
  asm("cvt.rna.tf32.f32 %0, %1;":"=r"(o1):"f"(v.y));
  asm("cvt.rna.tf32.f32 %0, %1;":"=r"(o2):"f"(v.z));
  asm("cvt.rna.tf32.f32 %0, %1;":"=r"(o3):"f"(v.w));
  float4 r;
  r.x=__uint_as_float(o0); r.y=__uint_as_float(o1);
  r.z=__uint_as_float(o2); r.w=__uint_as_float(o3);
  return r;
}
template<int EPI>
__global__ void __launch_bounds__(256) gemm_tf32_b(
    int M,int N,int K,
    const float* __restrict__ A0,int lda,size_t sA,
    const float* __restrict__ W0,const float* __restrict__ W1,int ldw,
    const float* __restrict__ b0,const float* __restrict__ b1,
    float* __restrict__ C0,int ldc,size_t sC)
{
  __shared__ __align__(16) float As[2][128*20];
  __shared__ __align__(16) float Ws[2][128*20];
  int z=blockIdx.z;
  const float* A=A0+(size_t)z*sA;
  const float* W=z?W1:W0;
  const float* bias=z?b1:b0;
  float* C=C0+(size_t)z*sC;
  int bm=blockIdx.y*128, bn=blockIdx.x*128;
  int tid=threadIdx.x;
  int warp=tid>>5, lane=tid&31;
  int wm=warp>>1, wn=warp&1;
  int g=lane>>2, t4=lane&3;
  int lr=tid>>1, lq=(tid&1)*8;
  float acc[2][8][4];
#pragma unroll
  for(int a=0;a<2;a++)
#pragma unroll
    for(int b=0;b<8;b++)
#pragma unroll
      for(int d=0;d<4;d++) acc[a][b][d]=0.f;
  const float* Arow=A+(size_t)(bm+lr)*lda;
  const float* Wrow=W+(size_t)(bn+lr)*ldw;
  {
    float4 a0=cvt_tf32_4(Arow+lq), a1=cvt_tf32_4(Arow+lq+4);
    float4 w0=cvt_tf32_4(Wrow+lq), w1=cvt_tf32_4(Wrow+lq+4);
    *(float4*)&As[0][lr*20+lq]=a0; *(float4*)&As[0][lr*20+lq+4]=a1;
    *(float4*)&Ws[0][lr*20+lq]=w0; *(float4*)&Ws[0][lr*20+lq+4]=w1;
  }
  __syncthreads();
  for(int k0=0;k0<K;k0+=16){
    int buf=(k0>>4)&1;
    bool more=(k0+16<K);
    float4 pa0,pa1,pw0,pw1;
    if(more){
      pa0=cvt_tf32_4(Arow+k0+16+lq); pa1=cvt_tf32_4(Arow+k0+16+lq+4);
      pw0=cvt_tf32_4(Wrow+k0+16+lq); pw1=cvt_tf32_4(Wrow+k0+16+lq+4);
    }
    const float* as=As[buf];
    const float* ws=Ws[buf];
#pragma unroll
    for(int kk=0;kk<2;kk++){
      int kof=kk*8+t4;
      uint32_t afr[2][4];
#pragma unroll
      for(int mt=0;mt<2;mt++){
        int mb=(wm*32+mt*16+g)*20+kof;
        afr[mt][0]=__float_as_uint(as[mb]);
        afr[mt][1]=__float_as_uint(as[mb+8*20]);
        afr[mt][2]=__float_as_uint(as[mb+4]);
        afr[mt][3]=__float_as_uint(as[mb+8*20+4]);
      }
#pragma unroll
      for(int nt=0;nt<8;nt++){
        int nb=(wn*64+nt*8+g)*20+kof;
        uint32_t bb0=__float_as_uint(ws[nb]);
        uint32_t bb1=__float_as_uint(ws[nb+4]);
#pragma unroll
        for(int mt=0;mt<2;mt++){
          asm("mma.sync.aligned.m16n8k8.row.col.f32.tf32.tf32.f32 "
              "{%0,%1,%2,%3}, {%4,%5,%6,%7}, {%8,%9}, {%0,%1,%2,%3};"
              : "+f"(acc[mt][nt][0]),"+f"(acc[mt][nt][1]),
                "+f"(acc[mt][nt][2]),"+f"(acc[mt][nt][3])
              : "r"(afr[mt][0]),"r"(afr[mt][1]),"r"(afr[mt][2]),"r"(afr[mt][3]),
                "r"(bb0),"r"(bb1));
        }
      }
    }
    if(more){
      int nb2=buf^1;
      *(float4*)&As[nb2][lr*20+lq]=pa0; *(float4*)&As[nb2][lr*20+lq+4]=pa1;
      *(float4*)&Ws[nb2][lr*20+lq]=pw0; *(float4*)&Ws[nb2][lr*20+lq+4]=pw1;
      __syncthreads();
    }
  }
#pragma unroll
  for(int mt=0;mt<2;mt++){
    int mrow=bm+wm*32+mt*16+g;
#pragma unroll
    for(int nt=0;nt<8;nt++){
      int ncol=bn+wn*64+nt*8+t4*2;
      float b0v=bias?bias[ncol]:0.f, b1v=bias?bias[ncol+1]:0.f;
      float v0=acc[mt][nt][0]+b0v, v1=acc[mt][nt][1]+b1v;
      float v2=acc[mt][nt][2]+b0v, v3=acc[mt][nt][3]+b1v;
      if(EPI==1){
        v0=0.5f*v0*(1.f+erff(v0*0.70710678118654752f));
        v1=0.5f*v1*(1.f+erff(v1*0.70710678118654752f));
        v2=0.5f*v2*(1.f+erff(v2*0.70710678118654752f));
        v3=0.5f*v3*(1.f+erff(v3*0.70710678118654752f));
      }
      *(float2*)(C+(size_t)mrow*ldc+ncol)=make_float2(v0,v1);
      *(float2*)(C+(size_t)(mrow+8)*ldc+ncol)=make_float2(v2,v3);
    }
  }
}

__global__ void k_tokenize(const float* __restrict__ sb){
  int r=blockIdx.x, slot=blockIdx.y, c=r&127, tid=threadIdx.x;
  int p=g_periods[c*2+slot], on=near_anchor(p), np=384/p, a=aidx_of(on);
  __shared__ float xs[384];
  __shared__ float zl[96];
  for(int t=tid;t<384;t+=128) xs[t]=g_xinv[(size_t)r*384+t];
  __syncthreads();
  const float* P=g_P+(size_t)(p-4)*PSLOT;
  float* z=g_zbuf+((size_t)r*2+slot)*ZLD;
  int tot=np*on;
  for(int idx=tid;idx<tot;idx+=128){
    int k=idx/on, i=idx-k*on;
    const float* Pr=P+(size_t)i*p;
    const float* xp=xs+k*p;
    float acc=0;
    for(int u=0;u<p;u++) acc+=Pr[u]*xp[u];
    z[idx]=acc;
    if(k==np-1) zl[i]=acc;
  }
  __syncthreads();
  const float* AT=g_anchT+(size_t)a*96*512;
  float* q=g_qb+((size_t)slot*ROWS+r)*512;
  for(int j=tid;j<512;j+=128){
    float acc=sb[j];
    for(int i=0;i<on;i++) acc+=AT[(size_t)i*512+j]*zl[i];
    q[j]=acc;
  }
}

__global__ void __launch_bounds__(256) k_attn(){
  __shared__ float us[6144];
  __shared__ float sc[6144];
  int c=blockIdx.x, slot=blockIdx.y, tid=threadIdx.x;
  int p=g_periods[c*2+slot], on=near_anchor(p), np=384/p, a=aidx_of(on);
  const float* WkA=g_WkA+(size_t)(slot*4+a)*512*96;
  const float* WvAT=g_WvAT+(size_t)(slot*4+a)*96*512;
  const float* Qb=g_Qb+(size_t)slot*ROWS*512;
  for(int hp=0;hp<2;hp++){
    for(int x=tid;x<4096;x+=256){
      int b=x>>8, rme=x&255;
      sc[x]=Qb[(size_t)(b*128+c)*512 + hp*256 + rme];
    }
    __syncthreads();
    for(int x=tid;x<2*on;x+=256){
      int hh=x/on, i=x-hh*on;
      int h=hp*2+hh;
      float acc[16];
#pragma unroll
      for(int b=0;b<16;b++) acc[b]=0;
      for(int e=0;e<128;e++){
        float wv=WkA[(size_t)(h*128+e)*96+i];
#pragma unroll
        for(int b=0;b<16;b++) acc[b]+=wv*sc[b*256+hh*128+e];
      }
#pragma unroll
      for(int b=0;b<16;b++) us[(b*4+h)*96+i]=acc[b];
    }
    __syncthreads();
  }
  const float isq=0.08838834764831845f;
  for(int x=tid;x<16*np;x+=256){
    int b=x/np, k=x-b*np;
    const float* zr=g_zbuf+((size_t)(b*128+c)*2+slot)*ZLD+(size_t)k*on;
    float a0=0,a1=0,a2=0,a3=0;
    for(int i=0;i<on;i++){ float zv=zr[i];
      a0+=us[(b*4)*96+i]*zv; a1+=us[(b*4+1)*96+i]*zv;
      a2+=us[(b*4+2)*96+i]*zv; a3+=us[(b*4+3)*96+i]*zv; }
    sc[(b*4)*96+k]=a0*isq; sc[(b*4+1)*96+k]=a1*isq;
    sc[(b*4+2)*96+k]=a2*isq; sc[(b*4+3)*96+k]=a3*isq;
  }
  __syncthreads();
  if(tid<64){
    float* row=sc+tid*96; float m=-INFINITY;
    for(int k=0;k<np;k++) m=fmaxf(m,row[k]);
    float s=0;
    for(int k=0;k<np;k++){ float e=expf(row[k]-m); row[k]=e; s+=e; }
    float inv=1.f/s;
    for(int k=0;k<np;k++) row[k]*=inv;
  }
  __syncthreads();
  for(int x=tid;x<4*on;x+=256){
    int h=x/on, i=x-h*on;
    for(int b=0;b<16;b++){
      const float* zr=g_zbuf+((size_t)(b*128+c)*2+slot)*ZLD;
      const float* ar=sc+(b*4+h)*96;
      float acc=0;
      for(int k=0;k<np;k++) acc+=ar[k]*zr[(size_t)k*on+i];
      us[(b*4+h)*96+i]=acc;
    }
  }
  __syncthreads();
  for(int j=tid;j<512;j+=256){
    int h=j>>7;
    float wacc[16];
#pragma unroll
    for(int b=0;b<16;b++) wacc[b]=0;
    for(int i=0;i<on;i++){
      float wv=WvAT[(size_t)i*512+j];
#pragma unroll
      for(int b=0;b<16;b++) wacc[b]+=wv*us[(b*4+h)*96+i];
    }
    float cvv=g_cvb[slot*512+j];
#pragma unroll
    for(int b=0;b<16;b++)
      g_ob[(size_t)slot*ROWS*512+(size_t)(b*128+c)*512+j]=wacc[b]+cvv;
  }
}

__global__ void k_ln(const float* __restrict__ g0,const float* __restrict__ b0,
                     const float* __restrict__ g1,const float* __restrict__ b1){
  __shared__ float red[8];
  int r=blockIdx.x, slot=blockIdx.y, tid=threadIdx.x;
  const float* g=slot?g1:g0;
  const float* bt=slot?b1:b0;
  const float* q=g_qb+((size_t)slot*ROWS+r)*512;
  const float* a=g_ab+((size_t)slot*ROWS+r)*512;
  float v0=q[tid]+a[tid], v1=q[tid+256]+a[tid+256];
  float s=v0+v1;
  for(int o=16;o;o>>=1) s+=__shfl_xor_sync(~0u,s,o);
  if((tid&31)==0) red[tid>>5]=s;
  __syncthreads();
  if(tid<8){ s=red[tid]; for(int o=4;o;o>>=1) s+=__shfl_xor_sync(0xff,s,o); red[0]=s; }
  __syncthreads();
  float mu=red[0]/512.f;
  __syncthreads();
  float d0=v0-mu, d1=v1-mu;
  s=d0*d0+d1*d1;
  for(int o=16;o;o>>=1) s+=__shfl_xor_sync(~0u,s,o);
  if((tid&31)==0) red[tid>>5]=s;
  __syncthreads();
  if(tid<8){ s=red[tid]; for(int o=4;o;o>>=1) s+=__shfl_xor_sync(0xff,s,o); red[0]=s; }
  __syncthreads();
  float inv=rsqrtf(red[0]/512.f+1e-5f);
  float* out=g_comb2+(size_t)r*CLD+slot*512;
  out[tid]=d0*inv*g[tid]+bt[tid];
  out[tid+256]=d1*inv*g[tid+256]+bt[tid+256];
  if(slot==0&&tid<16) g_comb2[(size_t)r*CLD+1120+tid]=0.f;
}

extern "C" void kernel_launch(void* const* d_in, const int* in_sizes, int n_in,
                              void* d_out, int out_size){
  const float* x   =(const float*)d_in[0];
  const float* a12 =(const float*)d_in[1];
  const float* a24 =(const float*)d_in[2];
  const float* a48 =(const float*)d_in[3];
  const float* a96 =(const float*)d_in[4];
  const float* sb  =(const float*)d_in[5];
  const float* inw[2]={(const float*)d_in[6],(const float*)d_in[12]};
  const float* inb[2]={(const float*)d_in[7],(const float*)d_in[13]};
  const float* ow[2]={(const float*)d_in[8],(const float*)d_in[14]};
  const float* obi[2]={(const float*)d_in[9],(const float*)d_in[15]};
  const float* lng[2]={(const float*)d_in[10],(const float*)d_in[16]};
  const float* lnb[2]={(const float*)d_in[11],(const float*)d_in[17]};
  const float* fw1=(const float*)d_in[18];
  const float* fb1=(const float*)d_in[19];
  const float* fw2=(const float*)d_in[20];
  const float* fb2=(const float*)d_in[21];
  float* out=(float*)d_out;

  float *xinv,*Ptr,*qb,*Qb,*ob,*ab,*comb2,*hb,*fw1m,*cc;
  cudaGetSymbolAddress((void**)&xinv,g_xinv);
  cudaGetSymbolAddress((void**)&Ptr,g_Ptr);
  cudaGetSymbolAddress((void**)&qb,g_qb);
  cudaGetSymbolAddress((void**)&Qb,g_Qb);
  cudaGetSymbolAddress((void**)&ob,g_ob);
  cudaGetSymbolAddress((void**)&ab,g_ab);
  cudaGetSymbolAddress((void**)&comb2,g_comb2);
  cudaGetSymbolAddress((void**)&hb,g_hb);
  cudaGetSymbolAddress((void**)&fw1m,g_fw1m);
  cudaGetSymbolAddress((void**)&cc,g_cc);

  const size_t SL=(size_t)ROWS*512;

  k_xinv<<<(ROWS*384+255)/256,256>>>(x);
  k_acf<<<128,96>>>(x);
  k_periods<<<1,192>>>();
  k_build_P<<<dim3(190,2),192>>>();
  k_anchT<<<4,256>>>(a12,a24,a48,a96);
  k_cv<<<3,512>>>(inw[0],inb[0],inw[1],inb[1],sb,fw1,fb1);
  k_fw1copy<<<(512*1040+255)/256,256>>>(fw1);

  k_smallgemm<<<dim3(8,4,17),256>>>(inw[0],inw[1],fw1);

  k_tokenize<<<dim3(ROWS,2),128>>>(sb);

  gemm_tf32_b<0><<<dim3(4,16,2),256>>>(ROWS,512,512,
    qb,512,SL, inw[0],inw[1],512, inb[0],inb[1], Qb,512,SL);

  k_attn<<<dim3(128,2),256>>>();

  gemm_tf32_b<0><<<dim3(4,16,2),256>>>(ROWS,512,512,
    ob,512,SL, ow[0],ow[1],512, obi[0],obi[1], ab,512,SL);

  k_ln<<<dim3(ROWS,2),256>>>(lng[0],lnb[0],lng[1],lnb[1]);

  gemm_nt<0><<<dim3(2,16),256>>>(ROWS,96,384, xinv,384, Ptr,384, nullptr, comb2+1024,CLD);

  gemm_tf32_b<1><<<dim3(4,16,1),256>>>(ROWS,512,CLD,
    comb2,CLD,0, fw1m,fw1m,CLD, cc,cc, hb,512,0);
  gemm_tf32_b<0><<<dim3(4,16,1),256>>>(ROWS,512,512,
    hb,512,0, fw2,fw2,512, fb2,fb2, out,512,0);
}

// round 15
// speedup vs baseline: 3.1445x; 1.0685x over previous
#include <cuda_runtime.h>
#include <math.h>
#include <stdint.h>

#define ROWS 2048
#define ZLD  1152
#define PSLOT 18432
#define CLD  1136

__device__ float g_xinv[ROWS*384];
__device__ float g_acfA[384*128];
__device__ int   g_periods[256];
__device__ int   g_needed[193];
__device__ float g_P[189*PSLOT];
__device__ float g_Ptr[96*384];
__device__ float g_anchT[4*96*512];
__device__ float g_WkA[8*512*96];
__device__ float g_WvAT[8*96*512];
__device__ float g_cvb[2*512];
__device__ float g_cc[512];
__device__ float g_fw1m[512*CLD];
__device__ float g_zbuf[(size_t)ROWS*2*ZLD];
__device__ float g_qb[2*ROWS*512];
__device__ float g_Qb[2*ROWS*512];
__device__ float g_ob[2*ROWS*512];
__device__ float g_ab[2*ROWS*512];
__device__ float g_comb2[(size_t)ROWS*CLD];
__device__ float g_hb[ROWS*512];

__device__ __host__ __forceinline__ int near_anchor(int L){
  return (L<=18)?12:(L<=36)?24:(L<=72)?48:96;
}
__device__ __forceinline__ int aidx_of(int o){ return (o==12)?0:(o==24)?1:(o==48)?2:3; }

__global__ void k_xinv(const float* __restrict__ x){
  int idx = blockIdx.x*256+threadIdx.x;
  if(idx>=ROWS*384) return;
  int t=idx%384, r=idx/384, b=r>>7, c=r&127;
  g_xinv[idx] = x[((size_t)b*384+t)*128+c];
}

__global__ void __launch_bounds__(96) k_acf(const float* __restrict__ x){
  __shared__ float xs[16][388];
  __shared__ float bm[16];
  int c=blockIdx.x, tid=threadIdx.x;
  for(int i=tid;i<16*384;i+=96){
    int b=i/384,t=i-b*384;
    xs[b][t]=x[((size_t)b*384+t)*128+c];
  }
  if(tid<64) xs[tid>>2][384+(tid&3)]=0.f;
  __syncthreads();
  if(tid<16){ float s0=0,s1=0;
    for(int t=0;t<384;t+=2){ s0+=xs[tid][t]; s1+=xs[tid][t+1]; }
    bm[tid]=(s0+s1)/384.f; }
  __syncthreads();
  for(int i=tid;i<16*384;i+=96){ int b=i/384; xs[b][i-b*384]-=bm[b]; }
  __syncthreads();
  int l=tid*4;
  float a0=0,a1=0,a2=0,a3=0;
  int n=384-l;
  for(int b=0;b<16;b++){
    const float* r=xs[b];
    float w0=r[l],w1=r[l+1],w2=r[l+2],w3=r[l+3];
    for(int t=0;t<n;t++){
      float rv=r[t];
      a0=fmaf(rv,w0,a0); a1=fmaf(rv,w1,a1);
      a2=fmaf(rv,w2,a2); a3=fmaf(rv,w3,a3);
      w0=w1; w1=w2; w2=w3; w3=r[t+l+4];
    }
  }
  g_acfA[l*128+c]=a0*0.0625f;
  g_acfA[(l+1)*128+c]=a1*0.0625f;
  g_acfA[(l+2)*128+c]=a2*0.0625f;
  g_acfA[(l+3)*128+c]=a3*0.0625f;
}

__global__ void k_periods(){
  int tid=threadIdx.x;
  for(int i=tid;i<193;i+=blockDim.x) g_needed[i]=0;
  __syncthreads();
  if(tid<128){
    int c=tid; float v1=-INFINITY,v2=-INFINITY; int i1=0,i2=1;
    float pv=-INFINITY;
    float v=g_acfA[4*128+c];
    for(int lag=4;lag<384;lag++){
      float nv=(lag==383)?-INFINITY:g_acfA[(lag+1)*128+c];
      if(v>pv&&v>nv&&v>0.f){
        if(v>v1){v2=v1;i2=i1;v1=v;i1=lag;}
        else if(v>v2){v2=v;i2=lag;}
      }
      pv=v; v=nv;
    }
    int p1=min(max(i1,4),192), p2=min(max(i2,4),192);
    g_periods[c*2]=p1; g_periods[c*2+1]=p2;
    g_needed[p1]=1; g_needed[p2]=1;
  }
}

template<int N> __device__ __forceinline__ void solve_unit(
    int m,const float* __restrict__ llf,const float* __restrict__ dinv,
    float* __restrict__ out){
  float w[N];
#pragma unroll
  for(int i=0;i<N;i++) w[i]=(i==m)?1.f:0.f;
#pragma unroll
  for(int i=1;i<N;i++) w[i]-=llf[i-1]*w[i-1];
#pragma unroll
  for(int i=0;i<N;i++) w[i]*=dinv[i];
#pragma unroll
  for(int i=N-2;i>=0;i--) w[i]-=llf[i]*w[i+1];
#pragma unroll
  for(int i=0;i<N;i++) out[i]=w[i];
}

__global__ void __launch_bounds__(384) k_build_P(){
  int bid=blockIdx.x; bool tr=(bid==189);
  int L=tr?384:bid+4;
  if(!tr && !g_needed[L]) return;
  int on=near_anchor(L);
  float* P = tr? g_Ptr : g_P + (size_t)bid*PSLOT;
  int tid=threadIdx.x;
  if(L==on){ for(int v=tid;v<on*L;v+=384) P[v]=(v/L==v%L)?1.f:0.f; return; }
  __shared__ int i0s[384]; __shared__ float ws[384];
  __shared__ float ddf[96], llf[96], dinv[96];
  __shared__ float wm[96][97];
  for(int j=tid;j<L;j+=384){
    float src=((float)j+0.5f)*(float)on/(float)L-0.5f;
    src=fminf(fmaxf(src,0.f),(float)(on-1));
    int i0=(int)src; i0s[j]=i0; ws[j]=src-(float)i0;
  }
  __syncthreads();
  int n=(L>on)?on:L;
  if(tid==0){
    float diag[96], sub[96];
    for(int i=0;i<96;i++){diag[i]=0;sub[i]=0;}
    if(L>on){
      for(int r=0;r<L;r++){ int i0=i0s[r]; float w=ws[r]; int i1=min(i0+1,on-1);
        float a,b; if(i1==i0){a=1;b=0;}else{a=1-w;b=w;}
        diag[i0]+=a*a; if(i1!=i0){diag[i1]+=b*b; sub[i0]+=a*b;} }
    } else {
      for(int r=0;r<L;r++){ int i0=i0s[r]; float w=ws[r]; int i1=min(i0+1,on-1);
        float a,b; if(i1==i0){a=1;b=0;}else{a=1-w;b=w;}
        diag[r]=a*a+b*b;
        if(r+1<L){ int j0=i0s[r+1]; float w2=ws[r+1]; int j1=min(j0+1,on-1);
          float cc,dv; if(j1==j0){cc=1;dv=0;}else{cc=1-w2;dv=w2;}
          float s=0;
          if(i0==j0)s+=a*cc; if(i0==j1&&j1!=j0)s+=a*dv;
          if(i1==j0&&i1!=i0)s+=b*cc; if(i1==j1&&i1!=i0&&j1!=j0)s+=b*dv;
          sub[r]=s; } }
    }
    ddf[0]=diag[0];
    for(int i=0;i+1<n;i++){ llf[i]=sub[i]/ddf[i]; ddf[i+1]=diag[i+1]-llf[i]*sub[i]; }
  }
  __syncthreads();
  for(int i=tid;i<n;i+=384) dinv[i]=1.f/ddf[i];
  __syncthreads();
  float sc=sqrtf((float)L/(float)on);
  if(L>on){
    if(tid<on){
      switch(on){
        case 12: solve_unit<12>(tid,llf,dinv,&wm[tid][0]); break;
        case 24: solve_unit<24>(tid,llf,dinv,&wm[tid][0]); break;
        case 48: solve_unit<48>(tid,llf,dinv,&wm[tid][0]); break;
        default: solve_unit<96>(tid,llf,dinv,&wm[tid][0]); break;
      }
    }
    __syncthreads();
    for(int j=tid;j<L;j+=384){
      int i0=i0s[j]; float w=ws[j]; int i1=min(i0+1,on-1);
      float a,b; if(i1==i0){a=1.f;b=0.f;}else{a=1.f-w;b=w;}
      const float* w0=&wm[i0][0];
      const float* w1=&wm[i1][0];
      for(int i=0;i<on;i++)
        P[(size_t)i*L+j]=sc*(a*w0[i]+b*w1[i]);
    }
  } else {
    int j=tid;
    if(j<n){
      float y[96], col[96];
      for(int i=0;i<n;i++) y[i]=0.f;
      for(int i=0;i<96;i++) col[i]=0.f;
      y[j]=1.f;
      for(int i=1;i<n;i++) y[i]-=llf[i-1]*y[i-1];
      for(int i=0;i<n;i++) y[i]*=dinv[i];
      for(int i=n-2;i>=0;i--) y[i]-=llf[i]*y[i+1];
      for(int r=0;r<n;r++){ int i0=i0s[r]; float w=ws[r]; int i1=min(i0+1,on-1);
        if(i1==i0) col[i0]+=y[r]; else { col[i0]+=(1.f-w)*y[r]; col[i1]+=w*y[r]; } }
      for(int i=0;i<on;i++) P[(size_t)i*L+j]=sc*col[i];
    }
  }
}

__global__ void k_anchT(const float* a12,const float* a24,const float* a48,const float* a96){
  int a=blockIdx.x;
  const int olds[4]={12,24,48,96};
  const float* A=(a==0)?a12:(a==1)?a24:(a==2)?a48:a96;
  int on=olds[a];
  for(int idx=threadIdx.x;idx<512*on;idx+=blockDim.x){
    int j=idx/on, i=idx-j*on;
    g_anchT[(size_t)a*96*512 + (size_t)i*512 + j]=A[idx];
  }
}

__global__ void k_cv(const float* w1,const float* b1,const float* w2,const float* b2,
                     const float* sb,const float* fw1,const float* fb1){
  int s=blockIdx.x, j=threadIdx.x;
  if(s<2){
    const float* W = (s? w2:w1) + (size_t)(1024+j)*512;
    float acc = (s? b2:b1)[1024+j];
    for(int e=0;e<512;e++) acc += W[e]*sb[e];
    g_cvb[s*512+j]=acc;
  } else {
    const float* W = fw1 + (size_t)j*1536 + 1024;
    float acc = fb1[j];
    for(int e=0;e<512;e++) acc += W[e]*sb[e];
    g_cc[j]=acc;
  }
}

__global__ void k_fw1copy(const float* __restrict__ fw1){
  int idx=blockIdx.x*256+threadIdx.x;
  if(idx>=512*1040) return;
  int j=idx/1040, t=idx-j*1040;
  if(t<1024) g_fw1m[(size_t)j*CLD+t]=fw1[(size_t)j*1536+t];
  else g_fw1m[(size_t)j*CLD+1120+(t-1024)]=0.f;
}

template<int EPI>
__device__ __forceinline__ void gemm_body(
    int M,int N,int K,
    const float* __restrict__ A,int lda,
    const float* __restrict__ W,int ldw,
    const float* __restrict__ bias,
    float* __restrict__ C,int ldc,
    int bm,int bn,
    float (*As)[16][132], float (*Ws)[16][68])
{
  int tid=threadIdx.x;
  int tx=tid&15, ty=tid>>4;
  int lm=tid>>2, lk=(tid&3)*4;
  int m0=bm+lm, m1=bm+lm+64, nn=bn+lm;
  float acc[8][4]={};
  float4 pa0,pa1,pw;
  const float4 z4=make_float4(0,0,0,0);
  pa0=(m0<M)?*(const float4*)(A+(size_t)m0*lda+lk):z4;
  pa1=(m1<M)?*(const float4*)(A+(size_t)m1*lda+lk):z4;
  pw =(nn<N)?*(const float4*)(W+(size_t)nn*ldw+lk):z4;
  As[0][lk][lm]=pa0.x; As[0][lk+1][lm]=pa0.y; As[0][lk+2][lm]=pa0.z; As[0][lk+3][lm]=pa0.w;
  As[0][lk][lm+64]=pa1.x; As[0][lk+1][lm+64]=pa1.y; As[0][lk+2][lm+64]=pa1.z; As[0][lk+3][lm+64]=pa1.w;
  Ws[0][lk][lm]=pw.x; Ws[0][lk+1][lm]=pw.y; Ws[0][lk+2][lm]=pw.z; Ws[0][lk+3][lm]=pw.w;
  __syncthreads();
  for(int k0=0;k0<K;k0+=16){
    int buf=(k0>>4)&1;
    bool more=(k0+16<K);
    if(more){
      pa0=(m0<M)?*(const float4*)(A+(size_t)m0*lda+k0+16+lk):z4;
      pa1=(m1<M)?*(const float4*)(A+(size_t)m1*lda+k0+16+lk):z4;
      pw =(nn<N)?*(const float4*)(W+(size_t)nn*ldw+k0+16+lk):z4;
    }
#pragma unroll
    for(int kk=0;kk<16;kk++){
      float4 a0=*(float4*)&As[buf][kk][ty*8];
      float4 a1=*(float4*)&As[buf][kk][ty*8+4];
      float4 wv=*(float4*)&Ws[buf][kk][tx*4];
      float am[8]={a0.x,a0.y,a0.z,a0.w,a1.x,a1.y,a1.z,a1.w};
      float wm4[4]={wv.x,wv.y,wv.z,wv.w};
#pragma unroll
      for(int i=0;i<8;i++)
#pragma unroll
        for(int j=0;j<4;j++) acc[i][j]+=am[i]*wm4[j];
    }
    if(more){
      int nb=buf^1;
      As[nb][lk][lm]=pa0.x; As[nb][lk+1][lm]=pa0.y; As[nb][lk+2][lm]=pa0.z; As[nb][lk+3][lm]=pa0.w;
      As[nb][lk][lm+64]=pa1.x; As[nb][lk+1][lm+64]=pa1.y; As[nb][lk+2][lm+64]=pa1.z; As[nb][lk+3][lm+64]=pa1.w;
      Ws[nb][lk][lm]=pw.x; Ws[nb][lk+1][lm]=pw.y; Ws[nb][lk+2][lm]=pw.z; Ws[nb][lk+3][lm]=pw.w;
      __syncthreads();
    }
  }
#pragma unroll
  for(int i=0;i<8;i++){
    int m=bm+ty*8+i;
    if(m>=M) continue;
#pragma unroll
    for(int j=0;j<4;j++){
      int n2=bn+tx*4+j;
      if(n2<N){
        float v=acc[i][j]+(bias?bias[n2]:0.f);
        if(EPI==1) v=0.5f*v*(1.f+erff(v*0.70710678118654752f));
        C[(size_t)m*ldc+n2]=v;
      }
    }
  }
}

template<int EPI>
__global__ void __launch_bounds__(256) gemm_nt(
    int M,int N,int K,
    const float* __restrict__ A,int lda,
    const float* __restrict__ W,int ldw,
    const float* __restrict__ bias,
    float* __restrict__ C,int ldc)
{
  __shared__ __align__(16) float As[2][16][132];
  __shared__ __align__(16) float Ws[2][16][68];
  gemm_body<EPI>(M,N,K,A,lda,W,ldw,bias,C,ldc,blockIdx.y*128,blockIdx.x*64,As,Ws);
}

__device__ __forceinline__ float4 cvt_tf32_4(const float* p){
  float4 v=*(const float4*)p;
  uint32_t o0,o1,o2,o3;
  asm("cvt.rna.tf32.f32 %0, %1;":"=r"(o0):"f"(v.x));
  asm("cvt.rna.tf32.f32 %0, %1;":"=r"(o1):"f"(v.y));
  asm("cvt.rna.tf32.f32 %0, %1;":"=r"(o2):"f"(v.z));
  asm("cvt.rna.tf32.f32 %0, %1;":"=r"(o3):"f"(v.w));
  float4 r;
  r.x=__uint_as_float(o0); r.y=__uint_as_float(o1);
  r.z=__uint_as_float(o2); r.w=__uint_as_float(o3);
  return r;
}

// 17 small GEMMs on tensor cores: M=512,K=512,N=on<=96 (padded to 128).
// z<16: kv=z&1,a=(z>>1)&3,s=z>>3.  kv0: WkA=Wk@anch (512xon). kv1: WvA=Wv@anch, stored transposed.
// z==16: fw1c@a96 -> g_fw1m[:,1024:1120].
__global__ void __launch_bounds__(256) k_sg_tf32(
    const float* __restrict__ inw0,const float* __restrict__ inw1,
    const float* __restrict__ fw1)
{
  __shared__ __align__(16) float As[2][128*20];
  __shared__ __align__(16) float Ws[2][128*20];
  int z=blockIdx.z;
  const float *A,*W; float* C; int lda,ldc,N; int transC;
  if(z<16){
    int kv=z&1,a=(z>>1)&3,s=z>>3;
    N=12<<a;
    const float* inw=s?inw1:inw0;
    W=g_anchT+(size_t)a*96*512;
    if(kv==0){ A=inw+512*512; C=g_WkA+(size_t)(s*4+a)*512*96; ldc=96; transC=0; }
    else     { A=inw+1024*512; C=g_WvAT+(size_t)(s*4+a)*96*512; ldc=512; transC=1; }
    lda=512;
  } else {
    A=fw1+1024; lda=1536; W=g_anchT+(size_t)3*96*512; N=96;
    C=g_fw1m+1024; ldc=CLD; transC=0;
  }
  const int K=512;
  int bm=blockIdx.y*128;
  int tid=threadIdx.x;
  int warp=tid>>5, lane=tid&31;
  int wmw=warp>>1, wn=warp&1;
  int g=lane>>2, t4=lane&3;
  int lr=tid>>1, lq=(tid&1)*8;
  float acc[2][8][4];
#pragma unroll
  for(int a2=0;a2<2;a2++)
#pragma unroll
    for(int b2=0;b2<8;b2++)
#pragma unroll
      for(int d=0;d<4;d++) acc[a2][b2][d]=0.f;
  const float* Arow=A+(size_t)(bm+lr)*lda;
  const float* Wrow=W+(size_t)min(lr,N-1)*512;
  {
    float4 a0=cvt_tf32_4(Arow+lq), a1=cvt_tf32_4(Arow+lq+4);
    float4 w0=cvt_tf32_4(Wrow+lq), w1=cvt_tf32_4(Wrow+lq+4);
    *(float4*)&As[0][lr*20+lq]=a0; *(float4*)&As[0][lr*20+lq+4]=a1;
    *(float4*)&Ws[0][lr*20+lq]=w0; *(float4*)&Ws[0][lr*20+lq+4]=w1;
  }
  __syncthreads();
  for(int k0=0;k0<K;k0+=16){
    int buf=(k0>>4)&1;
    bool more=(k0+16<K);
    float4 pa0,pa1,pw0,pw1;
    if(more){
      pa0=cvt_tf32_4(Arow+k0+16+lq); pa1=cvt_tf32_4(Arow+k0+16+lq+4);
      pw0=cvt_tf32_4(Wrow+k0+16+lq); pw1=cvt_tf32_4(Wrow+k0+16+lq+4);
    }
    const float* as=As[buf];
    const float* ws=Ws[buf];
#pragma unroll
    for(int kk=0;kk<2;kk++){
      int kof=kk*8+t4;
      uint32_t afr[2][4];
#pragma unroll
      for(int mt=0;mt<2;mt++){
        int mb=(wmw*32+mt*16+g)*20+kof;
        afr[mt][0]=__float_as_uint(as[mb]);
        afr[mt][1]=__float_as_uint(as[mb+8*20]);
        afr[mt][2]=__float_as_uint(as[mb+4]);
        afr[mt][3]=__float_as_uint(as[mb+8*20+4]);
      }
#pragma unroll
      for(int nt=0;nt<8;nt++){
        int nb=(wn*64+nt*8+g)*20+kof;
        uint32_t bb0=__float_as_uint(ws[nb]);
        uint32_t bb1=__float_as_uint(ws[nb+4]);
#pragma unroll
        for(int mt=0;mt<2;mt++){
          asm("mma.sync.aligned.m16n8k8.row.col.f32.tf32.tf32.f32 "
              "{%0,%1,%2,%3}, {%4,%5,%6,%7}, {%8,%9}, {%0,%1,%2,%3};"
              : "+f"(acc[mt][nt][0]),"+f"(acc[mt][nt][1]),
                "+f"(acc[mt][nt][2]),"+f"(acc[mt][nt][3])
              : "r"(afr[mt][0]),"r"(afr[mt][1]),"r"(afr[mt][2]),"r"(afr[mt][3]),
                "r"(bb0),"r"(bb1));
        }
      }
    }
    if(more){
      int nb2=buf^1;
      *(float4*)&As[nb2][lr*20+lq]=pa0; *(float4*)&As[nb2][lr*20+lq+4]=pa1;
      *(float4*)&Ws[nb2][lr*20+lq]=pw0; *(float4*)&Ws[nb2][lr*20+lq+4]=pw1;
      __syncthreads();
    }
  }
#pragma unroll
  for(int mt=0;mt<2;mt++){
    int mrow=bm+wmw*32+mt*16+g;
#pragma unroll
    for(int nt=0;nt<8;nt++){
      int nc0=wn*64+nt*8+t4*2;
#pragma unroll
      for(int dc=0;dc<2;dc++){
        int ncol=nc0+dc;
        if(ncol>=N) continue;
        float v0=acc[mt][nt][dc], v1=acc[mt][nt][2+dc];
        if(transC){
          C[(size_t)ncol*ldc+mrow]=v0;
          C[(size_t)ncol*ldc+mrow+8]=v1;
        } else {
          C[(size_t)mrow*ldc+ncol]=v0;
          C[(size_t)(mrow+8)*ldc+ncol]=v1;
        }
      }
    }
  }
}

template<int EPI>
__global__ void __launch_bounds__(256) gemm_tf32_b(
    int M,int N,int K,
    const float* __restrict__ A0,int lda,size_t sA,
    const float* __restrict__ W0,const float* __restrict__ W1,int ldw,
    const float* __restrict__ b0,const float* __restrict__ b1,
    float* __restrict__ C0,int ldc,size_t sC)
{
  __shared__ __align__(16) float As[2][128*20];
  __shared__ __align__(16) float Ws[2][128*20];
  int z=blockIdx.z;
  const float* A=A0+(size_t)z*sA;
  const float* W=z?W1:W0;
  const float* bias=z?b1:b0;
  float* C=C0+(size_t)z*sC;
  int bm=blockIdx.y*128, bn=blockIdx.x*128;
  int tid=threadIdx.x;
  int warp=tid>>5, lane=tid&31;
  int wm=warp>>1, wn=warp&1;
  int g=lane>>2, t4=lane&3;
  int lr=tid>>1, lq=(tid&1)*8;
  float acc[2][8][4];
#pragma unroll
  for(int a=0;a<2;a++)
#pragma unroll
    for(int b=0;b<8;b++)
#pragma unroll
      for(int d=0;d<4;d++) acc[a][b][d]=0.f;
  const float* Arow=A+(size_t)(bm+lr)*lda;
  const float* Wrow=W+(size_t)(bn+lr)*ldw;
  {
    float4 a0=cvt_tf32_4(Arow+lq), a1=cvt_tf32_4(Arow+lq+4);
    float4 w0=cvt_tf32_4(Wrow+lq), w1=cvt_tf32_4(Wrow+lq+4);
    *(float4*)&As[0][lr*20+lq]=a0; *(float4*)&As[0][lr*20+lq+4]=a1;
    *(float4*)&Ws[0][lr*20+lq]=w0; *(float4*)&Ws[0][lr*20+lq+4]=w1;
  }
  __syncthreads();
  for(int k0=0;k0<K;k0+=16){
    int buf=(k0>>4)&1;
    bool more=(k0+16<K);
    float4 pa0,pa1,pw0,pw1;
    if(more){
      pa0=cvt_tf32_4(Arow+k0+16+lq); pa1=cvt_tf32_4(Arow+k0+16+lq+4);
      pw0=cvt_tf32_4(Wrow+k0+16+lq); pw1=cvt_tf32_4(Wrow+k0+16+lq+4);
    }
    const float* as=As[buf];
    const float* ws=Ws[buf];
#pragma unroll
    for(int kk=0;kk<2;kk++){
      int kof=kk*8+t4;
      uint32_t afr[2][4];
#pragma unroll
      for(int mt=0;mt<2;mt++){
        int mb=(wm*32+mt*16+g)*20+kof;
        afr[mt][0]=__float_as_uint(as[mb]);
        afr[mt][1]=__float_as_uint(as[mb+8*20]);
        afr[mt][2]=__float_as_uint(as[mb+4]);
        afr[mt][3]=__float_as_uint(as[mb+8*20+4]);
      }
#pragma unroll
      for(int nt=0;nt<8;nt++){
        int nb=(wn*64+nt*8+g)*20+kof;
        uint32_t bb0=__float_as_uint(ws[nb]);
        uint32_t bb1=__float_as_uint(ws[nb+4]);
#pragma unroll
        for(int mt=0;mt<2;mt++){
          asm("mma.sync.aligned.m16n8k8.row.col.f32.tf32.tf32.f32 "
              "{%0,%1,%2,%3}, {%4,%5,%6,%7}, {%8,%9}, {%0,%1,%2,%3};"
              : "+f"(acc[mt][nt][0]),"+f"(acc[mt][nt][1]),
                "+f"(acc[mt][nt][2]),"+f"(acc[mt][nt][3])
              : "r"(afr[mt][0]),"r"(afr[mt][1]),"r"(afr[mt][2]),"r"(afr[mt][3]),
                "r"(bb0),"r"(bb1));
        }
      }
    }
    if(more){
      int nb2=buf^1;
      *(float4*)&As[nb2][lr*20+lq]=pa0; *(float4*)&As[nb2][lr*20+lq+4]=pa1;
      *(float4*)&Ws[nb2][lr*20+lq]=pw0; *(float4*)&Ws[nb2][lr*20+lq+4]=pw1;
      __syncthreads();
    }
  }
#pragma unroll
  for(int mt=0;mt<2;mt++){
    int mrow=bm+wm*32+mt*16+g;
#pragma unroll
    for(int nt=0;nt<8;nt++){
      int ncol=bn+wn*64+nt*8+t4*2;
      float b0v=bias?bias[ncol]:0.f, b1v=bias?bias[ncol+1]:0.f;
      float v0=acc[mt][nt][0]+b0v, v1=acc[mt][nt][1]+b1v;
      float v2=acc[mt][nt][2]+b0v, v3=acc[mt][nt][3]+b1v;
      if(EPI==1){
        v0=0.5f*v0*(1.f+erff(v0*0.70710678118654752f));
        v1=0.5f*v1*(1.f+erff(v1*0.70710678118654752f));
        v2=0.5f*v2*(1.f+erff(v2*0.70710678118654752f));
        v3=0.5f*v3*(1.f+erff(v3*0.70710678118654752f));
      }
      *(float2*)(C+(size_t)mrow*ldc+ncol)=make_float2(v0,v1);
      *(float2*)(C+(size_t)(mrow+8)*ldc+ncol)=make_float2(v2,v3);
    }
  }
}

__global__ void k_tokenize(const float* __restrict__ sb){
  int r=blockIdx.x, slot=blockIdx.y, c=r&127, tid=threadIdx.x;
  int p=g_periods[c*2+slot], on=near_anchor(p), np=384/p, a=aidx_of(on);
  __shared__ float xs[384];
  __shared__ float zl[96];
  for(int t=tid;t<384;t+=128) xs[t]=g_xinv[(size_t)r*384+t];
  __syncthreads();
  const float* P=g_P+(size_t)(p-4)*PSLOT;
  float* z=g_zbuf+((size_t)r*2+slot)*ZLD;
  int tot=np*on;
  for(int idx=tid;idx<tot;idx+=128){
    int k=idx/on, i=idx-k*on;
    const float* Pr=P+(size_t)i*p;
    const float* xp=xs+k*p;
    float acc=0;
    for(int u=0;u<p;u++) acc+=Pr[u]*xp[u];
    z[idx]=acc;
    if(k==np-1) zl[i]=acc;
  }
  __syncthreads();
  const float* AT=g_anchT+(size_t)a*96*512;
  float* q=g_qb+((size_t)slot*ROWS+r)*512;
  for(int j=tid;j<512;j+=128){
    float acc=sb[j];
    for(int i=0;i<on;i++) acc+=AT[(size_t)i*512+j]*zl[i];
    q[j]=acc;
  }
}

__global__ void __launch_bounds__(256) k_attn(){
  __shared__ float us[6144];
  __shared__ float sc[6144];
  int c=blockIdx.x, slot=blockIdx.y, tid=threadIdx.x;
  int p=g_periods[c*2+slot], on=near_anchor(p), np=384/p, a=aidx_of(on);
  const float* WkA=g_WkA+(size_t)(slot*4+a)*512*96;
  const float* WvAT=g_WvAT+(size_t)(slot*4+a)*96*512;
  const float* Qb=g_Qb+(size_t)slot*ROWS*512;
  for(int hp=0;hp<2;hp++){
    for(int x=tid;x<4096;x+=256){
      int b=x>>8, rme=x&255;
      sc[x]=Qb[(size_t)(b*128+c)*512 + hp*256 + rme];
    }
    __syncthreads();
    for(int x=tid;x<2*on;x+=256){
      int hh=x/on, i=x-hh*on;
      int h=hp*2+hh;
      float acc[16];
#pragma unroll
      for(int b=0;b<16;b++) acc[b]=0;
      for(int e=0;e<128;e++){
        float wv=WkA[(size_t)(h*128+e)*96+i];
#pragma unroll
        for(int b=0;b<16;b++) acc[b]+=wv*sc[b*256+hh*128+e];
      }
#pragma unroll
      for(int b=0;b<16;b++) us[(b*4+h)*96+i]=acc[b];
    }
    __syncthreads();
  }
  const float isq=0.08838834764831845f;
  for(int x=tid;x<16*np;x+=256){
    int b=x/np, k=x-b*np;
    const float* zr=g_zbuf+((size_t)(b*128+c)*2+slot)*ZLD+(size_t)k*on;
    float a0=0,a1=0,a2=0,a3=0;
    for(int i=0;i<on;i++){ float zv=zr[i];
      a0+=us[(b*4)*96+i]*zv; a1+=us[(b*4+1)*96+i]*zv;
      a2+=us[(b*4+2)*96+i]*zv; a3+=us[(b*4+3)*96+i]*zv; }
    sc[(b*4)*96+k]=a0*isq; sc[(b*4+1)*96+k]=a1*isq;
    sc[(b*4+2)*96+k]=a2*isq; sc[(b*4+3)*96+k]=a3*isq;
  }
  __syncthreads();
  if(tid<64){
    float* row=sc+tid*96; float m=-INFINITY;
    for(int k=0;k<np;k++) m=fmaxf(m,row[k]);
    float s=0;
    for(int k=0;k<np;k++){ float e=expf(row[k]-m); row[k]=e; s+=e; }
    float inv=1.f/s;
    for(int k=0;k<np;k++) row[k]*=inv;
  }
  __syncthreads();
  for(int x=tid;x<4*on;x+=256){
    int h=x/on, i=x-h*on;
    for(int b=0;b<16;b++){
      const float* zr=g_zbuf+((size_t)(b*128+c)*2+slot)*ZLD;
      const float* ar=sc+(b*4+h)*96;
      float acc=0;
      for(int k=0;k<np;k++) acc+=ar[k]*zr[(size_t)k*on+i];
      us[(b*4+h)*96+i]=acc;
    }
  }
  __syncthreads();
  for(int j=tid;j<512;j+=256){
    int h=j>>7;
    float wacc[16];
#pragma unroll
    for(int b=0;b<16;b++) wacc[b]=0;
    for(int i=0;i<on;i++){
      float wv=WvAT[(size_t)i*512+j];
#pragma unroll
      for(int b=0;b<16;b++) wacc[b]+=wv*us[(b*4+h)*96+i];
    }
    float cvv=g_cvb[slot*512+j];
#pragma unroll
    for(int b=0;b<16;b++)
      g_ob[(size_t)slot*ROWS*512+(size_t)(b*128+c)*512+j]=wacc[b]+cvv;
  }
}

__global__ void k_ln(const float* __restrict__ g0,const float* __restrict__ b0,
                     const float* __restrict__ g1,const float* __restrict__ b1){
  __shared__ float red[8];
  int r=blockIdx.x, slot=blockIdx.y, tid=threadIdx.x;
  const float* g=slot?g1:g0;
  const float* bt=slot?b1:b0;
  const float* q=g_qb+((size_t)slot*ROWS+r)*512;
  const float* a=g_ab+((size_t)slot*ROWS+r)*512;
  float v0=q[tid]+a[tid], v1=q[tid+256]+a[tid+256];
  float s=v0+v1;
  for(int o=16;o;o>>=1) s+=__shfl_xor_sync(~0u,s,o);
  if((tid&31)==0) red[tid>>5]=s;
  __syncthreads();
  if(tid<8){ s=red[tid]; for(int o=4;o;o>>=1) s+=__shfl_xor_sync(0xff,s,o); red[0]=s; }
  __syncthreads();
  float mu=red[0]/512.f;
  __syncthreads();
  float d0=v0-mu, d1=v1-mu;
  s=d0*d0+d1*d1;
  for(int o=16;o;o>>=1) s+=__shfl_xor_sync(~0u,s,o);
  if((tid&31)==0) red[tid>>5]=s;
  __syncthreads();
  if(tid<8){ s=red[tid]; for(int o=4;o;o>>=1) s+=__shfl_xor_sync(0xff,s,o); red[0]=s; }
  __syncthreads();
  float inv=rsqrtf(red[0]/512.f+1e-5f);
  float* out=g_comb2+(size_t)r*CLD+slot*512;
  out[tid]=d0*inv*g[tid]+bt[tid];
  out[tid+256]=d1*inv*g[tid+256]+bt[tid+256];
  if(slot==0&&tid<16) g_comb2[(size_t)r*CLD+1120+tid]=0.f;
}

extern "C" void kernel_launch(void* const* d_in, const int* in_sizes, int n_in,
                              void* d_out, int out_size){
  const float* x   =(const float*)d_in[0];
  const float* a12 =(const float*)d_in[1];
  const float* a24 =(const float*)d_in[2];
  const float* a48 =(const float*)d_in[3];
  const float* a96 =(const float*)d_in[4];
  const float* sb  =(const float*)d_in[5];
  const float* inw[2]={(const float*)d_in[6],(const float*)d_in[12]};
  const float* inb[2]={(const float*)d_in[7],(const float*)d_in[13]};
  const float* ow[2]={(const float*)d_in[8],(const float*)d_in[14]};
  const float* obi[2]={(const float*)d_in[9],(const float*)d_in[15]};
  const float* lng[2]={(const float*)d_in[10],(const float*)d_in[16]};
  const float* lnb[2]={(const float*)d_in[11],(const float*)d_in[17]};
  const float* fw1=(const float*)d_in[18];
  const float* fb1=(const float*)d_in[19];
  const float* fw2=(const float*)d_in[20];
  const float* fb2=(const float*)d_in[21];
  float* out=(float*)d_out;

  float *xinv,*Ptr,*qb,*Qb,*ob,*ab,*comb2,*hb,*fw1m,*cc;
  cudaGetSymbolAddress((void**)&xinv,g_xinv);
  cudaGetSymbolAddress((void**)&Ptr,g_Ptr);
  cudaGetSymbolAddress((void**)&qb,g_qb);
  cudaGetSymbolAddress((void**)&Qb,g_Qb);
  cudaGetSymbolAddress((void**)&ob,g_ob);
  cudaGetSymbolAddress((void**)&ab,g_ab);
  cudaGetSymbolAddress((void**)&comb2,g_comb2);
  cudaGetSymbolAddress((void**)&hb,g_hb);
  cudaGetSymbolAddress((void**)&fw1m,g_fw1m);
  cudaGetSymbolAddress((void**)&cc,g_cc);

  const size_t SL=(size_t)ROWS*512;

  k_xinv<<<(ROWS*384+255)/256,256>>>(x);
  k_acf<<<128,96>>>(x);
  k_periods<<<1,192>>>();
  k_build_P<<<190,384>>>();
  k_anchT<<<4,256>>>(a12,a24,a48,a96);
  k_cv<<<3,512>>>(inw[0],inb[0],inw[1],inb[1],sb,fw1,fb1);
  k_fw1copy<<<(512*1040+255)/256,256>>>(fw1);

  k_sg_tf32<<<dim3(1,4,17),256>>>(inw[0],inw[1],fw1);

  k_tokenize<<<dim3(ROWS,2),128>>>(sb);

  gemm_tf32_b<0><<<dim3(4,16,2),256>>>(ROWS,512,512,
    qb,512,SL, inw[0],inw[1],512, inb[0],inb[1], Qb,512,SL);

  k_attn<<<dim3(128,2),256>>>();

  gemm_tf32_b<0><<<dim3(4,16,2),256>>>(ROWS,512,512,
    ob,512,SL, ow[0],ow[1],512, obi[0],obi[1], ab,512,SL);

  k_ln<<<dim3(ROWS,2),256>>>(lng[0],lnb[0],lng[1],lnb[1]);

  gemm_nt<0><<<dim3(2,16),256>>>(ROWS,96,384, xinv,384, Ptr,384, nullptr, comb2+1024,CLD);

  gemm_tf32_b<1><<<dim3(4,16,1),256>>>(ROWS,512,CLD,
    comb2,CLD,0, fw1m,fw1m,CLD, cc,cc, hb,512,0);
  gemm_tf32_b<0><<<dim3(4,16,1),256>>>(ROWS,512,512,
    hb,512,0, fw2,fw2,512, fb2,fb2, out,512,0);
}

// round 16
// speedup vs baseline: 3.1763x; 1.0101x over previous
#include <cuda_runtime.h>
#include <math.h>
#include <stdint.h>

#define ROWS 2048
#define ZLD  1152
#define PSLOT 18432
#define CLD  1136

__device__ float g_xinv[ROWS*384];
__device__ float g_acfA[384*128];
__device__ int   g_periods[256];
__device__ int   g_needed[193];
__device__ float g_P[189*PSLOT];
__device__ float g_Ptr[96*384];
__device__ float g_anchT[4*96*512];
__device__ float g_WkA[8*512*96];
__device__ float g_WvAT[8*96*512];
__device__ float g_cvb[2*512];
__device__ float g_cc[512];
__device__ float g_fw1m[512*CLD];
__device__ float g_zbuf[(size_t)ROWS*2*ZLD];
__device__ float g_qb[2*ROWS*512];
__device__ float g_Qb[2*ROWS*512];
__device__ float g_ob[2*ROWS*512];
__device__ float g_ab[2*ROWS*512];
__device__ float g_comb2[(size_t)ROWS*CLD];
__device__ float g_hb[ROWS*512];

__device__ __host__ __forceinline__ int near_anchor(int L){
  return (L<=18)?12:(L<=36)?24:(L<=72)?48:96;
}
__device__ __forceinline__ int aidx_of(int o){ return (o==12)?0:(o==24)?1:(o==48)?2:3; }

__global__ void k_xinv(const float* __restrict__ x){
  int idx = blockIdx.x*256+threadIdx.x;
  if(idx>=ROWS*384) return;
  int t=idx%384, r=idx/384, b=r>>7, c=r&127;
  g_xinv[idx] = x[((size_t)b*384+t)*128+c];
}

__global__ void __launch_bounds__(96) k_acf(const float* __restrict__ x){
  __shared__ float xs[16][388];
  __shared__ float bm[16];
  int c=blockIdx.x, tid=threadIdx.x;
  for(int i=tid;i<16*384;i+=96){
    int b=i/384,t=i-b*384;
    xs[b][t]=x[((size_t)b*384+t)*128+c];
  }
  if(tid<64) xs[tid>>2][384+(tid&3)]=0.f;
  __syncthreads();
  if(tid<16){ float s0=0,s1=0;
    for(int t=0;t<384;t+=2){ s0+=xs[tid][t]; s1+=xs[tid][t+1]; }
    bm[tid]=(s0+s1)/384.f; }
  __syncthreads();
  for(int i=tid;i<16*384;i+=96){ int b=i/384; xs[b][i-b*384]-=bm[b]; }
  __syncthreads();
  int l=tid*4;
  float a0=0,a1=0,a2=0,a3=0;
  int n=384-l;
  for(int b=0;b<16;b++){
    const float* r=xs[b];
    float w0=r[l],w1=r[l+1],w2=r[l+2],w3=r[l+3];
    for(int t=0;t<n;t++){
      float rv=r[t];
      a0=fmaf(rv,w0,a0); a1=fmaf(rv,w1,a1);
      a2=fmaf(rv,w2,a2); a3=fmaf(rv,w3,a3);
      w0=w1; w1=w2; w2=w3; w3=r[t+l+4];
    }
  }
  g_acfA[l*128+c]=a0*0.0625f;
  g_acfA[(l+1)*128+c]=a1*0.0625f;
  g_acfA[(l+2)*128+c]=a2*0.0625f;
  g_acfA[(l+3)*128+c]=a3*0.0625f;
}

__global__ void k_periods(){
  int tid=threadIdx.x;
  for(int i=tid;i<193;i+=blockDim.x) g_needed[i]=0;
  __syncthreads();
  if(tid<128){
    int c=tid; float v1=-INFINITY,v2=-INFINITY; int i1=0,i2=1;
    float pv=-INFINITY;
    float v=g_acfA[4*128+c];
    for(int lag=4;lag<384;lag++){
      float nv=(lag==383)?-INFINITY:g_acfA[(lag+1)*128+c];
      if(v>pv&&v>nv&&v>0.f){
        if(v>v1){v2=v1;i2=i1;v1=v;i1=lag;}
        else if(v>v2){v2=v;i2=lag;}
      }
      pv=v; v=nv;
    }
    int p1=min(max(i1,4),192), p2=min(max(i2,4),192);
    g_periods[c*2]=p1; g_periods[c*2+1]=p2;
    g_needed[p1]=1; g_needed[p2]=1;
  }
}

template<int N> __device__ __forceinline__ void solve_unit(
    int m,const float* __restrict__ llf,const float* __restrict__ dinv,
    float* __restrict__ out){
  float w[N];
#pragma unroll
  for(int i=0;i<N;i++) w[i]=(i==m)?1.f:0.f;
#pragma unroll
  for(int i=1;i<N;i++) w[i]-=llf[i-1]*w[i-1];
#pragma unroll
  for(int i=0;i<N;i++) w[i]*=dinv[i];
#pragma unroll
  for(int i=N-2;i>=0;i--) w[i]-=llf[i]*w[i+1];
#pragma unroll
  for(int i=0;i<N;i++) out[i]=w[i];
}

__global__ void __launch_bounds__(384) k_build_P(){
  int bid=blockIdx.x; bool tr=(bid==189);
  int L=tr?384:bid+4;
  if(!tr && !g_needed[L]) return;
  int on=near_anchor(L);
  float* P = tr? g_Ptr : g_P + (size_t)bid*PSLOT;
  int tid=threadIdx.x;
  if(L==on){ for(int v=tid;v<on*L;v+=384) P[v]=(v/L==v%L)?1.f:0.f; return; }
  __shared__ int i0s[384]; __shared__ float ws[384];
  __shared__ float ddf[96], llf[96], dinv[96];
  __shared__ float wm[96][97];
  for(int j=tid;j<L;j+=384){
    float src=((float)j+0.5f)*(float)on/(float)L-0.5f;
    src=fminf(fmaxf(src,0.f),(float)(on-1));
    int i0=(int)src; i0s[j]=i0; ws[j]=src-(float)i0;
  }
  __syncthreads();
  int n=(L>on)?on:L;
  if(tid==0){
    float diag[96], sub[96];
    for(int i=0;i<96;i++){diag[i]=0;sub[i]=0;}
    if(L>on){
      for(int r=0;r<L;r++){ int i0=i0s[r]; float w=ws[r]; int i1=min(i0+1,on-1);
        float a,b; if(i1==i0){a=1;b=0;}else{a=1-w;b=w;}
        diag[i0]+=a*a; if(i1!=i0){diag[i1]+=b*b; sub[i0]+=a*b;} }
    } else {
      for(int r=0;r<L;r++){ int i0=i0s[r]; float w=ws[r]; int i1=min(i0+1,on-1);
        float a,b; if(i1==i0){a=1;b=0;}else{a=1-w;b=w;}
        diag[r]=a*a+b*b;
        if(r+1<L){ int j0=i0s[r+1]; float w2=ws[r+1]; int j1=min(j0+1,on-1);
          float cc,dv; if(j1==j0){cc=1;dv=0;}else{cc=1-w2;dv=w2;}
          float s=0;
          if(i0==j0)s+=a*cc; if(i0==j1&&j1!=j0)s+=a*dv;
          if(i1==j0&&i1!=i0)s+=b*cc; if(i1==j1&&i1!=i0&&j1!=j0)s+=b*dv;
          sub[r]=s; } }
    }
    ddf[0]=diag[0];
    for(int i=0;i+1<n;i++){ llf[i]=sub[i]/ddf[i]; ddf[i+1]=diag[i+1]-llf[i]*sub[i]; }
  }
  __syncthreads();
  for(int i=tid;i<n;i+=384) dinv[i]=1.f/ddf[i];
  __syncthreads();
  float sc=sqrtf((float)L/(float)on);
  if(L>on){
    if(tid<on){
      switch(on){
        case 12: solve_unit<12>(tid,llf,dinv,&wm[tid][0]); break;
        case 24: solve_unit<24>(tid,llf,dinv,&wm[tid][0]); break;
        case 48: solve_unit<48>(tid,llf,dinv,&wm[tid][0]); break;
        default: solve_unit<96>(tid,llf,dinv,&wm[tid][0]); break;
      }
    }
    __syncthreads();
    for(int j=tid;j<L;j+=384){
      int i0=i0s[j]; float w=ws[j]; int i1=min(i0+1,on-1);
      float a,b; if(i1==i0){a=1.f;b=0.f;}else{a=1.f-w;b=w;}
      const float* w0=&wm[i0][0];
      const float* w1=&wm[i1][0];
      for(int i=0;i<on;i++)
        P[(size_t)i*L+j]=sc*(a*w0[i]+b*w1[i]);
    }
  } else {
    int j=tid;
    if(j<n){
      float y[96], col[96];
      for(int i=0;i<n;i++) y[i]=0.f;
      for(int i=0;i<96;i++) col[i]=0.f;
      y[j]=1.f;
      for(int i=1;i<n;i++) y[i]-=llf[i-1]*y[i-1];
      for(int i=0;i<n;i++) y[i]*=dinv[i];
      for(int i=n-2;i>=0;i--) y[i]-=llf[i]*y[i+1];
      for(int r=0;r<n;r++){ int i0=i0s[r]; float w=ws[r]; int i1=min(i0+1,on-1);
        if(i1==i0) col[i0]+=y[r]; else { col[i0]+=(1.f-w)*y[r]; col[i1]+=w*y[r]; } }
      for(int i=0;i<on;i++) P[(size_t)i*L+j]=sc*col[i];
    }
  }
}

__global__ void k_anchT(const float* a12,const float* a24,const float* a48,const float* a96){
  int a=blockIdx.x;
  const int olds[4]={12,24,48,96};
  const float* A=(a==0)?a12:(a==1)?a24:(a==2)?a48:a96;
  int on=olds[a];
  for(int idx=threadIdx.x;idx<512*on;idx+=blockDim.x){
    int j=idx/on, i=idx-j*on;
    g_anchT[(size_t)a*96*512 + (size_t)i*512 + j]=A[idx];
  }
}

__global__ void k_cv(const float* w1,const float* b1,const float* w2,const float* b2,
                     const float* sb,const float* fw1,const float* fb1){
  int s=blockIdx.x, j=threadIdx.x;
  if(s<2){
    const float* W = (s? w2:w1) + (size_t)(1024+j)*512;
    float acc = (s? b2:b1)[1024+j];
    for(int e=0;e<512;e++) acc += W[e]*sb[e];
    g_cvb[s*512+j]=acc;
  } else {
    const float* W = fw1 + (size_t)j*1536 + 1024;
    float acc = fb1[j];
    for(int e=0;e<512;e++) acc += W[e]*sb[e];
    g_cc[j]=acc;
  }
}

__global__ void k_fw1copy(const float* __restrict__ fw1){
  int idx=blockIdx.x*256+threadIdx.x;
  if(idx>=512*1040) return;
  int j=idx/1040, t=idx-j*1040;
  if(t<1024) g_fw1m[(size_t)j*CLD+t]=fw1[(size_t)j*1536+t];
  else g_fw1m[(size_t)j*CLD+1120+(t-1024)]=0.f;
}

__device__ __forceinline__ float4 cvt_tf32_4(const float* p){
  float4 v=*(const float4*)p;
  uint32_t o0,o1,o2,o3;
  asm("cvt.rna.tf32.f32 %0, %1;":"=r"(o0):"f"(v.x));
  asm("cvt.rna.tf32.f32 %0, %1;":"=r"(o1):"f"(v.y));
  asm("cvt.rna.tf32.f32 %0, %1;":"=r"(o2):"f"(v.z));
  asm("cvt.rna.tf32.f32 %0, %1;":"=r"(o3):"f"(v.w));
  float4 r;
  r.x=__uint_as_float(o0); r.y=__uint_as_float(o1);
  r.z=__uint_as_float(o2); r.w=__uint_as_float(o3);
  return r;
}

// 17 small GEMMs on tensor cores: M=512,K=512,N=on<=96 (padded to 128).
__global__ void __launch_bounds__(256) k_sg_tf32(
    const float* __restrict__ inw0,const float* __restrict__ inw1,
    const float* __restrict__ fw1)
{
  __shared__ __align__(16) float As[2][128*20];
  __shared__ __align__(16) float Ws[2][128*20];
  int z=blockIdx.z;
  const float *A,*W; float* C; int lda,ldc,N; int transC;
  if(z<16){
    int kv=z&1,a=(z>>1)&3,s=z>>3;
    N=12<<a;
    const float* inw=s?inw1:inw0;
    W=g_anchT+(size_t)a*96*512;
    if(kv==0){ A=inw+512*512; C=g_WkA+(size_t)(s*4+a)*512*96; ldc=96; transC=0; }
    else     { A=inw+1024*512; C=g_WvAT+(size_t)(s*4+a)*96*512; ldc=512; transC=1; }
    lda=512;
  } else {
    A=fw1+1024; lda=1536; W=g_anchT+(size_t)3*96*512; N=96;
    C=g_fw1m+1024; ldc=CLD; transC=0;
  }
  const int K=512;
  int bm=blockIdx.y*128;
  int tid=threadIdx.x;
  int warp=tid>>5, lane=tid&31;
  int wmw=warp>>1, wn=warp&1;
  int g=lane>>2, t4=lane&3;
  int lr=tid>>1, lq=(tid&1)*8;
  float acc[2][8][4];
#pragma unroll
  for(int a2=0;a2<2;a2++)
#pragma unroll
    for(int b2=0;b2<8;b2++)
#pragma unroll
      for(int d=0;d<4;d++) acc[a2][b2][d]=0.f;
  const float* Arow=A+(size_t)(bm+lr)*lda;
  const float* Wrow=W+(size_t)min(lr,N-1)*512;
  {
    float4 a0=cvt_tf32_4(Arow+lq), a1=cvt_tf32_4(Arow+lq+4);
    float4 w0=cvt_tf32_4(Wrow+lq), w1=cvt_tf32_4(Wrow+lq+4);
    *(float4*)&As[0][lr*20+lq]=a0; *(float4*)&As[0][lr*20+lq+4]=a1;
    *(float4*)&Ws[0][lr*20+lq]=w0; *(float4*)&Ws[0][lr*20+lq+4]=w1;
  }
  __syncthreads();
  for(int k0=0;k0<K;k0+=16){
    int buf=(k0>>4)&1;
    bool more=(k0+16<K);
    float4 pa0,pa1,pw0,pw1;
    if(more){
      pa0=cvt_tf32_4(Arow+k0+16+lq); pa1=cvt_tf32_4(Arow+k0+16+lq+4);
      pw0=cvt_tf32_4(Wrow+k0+16+lq); pw1=cvt_tf32_4(Wrow+k0+16+lq+4);
    }
    const float* as=As[buf];
    const float* ws=Ws[buf];
#pragma unroll
    for(int kk=0;kk<2;kk++){
      int kof=kk*8+t4;
      uint32_t afr[2][4];
#pragma unroll
      for(int mt=0;mt<2;mt++){
        int mb=(wmw*32+mt*16+g)*20+kof;
        afr[mt][0]=__float_as_uint(as[mb]);
        afr[mt][1]=__float_as_uint(as[mb+8*20]);
        afr[mt][2]=__float_as_uint(as[mb+4]);
        afr[mt][3]=__float_as_uint(as[mb+8*20+4]);
      }
#pragma unroll
      for(int nt=0;nt<8;nt++){
        int nb=(wn*64+nt*8+g)*20+kof;
        uint32_t bb0=__float_as_uint(ws[nb]);
        uint32_t bb1=__float_as_uint(ws[nb+4]);
#pragma unroll
        for(int mt=0;mt<2;mt++){
          asm("mma.sync.aligned.m16n8k8.row.col.f32.tf32.tf32.f32 "
              "{%0,%1,%2,%3}, {%4,%5,%6,%7}, {%8,%9}, {%0,%1,%2,%3};"
              : "+f"(acc[mt][nt][0]),"+f"(acc[mt][nt][1]),
                "+f"(acc[mt][nt][2]),"+f"(acc[mt][nt][3])
              : "r"(afr[mt][0]),"r"(afr[mt][1]),"r"(afr[mt][2]),"r"(afr[mt][3]),
                "r"(bb0),"r"(bb1));
        }
      }
    }
    if(more){
      int nb2=buf^1;
      *(float4*)&As[nb2][lr*20+lq]=pa0; *(float4*)&As[nb2][lr*20+lq+4]=pa1;
      *(float4*)&Ws[nb2][lr*20+lq]=pw0; *(float4*)&Ws[nb2][lr*20+lq+4]=pw1;
      __syncthreads();
    }
  }
#pragma unroll
  for(int mt=0;mt<2;mt++){
    int mrow=bm+wmw*32+mt*16+g;
#pragma unroll
    for(int nt=0;nt<8;nt++){
      int nc0=wn*64+nt*8+t4*2;
#pragma unroll
      for(int dc=0;dc<2;dc++){
        int ncol=nc0+dc;
        if(ncol>=N) continue;
        float v0=acc[mt][nt][dc], v1=acc[mt][nt][2+dc];
        if(transC){
          C[(size_t)ncol*ldc+mrow]=v0;
          C[(size_t)ncol*ldc+mrow+8]=v1;
        } else {
          C[(size_t)mrow*ldc+ncol]=v0;
          C[(size_t)(mrow+8)*ldc+ncol]=v1;
        }
      }
    }
  }
}

// TF32 GEMM, BN=64 (better SM utilization), z-batched, N-guarded.
// M%128==0, K%16==0, any N.
template<int EPI>
__global__ void __launch_bounds__(256) gemm_tf32_b(
    int M,int N,int K,
    const float* __restrict__ A0,int lda,size_t sA,
    const float* __restrict__ W0,const float* __restrict__ W1,int ldw,
    const float* __restrict__ b0,const float* __restrict__ b1,
    float* __restrict__ C0,int ldc,size_t sC)
{
  __shared__ __align__(16) float As[2][128*20];
  __shared__ __align__(16) float Ws[2][64*20];
  int z=blockIdx.z;
  const float* A=A0+(size_t)z*sA;
  const float* W=z?W1:W0;
  const float* bias=z?b1:b0;
  float* C=C0+(size_t)z*sC;
  int bm=blockIdx.y*128, bn=blockIdx.x*64;
  int tid=threadIdx.x;
  int warp=tid>>5, lane=tid&31;
  int wm=warp>>1, wn=warp&1;
  int g=lane>>2, t4=lane&3;
  int lr=tid>>1, lq=(tid&1)*8;
  float acc[2][4][4];
#pragma unroll
  for(int a=0;a<2;a++)
#pragma unroll
    for(int b=0;b<4;b++)
#pragma unroll
      for(int d=0;d<4;d++) acc[a][b][d]=0.f;
  const float* Arow=A+(size_t)(bm+lr)*lda;
  const float* Wrow=W+(size_t)min(bn+lr,N-1)*ldw;
  {
    float4 a0=cvt_tf32_4(Arow+lq), a1=cvt_tf32_4(Arow+lq+4);
    *(float4*)&As[0][lr*20+lq]=a0; *(float4*)&As[0][lr*20+lq+4]=a1;
    if(tid<128){
      float4 w0=cvt_tf32_4(Wrow+lq), w1=cvt_tf32_4(Wrow+lq+4);
      *(float4*)&Ws[0][lr*20+lq]=w0; *(float4*)&Ws[0][lr*20+lq+4]=w1;
    }
  }
  __syncthreads();
  for(int k0=0;k0<K;k0+=16){
    int buf=(k0>>4)&1;
    bool more=(k0+16<K);
    float4 pa0,pa1,pw0,pw1;
    if(more){
      pa0=cvt_tf32_4(Arow+k0+16+lq); pa1=cvt_tf32_4(Arow+k0+16+lq+4);
      if(tid<128){
        pw0=cvt_tf32_4(Wrow+k0+16+lq); pw1=cvt_tf32_4(Wrow+k0+16+lq+4);
      }
    }
    const float* as=As[buf];
    const float* ws=Ws[buf];
#pragma unroll
    for(int kk=0;kk<2;kk++){
      int kof=kk*8+t4;
      uint32_t afr[2][4];
#pragma unroll
      for(int mt=0;mt<2;mt++){
        int mb=(wm*32+mt*16+g)*20+kof;
        afr[mt][0]=__float_as_uint(as[mb]);
        afr[mt][1]=__float_as_uint(as[mb+8*20]);
        afr[mt][2]=__float_as_uint(as[mb+4]);
        afr[mt][3]=__float_as_uint(as[mb+8*20+4]);
      }
#pragma unroll
      for(int nt=0;nt<4;nt++){
        int nb=(wn*32+nt*8+g)*20+kof;
        uint32_t bb0=__float_as_uint(ws[nb]);
        uint32_t bb1=__float_as_uint(ws[nb+4]);
#pragma unroll
        for(int mt=0;mt<2;mt++){
          asm("mma.sync.aligned.m16n8k8.row.col.f32.tf32.tf32.f32 "
              "{%0,%1,%2,%3}, {%4,%5,%6,%7}, {%8,%9}, {%0,%1,%2,%3};"
              : "+f"(acc[mt][nt][0]),"+f"(acc[mt][nt][1]),
                "+f"(acc[mt][nt][2]),"+f"(acc[mt][nt][3])
              : "r"(afr[mt][0]),"r"(afr[mt][1]),"r"(afr[mt][2]),"r"(afr[mt][3]),
                "r"(bb0),"r"(bb1));
        }
      }
    }
    if(more){
      int nb2=buf^1;
      *(float4*)&As[nb2][lr*20+lq]=pa0; *(float4*)&As[nb2][lr*20+lq+4]=pa1;
      if(tid<128){
        *(float4*)&Ws[nb2][lr*20+lq]=pw0; *(float4*)&Ws[nb2][lr*20+lq+4]=pw1;
      }
      __syncthreads();
    }
  }
#pragma unroll
  for(int mt=0;mt<2;mt++){
    int mrow=bm+wm*32+mt*16+g;
#pragma unroll
    for(int nt=0;nt<4;nt++){
      int ncol=bn+wn*32+nt*8+t4*2;
      if(ncol>=N) continue;
      float b0v=bias?bias[ncol]:0.f, b1v=bias?bias[ncol+1]:0.f;
      float v0=acc[mt][nt][0]+b0v, v1=acc[mt][nt][1]+b1v;
      float v2=acc[mt][nt][2]+b0v, v3=acc[mt][nt][3]+b1v;
      if(EPI==1){
        v0=0.5f*v0*(1.f+erff(v0*0.70710678118654752f));
        v1=0.5f*v1*(1.f+erff(v1*0.70710678118654752f));
        v2=0.5f*v2*(1.f+erff(v2*0.70710678118654752f));
        v3=0.5f*v3*(1.f+erff(v3*0.70710678118654752f));
      }
      *(float2*)(C+(size_t)mrow*ldc+ncol)=make_float2(v0,v1);
      *(float2*)(C+(size_t)(mrow+8)*ldc+ncol)=make_float2(v2,v3);
    }
  }
}

__global__ void k_tokenize(const float* __restrict__ sb){
  int r=blockIdx.x, slot=blockIdx.y, c=r&127, tid=threadIdx.x;
  int p=g_periods[c*2+slot], on=near_anchor(p), np=384/p, a=aidx_of(on);
  __shared__ float xs[384];
  __shared__ float zl[96];
  for(int t=tid;t<384;t+=128) xs[t]=g_xinv[(size_t)r*384+t];
  __syncthreads();
  const float* P=g_P+(size_t)(p-4)*PSLOT;
  float* z=g_zbuf+((size_t)r*2+slot)*ZLD;
  int tot=np*on;
  for(int idx=tid;idx<tot;idx+=128){
    int k=idx/on, i=idx-k*on;
    const float* Pr=P+(size_t)i*p;
    const float* xp=xs+k*p;
    float acc=0;
    for(int u=0;u<p;u++) acc+=Pr[u]*xp[u];
    z[idx]=acc;
    if(k==np-1) zl[i]=acc;
  }
  __syncthreads();
  const float* AT=g_anchT+(size_t)a*96*512;
  float* q=g_qb+((size_t)slot*ROWS+r)*512;
  for(int j=tid;j<512;j+=128){
    float acc=sb[j];
    for(int i=0;i<on;i++) acc+=AT[(size_t)i*512+j]*zl[i];
    q[j]=acc;
  }
}

__global__ void __launch_bounds__(256) k_attn(){
  __shared__ float us[6144];
  __shared__ float sc[6144];
  int c=blockIdx.x, slot=blockIdx.y, tid=threadIdx.x;
  int p=g_periods[c*2+slot], on=near_anchor(p), np=384/p, a=aidx_of(on);
  const float* WkA=g_WkA+(size_t)(slot*4+a)*512*96;
  const float* WvAT=g_WvAT+(size_t)(slot*4+a)*96*512;
  const float* Qb=g_Qb+(size_t)slot*ROWS*512;
  for(int hp=0;hp<2;hp++){
    for(int x=tid;x<4096;x+=256){
      int b=x>>8, rme=x&255;
      sc[x]=Qb[(size_t)(b*128+c)*512 + hp*256 + rme];
    }
    __syncthreads();
    for(int x=tid;x<2*on;x+=256){
      int hh=x/on, i=x-hh*on;
      int h=hp*2+hh;
      float acc[16];
#pragma unroll
      for(int b=0;b<16;b++) acc[b]=0;
      for(int e=0;e<128;e++){
        float wv=WkA[(size_t)(h*128+e)*96+i];
#pragma unroll
        for(int b=0;b<16;b++) acc[b]+=wv*sc[b*256+hh*128+e];
      }
#pragma unroll
      for(int b=0;b<16;b++) us[(b*4+h)*96+i]=acc[b];
    }
    __syncthreads();
  }
  const float isq=0.08838834764831845f;
  for(int x=tid;x<16*np;x+=256){
    int b=x/np, k=x-b*np;
    const float* zr=g_zbuf+((size_t)(b*128+c)*2+slot)*ZLD+(size_t)k*on;
    float a0=0,a1=0,a2=0,a3=0;
    for(int i=0;i<on;i++){ float zv=zr[i];
      a0+=us[(b*4)*96+i]*zv; a1+=us[(b*4+1)*96+i]*zv;
      a2+=us[(b*4+2)*96+i]*zv; a3+=us[(b*4+3)*96+i]*zv; }
    sc[(b*4)*96+k]=a0*isq; sc[(b*4+1)*96+k]=a1*isq;
    sc[(b*4+2)*96+k]=a2*isq; sc[(b*4+3)*96+k]=a3*isq;
  }
  __syncthreads();
  if(tid<64){
    float* row=sc+tid*96; float m=-INFINITY;
    for(int k=0;k<np;k++) m=fmaxf(m,row[k]);
    float s=0;
    for(int k=0;k<np;k++){ float e=expf(row[k]-m); row[k]=e; s+=e; }
    float inv=1.f/s;
    for(int k=0;k<np;k++) row[k]*=inv;
  }
  __syncthreads();
  for(int x=tid;x<4*on;x+=256){
    int h=x/on, i=x-h*on;
    for(int b=0;b<16;b++){
      const float* zr=g_zbuf+((size_t)(b*128+c)*2+slot)*ZLD;
      const float* ar=sc+(b*4+h)*96;
      float acc=0;
      for(int k=0;k<np;k++) acc+=ar[k]*zr[(size_t)k*on+i];
      us[(b*4+h)*96+i]=acc;
    }
  }
  __syncthreads();
  for(int j=tid;j<512;j+=256){
    int h=j>>7;
    float wacc[16];
#pragma unroll
    for(int b=0;b<16;b++) wacc[b]=0;
    for(int i=0;i<on;i++){
      float wv=WvAT[(size_t)i*512+j];
#pragma unroll
      for(int b=0;b<16;b++) wacc[b]+=wv*us[(b*4+h)*96+i];
    }
    float cvv=g_cvb[slot*512+j];
#pragma unroll
    for(int b=0;b<16;b++)
      g_ob[(size_t)slot*ROWS*512+(size_t)(b*128+c)*512+j]=wacc[b]+cvv;
  }
}

__global__ void k_ln(const float* __restrict__ g0,const float* __restrict__ b0,
                     const float* __restrict__ g1,const float* __restrict__ b1){
  __shared__ float red[8];
  int r=blockIdx.x, slot=blockIdx.y, tid=threadIdx.x;
  const float* g=slot?g1:g0;
  const float* bt=slot?b1:b0;
  const float* q=g_qb+((size_t)slot*ROWS+r)*512;
  const float* a=g_ab+((size_t)slot*ROWS+r)*512;
  float v0=q[tid]+a[tid], v1=q[tid+256]+a[tid+256];
  float s=v0+v1;
  for(int o=16;o;o>>=1) s+=__shfl_xor_sync(~0u,s,o);
  if((tid&31)==0) red[tid>>5]=s;
  __syncthreads();
  if(tid<8){ s=red[tid]; for(int o=4;o;o>>=1) s+=__shfl_xor_sync(0xff,s,o); red[0]=s; }
  __syncthreads();
  float mu=red[0]/512.f;
  __syncthreads();
  float d0=v0-mu, d1=v1-mu;
  s=d0*d0+d1*d1;
  for(int o=16;o;o>>=1) s+=__shfl_xor_sync(~0u,s,o);
  if((tid&31)==0) red[tid>>5]=s;
  __syncthreads();
  if(tid<8){ s=red[tid]; for(int o=4;o;o>>=1) s+=__shfl_xor_sync(0xff,s,o); red[0]=s; }
  __syncthreads();
  float inv=rsqrtf(red[0]/512.f+1e-5f);
  float* out=g_comb2+(size_t)r*CLD+slot*512;
  out[tid]=d0*inv*g[tid]+bt[tid];
  out[tid+256]=d1*inv*g[tid+256]+bt[tid+256];
  if(slot==0&&tid<16) g_comb2[(size_t)r*CLD+1120+tid]=0.f;
}

extern "C" void kernel_launch(void* const* d_in, const int* in_sizes, int n_in,
                              void* d_out, int out_size){
  const float* x   =(const float*)d_in[0];
  const float* a12 =(const float*)d_in[1];
  const float* a24 =(const float*)d_in[2];
  const float* a48 =(const float*)d_in[3];
  const float* a96 =(const float*)d_in[4];
  const float* sb  =(const float*)d_in[5];
  const float* inw[2]={(const float*)d_in[6],(const float*)d_in[12]};
  const float* inb[2]={(const float*)d_in[7],(const float*)d_in[13]};
  const float* ow[2]={(const float*)d_in[8],(const float*)d_in[14]};
  const float* obi[2]={(const float*)d_in[9],(const float*)d_in[15]};
  const float* lng[2]={(const float*)d_in[10],(const float*)d_in[16]};
  const float* lnb[2]={(const float*)d_in[11],(const float*)d_in[17]};
  const float* fw1=(const float*)d_in[18];
  const float* fb1=(const float*)d_in[19];
  const float* fw2=(const float*)d_in[20];
  const float* fb2=(const float*)d_in[21];
  float* out=(float*)d_out;

  float *xinv,*Ptr,*qb,*Qb,*ob,*ab,*comb2,*hb,*fw1m,*cc;
  cudaGetSymbolAddress((void**)&xinv,g_xinv);
  cudaGetSymbolAddress((void**)&Ptr,g_Ptr);
  cudaGetSymbolAddress((void**)&qb,g_qb);
  cudaGetSymbolAddress((void**)&Qb,g_Qb);
  cudaGetSymbolAddress((void**)&ob,g_ob);
  cudaGetSymbolAddress((void**)&ab,g_ab);
  cudaGetSymbolAddress((void**)&comb2,g_comb2);
  cudaGetSymbolAddress((void**)&hb,g_hb);
  cudaGetSymbolAddress((void**)&fw1m,g_fw1m);
  cudaGetSymbolAddress((void**)&cc,g_cc);

  const size_t SL=(size_t)ROWS*512;

  k_xinv<<<(ROWS*384+255)/256,256>>>(x);
  k_acf<<<128,96>>>(x);
  k_periods<<<1,192>>>();
  k_build_P<<<190,384>>>();
  k_anchT<<<4,256>>>(a12,a24,a48,a96);
  k_cv<<<3,512>>>(inw[0],inb[0],inw[1],inb[1],sb,fw1,fb1);
  k_fw1copy<<<(512*1040+255)/256,256>>>(fw1);

  k_sg_tf32<<<dim3(1,4,17),256>>>(inw[0],inw[1],fw1);

  k_tokenize<<<dim3(ROWS,2),128>>>(sb);

  gemm_tf32_b<0><<<dim3(8,16,2),256>>>(ROWS,512,512,
    qb,512,SL, inw[0],inw[1],512, inb[0],inb[1], Qb,512,SL);

  k_attn<<<dim3(128,2),256>>>();

  gemm_tf32_b<0><<<dim3(8,16,2),256>>>(ROWS,512,512,
    ob,512,SL, ow[0],ow[1],512, obi[0],obi[1], ab,512,SL);

  k_ln<<<dim3(ROWS,2),256>>>(lng[0],lnb[0],lng[1],lnb[1]);

  gemm_tf32_b<0><<<dim3(2,16,1),256>>>(ROWS,96,384,
    xinv,384,0, Ptr,Ptr,384, (const float*)nullptr,(const float*)nullptr,
    comb2+1024,CLD,0);

  gemm_tf32_b<1><<<dim3(8,16,1),256>>>(ROWS,512,CLD,
    comb2,CLD,0, fw1m,fw1m,CLD, cc,cc, hb,512,0);
  gemm_tf32_b<0><<<dim3(8,16,1),256>>>(ROWS,512,512,
    hb,512,0, fw2,fw2,512, fb2,fb2, out,512,0);
}